// round 6
// baseline (speedup 1.0000x reference)
#include <cuda_runtime.h>
#include <cuda_bf16.h>
#include <cstdint>

#define B_      2
#define C_      192
#define C3_     576
#define H_      256
#define W_      256
#define HW_     65536
#define HEADS_  8
#define KSPLIT_ 4

// ---------------- scratch (device globals: allocation-free rule) ----------------
__device__ __nv_bfloat16 g_xh  [(size_t)B_ * C_ * HW_];
__device__ __nv_bfloat16 g_xl  [(size_t)B_ * C_ * HW_];
__device__ __nv_bfloat16 g_wqh [C3_ * C_];
__device__ __nv_bfloat16 g_wql [C3_ * C_];
__device__ __nv_bfloat16 g_wph [C_ * C_];
__device__ __nv_bfloat16 g_wpl [C_ * C_];
__device__ __nv_bfloat16 g_qkvh[(size_t)B_ * C3_ * HW_];
__device__ __nv_bfloat16 g_qkvl[(size_t)B_ * C3_ * HW_];
__device__ __nv_bfloat16 g_dwh [(size_t)B_ * C3_ * HW_];
__device__ __nv_bfloat16 g_dwl [(size_t)B_ * C3_ * HW_];
__device__ __nv_bfloat16 g_avh [(size_t)B_ * C_ * HW_];
__device__ __nv_bfloat16 g_avl [(size_t)B_ * C_ * HW_];
__device__ float g_gramp[(size_t)KSPLIT_ * B_ * HEADS_ * C_ * C_];
__device__ __nv_bfloat16 g_attnh[(size_t)B_ * HEADS_ * C_ * C_];
__device__ __nv_bfloat16 g_attnl[(size_t)B_ * HEADS_ * C_ * C_];
__device__ float g_partq[B_ * C_ * 8 * 8];
__device__ float g_partk[B_ * C_ * 8 * 8];
__device__ float g_invq [B_ * C_ * 8];
__device__ float g_invk [B_ * C_ * 8];

// ---------------- mma / ldmatrix / cp.async helpers ----------------
__device__ __forceinline__ void ldsm4(unsigned* r, const void* p) {
    unsigned a = (unsigned)__cvta_generic_to_shared(p);
    asm volatile("ldmatrix.sync.aligned.m8n8.x4.shared.b16 {%0,%1,%2,%3}, [%4];"
                 : "=r"(r[0]), "=r"(r[1]), "=r"(r[2]), "=r"(r[3]) : "r"(a));
}
__device__ __forceinline__ void ldsm4t(unsigned* r, const void* p) {
    unsigned a = (unsigned)__cvta_generic_to_shared(p);
    asm volatile("ldmatrix.sync.aligned.m8n8.x4.trans.shared.b16 {%0,%1,%2,%3}, [%4];"
                 : "=r"(r[0]), "=r"(r[1]), "=r"(r[2]), "=r"(r[3]) : "r"(a));
}
__device__ __forceinline__ void ldsm2(unsigned* r, const void* p) {
    unsigned a = (unsigned)__cvta_generic_to_shared(p);
    asm volatile("ldmatrix.sync.aligned.m8n8.x2.shared.b16 {%0,%1}, [%2];"
                 : "=r"(r[0]), "=r"(r[1]) : "r"(a));
}
__device__ __forceinline__ void mma16816(float* c, const unsigned* a, const unsigned* b) {
    asm volatile("mma.sync.aligned.m16n8k16.row.col.f32.bf16.bf16.f32 "
                 "{%0,%1,%2,%3},{%4,%5,%6,%7},{%8,%9},{%0,%1,%2,%3};"
                 : "+f"(c[0]), "+f"(c[1]), "+f"(c[2]), "+f"(c[3])
                 : "r"(a[0]), "r"(a[1]), "r"(a[2]), "r"(a[3]), "r"(b[0]), "r"(b[1]));
}
__device__ __forceinline__ void cpa16(unsigned dst, const void* src) {
    asm volatile("cp.async.cg.shared.global [%0], [%1], 16;\n" :: "r"(dst), "l"(src));
}
#define CP_COMMIT() asm volatile("cp.async.commit_group;\n")
#define CP_WAIT1()  asm volatile("cp.async.wait_group 1;\n")

__device__ __forceinline__ void stsplit(__nv_bfloat16* ph, __nv_bfloat16* pl, float4 v) {
    __nv_bfloat16 h0 = __float2bfloat16(v.x), h1 = __float2bfloat16(v.y);
    __nv_bfloat16 h2 = __float2bfloat16(v.z), h3 = __float2bfloat16(v.w);
    __nv_bfloat162 t;
    t.x = h0; t.y = h1; ((__nv_bfloat162*)ph)[0] = t;
    t.x = h2; t.y = h3; ((__nv_bfloat162*)ph)[1] = t;
    t.x = __float2bfloat16(v.x - __bfloat162float(h0));
    t.y = __float2bfloat16(v.y - __bfloat162float(h1)); ((__nv_bfloat162*)pl)[0] = t;
    t.x = __float2bfloat16(v.z - __bfloat162float(h2));
    t.y = __float2bfloat16(v.w - __bfloat162float(h3)); ((__nv_bfloat162*)pl)[1] = t;
}
__device__ __forceinline__ void st_pair(__nv_bfloat16* ph, __nv_bfloat16* pl, float x, float y) {
    __nv_bfloat16 hx = __float2bfloat16(x), hy = __float2bfloat16(y);
    __nv_bfloat162 hp; hp.x = hx; hp.y = hy; *(__nv_bfloat162*)ph = hp;
    __nv_bfloat162 lp;
    lp.x = __float2bfloat16(x - __bfloat162float(hx));
    lp.y = __float2bfloat16(y - __bfloat162float(hy));
    *(__nv_bfloat162*)pl = lp;
}

// ---------------- fp32 -> bf16 hi/lo split (elementwise) ----------------
__global__ __launch_bounds__(256) void split_kernel(
    const float* __restrict__ in, __nv_bfloat16* __restrict__ oh,
    __nv_bfloat16* __restrict__ ol, int n)
{
    int i = (blockIdx.x * 256 + threadIdx.x) * 4;
    if (i < n) {
        float4 v = *(const float4*)(in + i);
        stsplit(oh + i, ol + i, v);
    }
}

// ---------------- maps ----------------
struct QkvMap {
    const __nv_bfloat16 *Ah, *Al, *Bh, *Bl; __nv_bfloat16 *Ch, *Cl;
    static constexpr bool C_BF16 = true;
    static constexpr size_t BSTRIDE32 = (size_t)32 * HW_;
    __device__ const __nv_bfloat16* aRowH(int z, int m) const { return Ah + (size_t)m * C_; }
    __device__ const __nv_bfloat16* aRowL(int z, int m) const { return Al + (size_t)m * C_; }
    __device__ const __nv_bfloat16* bRowH(int z, int k) const { return Bh + ((size_t)z * C_ + k) * HW_; }
    __device__ const __nv_bfloat16* bRowL(int z, int k) const { return Bl + ((size_t)z * C_ + k) * HW_; }
    __device__ __nv_bfloat16* cRowH(int z, int m) const { return Ch + ((size_t)z * C3_ + m) * HW_; }
    __device__ __nv_bfloat16* cRowL(int z, int m) const { return Cl + ((size_t)z * C3_ + m) * HW_; }
};
struct AvMap {
    const __nv_bfloat16 *Ah, *Al, *Bh, *Bl; __nv_bfloat16 *Ch, *Cl;
    static constexpr bool C_BF16 = true;
    static constexpr size_t BSTRIDE32 = (size_t)4 << 16;
    __device__ const __nv_bfloat16* aRowH(int z, int m) const { return Ah + (size_t)z * (C_ * C_) + (size_t)m * C_; }
    __device__ const __nv_bfloat16* aRowL(int z, int m) const { return Al + (size_t)z * (C_ * C_) + (size_t)m * C_; }
    __device__ const __nv_bfloat16* bRowH(int z, int k) const {
        int b = z >> 3, h = z & 7;
        return Bh + ((size_t)(b * C3_ + 2 * C_ + h * 24 + (k >> 3)) << 16) + ((k & 7) << 13);
    }
    __device__ const __nv_bfloat16* bRowL(int z, int k) const {
        int b = z >> 3, h = z & 7;
        return Bl + ((size_t)(b * C3_ + 2 * C_ + h * 24 + (k >> 3)) << 16) + ((k & 7) << 13);
    }
    __device__ __nv_bfloat16* cRowH(int z, int m) const {
        int b = z >> 3, h = z & 7;
        return Ch + ((size_t)(b * C_ + h * 24 + (m >> 3)) << 16) + ((m & 7) << 13);
    }
    __device__ __nv_bfloat16* cRowL(int z, int m) const {
        int b = z >> 3, h = z & 7;
        return Cl + ((size_t)(b * C_ + h * 24 + (m >> 3)) << 16) + ((m & 7) << 13);
    }
};
struct ProjMap {
    const __nv_bfloat16 *Ah, *Al, *Bh, *Bl; float* C;
    static constexpr bool C_BF16 = false;
    static constexpr size_t BSTRIDE32 = (size_t)32 * HW_;
    __device__ const __nv_bfloat16* aRowH(int z, int m) const { return Ah + (size_t)m * C_; }
    __device__ const __nv_bfloat16* aRowL(int z, int m) const { return Al + (size_t)m * C_; }
    __device__ const __nv_bfloat16* bRowH(int z, int k) const { return Bh + ((size_t)z * C_ + k) * HW_; }
    __device__ const __nv_bfloat16* bRowL(int z, int k) const { return Bl + ((size_t)z * C_ + k) * HW_; }
    __device__ float* cRow(int z, int m) const { return C + ((size_t)z * C_ + m) * HW_; }
};

// =====================================================================
// bf16-split MMA GEMM, BM=96 BN=128 BK=32, cp.async 3-stage pipeline.
// grid: x = m-tiles, y = n-tiles (adjacent blocks share B tile in L2).
// =====================================================================
template <class Map>
__global__ __launch_bounds__(256, 2) void gemm_mma(const Map map, const int K)
{
    __shared__ alignas(16) __nv_bfloat16 Ash[3][96][40];
    __shared__ alignas(16) __nv_bfloat16 Asl[3][96][40];
    __shared__ alignas(16) __nv_bfloat16 Bsh[3][32][136];
    __shared__ alignas(16) __nv_bfloat16 Bsl[3][32][136];
    constexpr unsigned ASTG = 96 * 40 * 2;
    constexpr unsigned BSTG = 32 * 136 * 2;

    const int z = blockIdx.z, bm = blockIdx.x * 96, bn = blockIdx.y * 128;
    const int tid = threadIdx.x, lane = tid & 31, w = tid >> 5;
    const int m0 = (w >> 2) * 48, n0 = (w & 3) * 32;

    // loader chunk maps (16B each): A 768 chunks, B 1024 chunks
    const __nv_bfloat16* asrc[3]; unsigned adst[3];
#pragma unroll
    for (int it = 0; it < 3; ++it) {
        int idx = tid + it * 256;
        int which = idx / 384, w2 = idx % 384;
        int row = w2 >> 2, c4 = w2 & 3;
        const __nv_bfloat16* base = which ? map.aRowL(z, bm + row) : map.aRowH(z, bm + row);
        asrc[it] = base + c4 * 8;
        adst[it] = (unsigned)__cvta_generic_to_shared(which ? &Asl[0][row][c4 * 8] : &Ash[0][row][c4 * 8]);
    }
    const __nv_bfloat16* bsrc[4]; unsigned bdst[4];
#pragma unroll
    for (int it = 0; it < 4; ++it) {
        int idx = tid + it * 256;
        int which = idx >> 9, w2 = idx & 511;
        int row = w2 >> 4, c4 = w2 & 15;
        const __nv_bfloat16* base = which ? map.bRowL(z, row) : map.bRowH(z, row);
        bsrc[it] = base + bn + c4 * 8;
        bdst[it] = (unsigned)__cvta_generic_to_shared(which ? &Bsl[0][row][c4 * 8] : &Bsh[0][row][c4 * 8]);
    }

    float acc[3][4][4];
#pragma unroll
    for (int i = 0; i < 3; ++i)
#pragma unroll
        for (int j = 0; j < 4; ++j)
#pragma unroll
            for (int q = 0; q < 4; ++q) acc[i][j][q] = 0.f;

    const int nStage = K >> 5;
    // prologue: stages 0,1
#pragma unroll
    for (int p = 0; p < 2; ++p) {
#pragma unroll
        for (int it = 0; it < 3; ++it) cpa16(adst[it] + p * ASTG, asrc[it] + p * 32);
#pragma unroll
        for (int it = 0; it < 4; ++it) cpa16(bdst[it] + p * BSTG, bsrc[it] + p * Map::BSTRIDE32);
        CP_COMMIT();
    }

    int buf = 0;
#pragma unroll 1
    for (int s = 0; s < nStage; ++s) {
        CP_WAIT1();
        __syncthreads();
        if (s + 2 < nStage) {
            const int b2 = (s + 2) % 3;
            const int ka = (s + 2) * 32;
            const size_t kb = (size_t)(s + 2) * Map::BSTRIDE32;
#pragma unroll
            for (int it = 0; it < 3; ++it) cpa16(adst[it] + b2 * ASTG, asrc[it] + ka);
#pragma unroll
            for (int it = 0; it < 4; ++it) cpa16(bdst[it] + b2 * BSTG, bsrc[it] + kb);
        }
        CP_COMMIT();
#pragma unroll
        for (int kk = 0; kk < 32; kk += 16) {
            unsigned ah[3][4], al[3][4], bh[2][4], bl[2][4];
            const int g = lane >> 3;
            const int brow = kk + ((g & 1) << 3) + (lane & 7);
            const int l15 = lane & 15;
#pragma unroll
            for (int mi = 0; mi < 3; ++mi) {
                ldsm4(ah[mi], &Ash[buf][m0 + mi * 16 + l15][kk + (lane >> 4) * 8]);
                ldsm4(al[mi], &Asl[buf][m0 + mi * 16 + l15][kk + (lane >> 4) * 8]);
            }
#pragma unroll
            for (int p = 0; p < 2; ++p) {
                const int bcol = n0 + p * 16 + ((g >> 1) << 3);
                ldsm4t(bh[p], &Bsh[buf][brow][bcol]);
                ldsm4t(bl[p], &Bsl[buf][brow][bcol]);
            }
#pragma unroll
            for (int mi = 0; mi < 3; ++mi)
#pragma unroll
                for (int p = 0; p < 2; ++p)
#pragma unroll
                    for (int h2 = 0; h2 < 2; ++h2) {
                        float* a = acc[mi][p * 2 + h2];
                        mma16816(a, ah[mi], bh[p] + h2 * 2);
                        mma16816(a, al[mi], bh[p] + h2 * 2);
                        mma16816(a, ah[mi], bl[p] + h2 * 2);
                    }
        }
        buf = (buf == 2) ? 0 : buf + 1;
    }

#pragma unroll
    for (int mi = 0; mi < 3; ++mi)
#pragma unroll
        for (int ni = 0; ni < 4; ++ni) {
            const int r = bm + m0 + mi * 16 + (lane >> 2);
            const int cc = bn + n0 + ni * 8 + (lane & 3) * 2;
            const float* a = acc[mi][ni];
            if constexpr (Map::C_BF16) {
                st_pair(map.cRowH(z, r) + cc,     map.cRowL(z, r) + cc,     a[0], a[1]);
                st_pair(map.cRowH(z, r + 8) + cc, map.cRowL(z, r + 8) + cc, a[2], a[3]);
            } else {
                *(float2*)(map.cRow(z, r) + cc)     = make_float2(a[0], a[1]);
                *(float2*)(map.cRow(z, r + 8) + cc) = make_float2(a[2], a[3]);
            }
        }
}

// =====================================================================
// Gram (q @ k^T), BM=BN=96 BK=32, split-K=4, cp.async 3-stage pipeline.
// =====================================================================
__global__ __launch_bounds__(256, 2) void gram_mma(
    const __nv_bfloat16* __restrict__ dwh, const __nv_bfloat16* __restrict__ dwl,
    float* __restrict__ gramp)
{
    __shared__ alignas(16) __nv_bfloat16 Ash[3][96][40];
    __shared__ alignas(16) __nv_bfloat16 Asl[3][96][40];
    __shared__ alignas(16) __nv_bfloat16 Bsh[3][96][40];
    __shared__ alignas(16) __nv_bfloat16 Bsl[3][96][40];
    constexpr unsigned STG = 96 * 40 * 2;
    constexpr int KS_LEN = 8192 / KSPLIT_;          // 2048
    constexpr int NSTG = KS_LEN / 32;               // 64

    const int z = blockIdx.z;
    const int ks = z & (KSPLIT_ - 1), bh_ = z / KSPLIT_;
    const int h = bh_ & 7, b = bh_ >> 3;
    const int bi = blockIdx.y * 96, bj = blockIdx.x * 96;
    const int tid = threadIdx.x, lane = tid & 31, w = tid >> 5;
    const int m0 = (w >> 2) * 48, n0 = (w & 3) * 24;
    const int kbase = ks * KS_LEN;

    const __nv_bfloat16* src[6]; unsigned dst[6];
#pragma unroll
    for (int it = 0; it < 6; ++it) {
        int idx = tid + it * 256;
        int which = idx / 384, w2 = idx % 384;
        int row = w2 >> 2, c4 = w2 & 3;
        size_t off;
        if (which < 2) { int qi = bi + row; off = ((size_t)(b * C3_ + h * 24 + (qi >> 3)) << 16) + ((size_t)(qi & 7) << 13); }
        else           { int kj = bj + row; off = ((size_t)(b * C3_ + C_ + h * 24 + (kj >> 3)) << 16) + ((size_t)(kj & 7) << 13); }
        src[it] = ((which & 1) ? dwl : dwh) + off + kbase + c4 * 8;
        __nv_bfloat16* d;
        if      (which == 0) d = &Ash[0][row][c4 * 8];
        else if (which == 1) d = &Asl[0][row][c4 * 8];
        else if (which == 2) d = &Bsh[0][row][c4 * 8];
        else                 d = &Bsl[0][row][c4 * 8];
        dst[it] = (unsigned)__cvta_generic_to_shared(d);
    }

    float acc[3][3][4];
#pragma unroll
    for (int i = 0; i < 3; ++i)
#pragma unroll
        for (int j = 0; j < 3; ++j)
#pragma unroll
            for (int q = 0; q < 4; ++q) acc[i][j][q] = 0.f;

#pragma unroll
    for (int p = 0; p < 2; ++p) {
#pragma unroll
        for (int it = 0; it < 6; ++it) cpa16(dst[it] + p * STG, src[it] + p * 32);
        CP_COMMIT();
    }

    int buf = 0;
#pragma unroll 1
    for (int s = 0; s < NSTG; ++s) {
        CP_WAIT1();
        __syncthreads();
        if (s + 2 < NSTG) {
            const int b2 = (s + 2) % 3;
            const int ka = (s + 2) * 32;
#pragma unroll
            for (int it = 0; it < 6; ++it) cpa16(dst[it] + b2 * STG, src[it] + ka);
        }
        CP_COMMIT();
#pragma unroll
        for (int kk = 0; kk < 32; kk += 16) {
            unsigned ah[3][4], al[3][4], bph[4], bpl[4], b2h[2], b2l[2];
            const int g = lane >> 3;
            const int l15 = lane & 15;
#pragma unroll
            for (int mi = 0; mi < 3; ++mi) {
                ldsm4(ah[mi], &Ash[buf][m0 + mi * 16 + l15][kk + (lane >> 4) * 8]);
                ldsm4(al[mi], &Asl[buf][m0 + mi * 16 + l15][kk + (lane >> 4) * 8]);
            }
            {
                const int brow = n0 + ((g >> 1) << 3) + (lane & 7);
                const int bcol = kk + ((g & 1) << 3);
                ldsm4(bph, &Bsh[buf][brow][bcol]);
                ldsm4(bpl, &Bsl[buf][brow][bcol]);
                ldsm2(b2h, &Bsh[buf][n0 + 16 + (l15 & 7)][kk + ((l15 >> 3) << 3)]);
                ldsm2(b2l, &Bsl[buf][n0 + 16 + (l15 & 7)][kk + ((l15 >> 3) << 3)]);
            }
#pragma unroll
            for (int mi = 0; mi < 3; ++mi) {
#pragma unroll
                for (int h2 = 0; h2 < 2; ++h2) {
                    float* a = acc[mi][h2];
                    mma16816(a, ah[mi], bph + h2 * 2);
                    mma16816(a, al[mi], bph + h2 * 2);
                    mma16816(a, ah[mi], bpl + h2 * 2);
                }
                float* a2 = acc[mi][2];
                mma16816(a2, ah[mi], b2h);
                mma16816(a2, al[mi], b2h);
                mma16816(a2, ah[mi], b2l);
            }
        }
        buf = (buf == 2) ? 0 : buf + 1;
    }

    float* gp = gramp + ((size_t)ks * (B_ * HEADS_) + bh_) * (C_ * C_);
#pragma unroll
    for (int mi = 0; mi < 3; ++mi)
#pragma unroll
        for (int ni = 0; ni < 3; ++ni) {
            const int r = bi + m0 + mi * 16 + (lane >> 2);
            const int cc = bj + n0 + ni * 8 + (lane & 3) * 2;
            const float* a = acc[mi][ni];
            *(float2*)(gp + (size_t)r * C_ + cc)       = make_float2(a[0], a[1]);
            *(float2*)(gp + (size_t)(r + 8) * C_ + cc) = make_float2(a[2], a[3]);
        }
}

// ---------------- depthwise 3x3 + fused q/k norm partials ---------------------
__global__ __launch_bounds__(256) void dw_kernel(
    const __nv_bfloat16* __restrict__ inh, const __nv_bfloat16* __restrict__ inl,
    const float* __restrict__ dww,
    __nv_bfloat16* __restrict__ outh, __nv_bfloat16* __restrict__ outl,
    float* __restrict__ partq, float* __restrict__ partk)
{
    const int chg = blockIdx.z;            // b*576 + c
    const int c = chg % C3_;
    const int b = chg / C3_;
    const size_t base = (size_t)chg << 16;

    float w[9];
#pragma unroll
    for (int i = 0; i < 9; ++i) w[i] = __ldg(&dww[c * 9 + i]);

    __shared__ float s[34][34];
    const int ox = blockIdx.x * 32 - 1, oy = blockIdx.y * 32 - 1;
    for (int t = threadIdx.x; t < 34 * 34; t += 256) {
        int lx = t % 34, ly = t / 34;
        int gx = ox + lx, gy = oy + ly;
        float v = 0.f;
        if ((unsigned)gx < W_ && (unsigned)gy < H_) {
            size_t idx = base + gy * W_ + gx;
            v = __bfloat162float(inh[idx]) + __bfloat162float(inl[idx]);
        }
        s[ly][lx] = v;
    }
    __syncthreads();

    const int tx = threadIdx.x & 31, ty0 = threadIdx.x >> 5;
    float ss = 0.f;
#pragma unroll
    for (int r = 0; r < 4; ++r) {
        int ly = ty0 + 8 * r;
        float acc = s[ly + 0][tx + 0] * w[0] + s[ly + 0][tx + 1] * w[1] + s[ly + 0][tx + 2] * w[2]
                  + s[ly + 1][tx + 0] * w[3] + s[ly + 1][tx + 1] * w[4] + s[ly + 1][tx + 2] * w[5]
                  + s[ly + 2][tx + 0] * w[6] + s[ly + 2][tx + 1] * w[7] + s[ly + 2][tx + 2] * w[8];
        ss += acc * acc;
        size_t idx = base + (size_t)(blockIdx.y * 32 + ly) * W_ + blockIdx.x * 32 + tx;
        __nv_bfloat16 hh = __float2bfloat16(acc);
        outh[idx] = hh;
        outl[idx] = __float2bfloat16(acc - __bfloat162float(hh));
    }

    if (c < 2 * C_) {
        __shared__ float red[8];
#pragma unroll
        for (int o = 16; o > 0; o >>= 1) ss += __shfl_xor_sync(0xffffffffu, ss, o);
        if ((threadIdx.x & 31) == 0) red[threadIdx.x >> 5] = ss;
        __syncthreads();
        if (threadIdx.x == 0) {
            float tot = 0.f;
#pragma unroll
            for (int i = 0; i < 8; ++i) tot += red[i];
            if (c < C_)
                partq[((b * C_ + c) * 8 + blockIdx.y) * 8 + blockIdx.x] = tot;
            else
                partk[((b * C_ + (c - C_)) * 8 + blockIdx.y) * 8 + blockIdx.x] = tot;
        }
    }
}

__global__ void norms_finish(
    const float* __restrict__ partq, const float* __restrict__ partk,
    float* __restrict__ invq, float* __restrict__ invk)
{
    int idx = blockIdx.x * blockDim.x + threadIdx.x;
    if (idx < B_ * C_ * 8) {
        float sq = 0.f, sk = 0.f;
#pragma unroll
        for (int i = 0; i < 8; ++i) { sq += partq[idx * 8 + i]; sk += partk[idx * 8 + i]; }
        invq[idx] = 1.f / fmaxf(sqrtf(sq), 1e-12f);
        invk[idx] = 1.f / fmaxf(sqrtf(sk), 1e-12f);
    }
}

// ---------------- split-K reduce + scale + softmax -> bf16 h/l ---------------
__global__ void softmax_kernel(
    const float* __restrict__ gramp, const float* __restrict__ invq,
    const float* __restrict__ invk, const float* __restrict__ temp,
    __nv_bfloat16* __restrict__ attnh, __nv_bfloat16* __restrict__ attnl)
{
    const int i = blockIdx.x % C_;
    const int bh = blockIdx.x / C_;
    const int head = bh & 7, b = bh >> 3;
    const int j = threadIdx.x;              // 192 threads

    const long long base = (long long)bh * (C_ * C_) + i * C_ + j;
    float s = 0.f;
#pragma unroll
    for (int ks = 0; ks < KSPLIT_; ++ks)
        s += gramp[(long long)ks * (B_ * HEADS_ * C_ * C_) + base];

    s *= invq[(b * C_ + head * 24 + (i >> 3)) * 8 + (i & 7)]
       * invk[(b * C_ + head * 24 + (j >> 3)) * 8 + (j & 7)]
       * temp[head];

    __shared__ float red[8];
    float m = s;
#pragma unroll
    for (int o = 16; o > 0; o >>= 1) m = fmaxf(m, __shfl_xor_sync(0xffffffffu, m, o));
    if ((threadIdx.x & 31) == 0) red[threadIdx.x >> 5] = m;
    __syncthreads();
    m = fmaxf(fmaxf(fmaxf(red[0], red[1]), fmaxf(red[2], red[3])), fmaxf(red[4], red[5]));

    float p = expf(s - m);
    float sum = p;
#pragma unroll
    for (int o = 16; o > 0; o >>= 1) sum += __shfl_xor_sync(0xffffffffu, sum, o);
    __syncthreads();
    if ((threadIdx.x & 31) == 0) red[threadIdx.x >> 5] = sum;
    __syncthreads();
    sum = red[0] + red[1] + red[2] + red[3] + red[4] + red[5];

    float v = p / sum;
    __nv_bfloat16 hh = __float2bfloat16(v);
    attnh[base] = hh;
    attnl[base] = __float2bfloat16(v - __bfloat162float(hh));
}

// ---------------- launch -------------------------------------------------------
extern "C" void kernel_launch(void* const* d_in, const int* in_sizes, int n_in,
                              void* d_out, int out_size)
{
    const float* x      = (const float*)d_in[0];
    const float* qkv_w  = (const float*)d_in[1];
    const float* dw_w   = (const float*)d_in[2];
    const float* proj_w = (const float*)d_in[3];
    const float* temp   = (const float*)d_in[4];
    float* out = (float*)d_out;

    __nv_bfloat16 *xh, *xl, *wqh, *wql, *wph, *wpl;
    __nv_bfloat16 *qkvh, *qkvl, *dwh, *dwl, *avh, *avl, *attnh, *attnl;
    float *gramp, *partq, *partk, *invq, *invk;
    cudaGetSymbolAddress((void**)&xh,   g_xh);
    cudaGetSymbolAddress((void**)&xl,   g_xl);
    cudaGetSymbolAddress((void**)&wqh,  g_wqh);
    cudaGetSymbolAddress((void**)&wql,  g_wql);
    cudaGetSymbolAddress((void**)&wph,  g_wph);
    cudaGetSymbolAddress((void**)&wpl,  g_wpl);
    cudaGetSymbolAddress((void**)&qkvh, g_qkvh);
    cudaGetSymbolAddress((void**)&qkvl, g_qkvl);
    cudaGetSymbolAddress((void**)&dwh,  g_dwh);
    cudaGetSymbolAddress((void**)&dwl,  g_dwl);
    cudaGetSymbolAddress((void**)&avh,  g_avh);
    cudaGetSymbolAddress((void**)&avl,  g_avl);
    cudaGetSymbolAddress((void**)&attnh, g_attnh);
    cudaGetSymbolAddress((void**)&attnl, g_attnl);
    cudaGetSymbolAddress((void**)&gramp, g_gramp);
    cudaGetSymbolAddress((void**)&partq, g_partq);
    cudaGetSymbolAddress((void**)&partk, g_partk);
    cudaGetSymbolAddress((void**)&invq,  g_invq);
    cudaGetSymbolAddress((void**)&invk,  g_invk);

    // 0) pre-split fp32 operands into bf16 hi/lo
    split_kernel<<<(B_ * C_ * HW_ / 4 + 255) / 256, 256>>>(x, xh, xl, B_ * C_ * HW_);
    split_kernel<<<(C3_ * C_ / 4 + 255) / 256, 256>>>(qkv_w, wqh, wql, C3_ * C_);
    split_kernel<<<(C_ * C_ / 4 + 255) / 256, 256>>>(proj_w, wph, wpl, C_ * C_);

    // 1) qkv = qkv_w @ x   (grid: x=m-tiles, y=n-tiles for B-tile L2 reuse)
    {
        QkvMap m{wqh, wql, xh, xl, qkvh, qkvl};
        gemm_mma<QkvMap><<<dim3(C3_ / 96, HW_ / 128, B_), 256>>>(m, C_);
    }
    // 2) depthwise 3x3 + fused norm partials
    dw_kernel<<<dim3(W_ / 32, H_ / 32, B_ * C3_), 256>>>(qkvh, qkvl, dw_w, dwh, dwl, partq, partk);
    // 3) finish norms
    norms_finish<<<(B_ * C_ * 8 + 255) / 256, 256>>>(partq, partk, invq, invk);
    // 4) gram partials (split-K = 4)
    gram_mma<<<dim3(2, 2, B_ * HEADS_ * KSPLIT_), 256>>>(dwh, dwl, gramp);
    // 5) softmax -> bf16 h/l attn
    softmax_kernel<<<B_ * HEADS_ * C_, C_>>>(gramp, invq, invk, temp, attnh, attnl);
    // 6) attn @ v
    {
        AvMap m{attnh, attnl, dwh, dwl, avh, avl};
        gemm_mma<AvMap><<<dim3(C_ / 96, HW_ / HEADS_ / 128, B_ * HEADS_), 256>>>(m, C_);
    }
    // 7) out = proj_w @ av
    {
        ProjMap m{wph, wpl, avh, avl, out};
        gemm_mma<ProjMap><<<dim3(C_ / 96, HW_ / 128, B_), 256>>>(m, C_);
    }
}

// round 8
// speedup vs baseline: 1.2271x; 1.2271x over previous
#include <cuda_runtime.h>
#include <cuda_fp16.h>
#include <cstdint>

#define B_      2
#define C_      192
#define C3_     576
#define H_      256
#define W_      256
#define HW_     65536
#define HEADS_  8
#define KSPLIT_ 8

// ---------------- scratch (device globals: allocation-free rule) ----------------
__device__ __half g_xh  [(size_t)B_ * C_ * HW_];                 // x -> fp16 (B side of QKV)
__device__ __half g_wqh [C3_ * C_];
__device__ __half g_wql [C3_ * C_];
__device__ __half g_wph [C_ * C_];
__device__ __half g_wpl [C_ * C_];
__device__ __half g_qkvh[(size_t)B_ * C3_ * HW_];                // qkv hi
__device__ __half g_qkvl[(size_t)B_ * C3_ * HW_];                // qkv lo
__device__ __half g_dwh [(size_t)B_ * C3_ * HW_];                // dw out hi (q,k,v)
__device__ __half g_dwl [(size_t)B_ * C_ * HW_];                 // dw out lo (q channels only)
__device__ __half g_av  [(size_t)B_ * C_ * HW_];                 // attn@v (fp16, hi only)
__device__ float  g_gramp[(size_t)KSPLIT_ * B_ * HEADS_ * C_ * C_];
__device__ __half g_attnh[(size_t)B_ * HEADS_ * C_ * C_];
__device__ __half g_attnl[(size_t)B_ * HEADS_ * C_ * C_];
__device__ float g_partq[B_ * C_ * 64];
__device__ float g_partk[B_ * C_ * 64];
__device__ float g_invq [B_ * C_ * 8];
__device__ float g_invk [B_ * C_ * 8];

// ---------------- mma / ldmatrix / cp.async helpers ----------------
__device__ __forceinline__ void ldsm4(unsigned* r, const void* p) {
    unsigned a = (unsigned)__cvta_generic_to_shared(p);
    asm volatile("ldmatrix.sync.aligned.m8n8.x4.shared.b16 {%0,%1,%2,%3}, [%4];"
                 : "=r"(r[0]), "=r"(r[1]), "=r"(r[2]), "=r"(r[3]) : "r"(a));
}
__device__ __forceinline__ void ldsm2t(unsigned* r, const void* p) {
    unsigned a = (unsigned)__cvta_generic_to_shared(p);
    asm volatile("ldmatrix.sync.aligned.m8n8.x2.trans.shared.b16 {%0,%1}, [%2];"
                 : "=r"(r[0]), "=r"(r[1]) : "r"(a));
}
__device__ __forceinline__ void ldsm2(unsigned* r, const void* p) {
    unsigned a = (unsigned)__cvta_generic_to_shared(p);
    asm volatile("ldmatrix.sync.aligned.m8n8.x2.shared.b16 {%0,%1}, [%2];"
                 : "=r"(r[0]), "=r"(r[1]) : "r"(a));
}
__device__ __forceinline__ void mma16816(float* c, const unsigned* a, const unsigned* b) {
    asm volatile("mma.sync.aligned.m16n8k16.row.col.f32.f16.f16.f32 "
                 "{%0,%1,%2,%3},{%4,%5,%6,%7},{%8,%9},{%0,%1,%2,%3};"
                 : "+f"(c[0]), "+f"(c[1]), "+f"(c[2]), "+f"(c[3])
                 : "r"(a[0]), "r"(a[1]), "r"(a[2]), "r"(a[3]), "r"(b[0]), "r"(b[1]));
}
__device__ __forceinline__ void cpa16(unsigned dst, const void* src) {
    asm volatile("cp.async.cg.shared.global [%0], [%1], 16;\n" :: "r"(dst), "l"(src));
}
#define CP_COMMIT() asm volatile("cp.async.commit_group;\n")
#define CP_WAIT0()  asm volatile("cp.async.wait_group 0;\n")

__device__ __forceinline__ void st_pair_h(__half* ph, __half* pl, float x, float y) {
    __half hx = __float2half(x), hy = __float2half(y);
    __half2 hp; hp.x = hx; hp.y = hy; *(__half2*)ph = hp;
    __half2 lp;
    lp.x = __float2half(x - __half2float(hx));
    lp.y = __float2half(y - __half2float(hy));
    *(__half2*)pl = lp;
}

// ---------------- fp32 -> fp16 split kernels ----------------
__global__ __launch_bounds__(256) void split_hl_kernel(
    const float* __restrict__ in, __half* __restrict__ oh,
    __half* __restrict__ ol, int n)
{
    int i = (blockIdx.x * 256 + threadIdx.x) * 4;
    if (i < n) {
        float4 v = *(const float4*)(in + i);
        st_pair_h(oh + i,     ol + i,     v.x, v.y);
        st_pair_h(oh + i + 2, ol + i + 2, v.z, v.w);
    }
}
__global__ __launch_bounds__(256) void split_h_kernel(
    const float* __restrict__ in, __half* __restrict__ oh, int n)
{
    int i = (blockIdx.x * 256 + threadIdx.x) * 4;
    if (i < n) {
        float4 v = *(const float4*)(in + i);
        __half2 a; a.x = __float2half(v.x); a.y = __float2half(v.y);
        __half2 b; b.x = __float2half(v.z); b.y = __float2half(v.w);
        ((__half2*)(oh + i))[0] = a;
        ((__half2*)(oh + i))[1] = b;
    }
}

// ---------------- maps ----------------
struct QkvMap {
    const __half *Ah, *Al, *B; __half *Ch, *Cl;
    static constexpr int CMODE = 0;                    // fp16 h/l pair out
    static constexpr size_t BSTRIDE32 = (size_t)32 * HW_;
    __device__ const __half* aRowH(int z, int m) const { return Ah + (size_t)m * C_; }
    __device__ const __half* aRowL(int z, int m) const { return Al + (size_t)m * C_; }
    __device__ const __half* bRow(int z, int k) const { return B + ((size_t)z * C_ + k) * HW_; }
    __device__ __half* cRowH(int z, int m) const { return Ch + ((size_t)z * C3_ + m) * HW_; }
    __device__ __half* cRowL(int z, int m) const { return Cl + ((size_t)z * C3_ + m) * HW_; }
    __device__ __half* cRow(int z, int m) const { return nullptr; }
    __device__ float*  cRowF(int z, int m) const { return nullptr; }
};
struct AvMap {
    const __half *Ah, *Al, *B; __half *Cc;
    static constexpr int CMODE = 1;                    // fp16 single out
    static constexpr size_t BSTRIDE32 = (size_t)4 << 16;
    __device__ const __half* aRowH(int z, int m) const { return Ah + (size_t)z * (C_ * C_) + (size_t)m * C_; }
    __device__ const __half* aRowL(int z, int m) const { return Al + (size_t)z * (C_ * C_) + (size_t)m * C_; }
    __device__ const __half* bRow(int z, int k) const {
        int b = z >> 3, h = z & 7;
        return B + ((size_t)(b * C3_ + 2 * C_ + h * 24 + (k >> 3)) << 16) + ((k & 7) << 13);
    }
    __device__ __half* cRow(int z, int m) const {
        int b = z >> 3, h = z & 7;
        return Cc + ((size_t)(b * C_ + h * 24 + (m >> 3)) << 16) + ((m & 7) << 13);
    }
    __device__ __half* cRowH(int z, int m) const { return nullptr; }
    __device__ __half* cRowL(int z, int m) const { return nullptr; }
    __device__ float*  cRowF(int z, int m) const { return nullptr; }
};
struct ProjMap {
    const __half *Ah, *Al, *B; float* C;
    static constexpr int CMODE = 2;                    // fp32 out
    static constexpr size_t BSTRIDE32 = (size_t)32 * HW_;
    __device__ const __half* aRowH(int z, int m) const { return Ah + (size_t)m * C_; }
    __device__ const __half* aRowL(int z, int m) const { return Al + (size_t)m * C_; }
    __device__ const __half* bRow(int z, int k) const { return B + ((size_t)z * C_ + k) * HW_; }
    __device__ float* cRowF(int z, int m) const { return C + ((size_t)z * C_ + m) * HW_; }
    __device__ __half* cRowH(int z, int m) const { return nullptr; }
    __device__ __half* cRowL(int z, int m) const { return nullptr; }
    __device__ __half* cRow(int z, int m) const { return nullptr; }
};

// =====================================================================
// fp16-split MMA GEMM: C = (Ah+Al) @ Bh.  BM=96 BN=128 BK=32,
// 2-stage cp.async, 256 threads, warp tile 48x32. 24 MMA / kk-pair.
// =====================================================================
template <class Map>
__global__ __launch_bounds__(256, 2) void gemm_mma(const Map map, const int K)
{
    __shared__ alignas(16) __half Ash[2][96][40];
    __shared__ alignas(16) __half Asl[2][96][40];
    __shared__ alignas(16) __half Bs [2][32][136];
    constexpr unsigned ASTG = 96 * 40 * 2;
    constexpr unsigned BSTG = 32 * 136 * 2;

    const int z = blockIdx.z, bm = blockIdx.y * 96, bn = blockIdx.x * 128;
    const int tid = threadIdx.x, lane = tid & 31, w = tid >> 5;
    const int m0 = (w >> 2) * 48, n0 = (w & 3) * 32;

    // A loaders: 768 chunks (384 h + 384 l), 3 iters
    const __half* asrc[3]; unsigned adst[3];
#pragma unroll
    for (int it = 0; it < 3; ++it) {
        int idx = tid + it * 256;
        int which = idx / 384, w2 = idx % 384;
        int row = w2 >> 2, c4 = w2 & 3;
        const __half* base = which ? map.aRowL(z, bm + row) : map.aRowH(z, bm + row);
        asrc[it] = base + c4 * 8;
        adst[it] = (unsigned)__cvta_generic_to_shared(which ? &Asl[0][row][c4 * 8] : &Ash[0][row][c4 * 8]);
    }
    // B loaders: 512 chunks, 2 iters
    const __half* bsrc[2]; unsigned bdst[2];
#pragma unroll
    for (int it = 0; it < 2; ++it) {
        int idx = tid + it * 256;
        int row = idx >> 4, c4 = idx & 15;
        bsrc[it] = map.bRow(z, row) + bn + c4 * 8;
        bdst[it] = (unsigned)__cvta_generic_to_shared(&Bs[0][row][c4 * 8]);
    }

    float acc[3][4][4];
#pragma unroll
    for (int i = 0; i < 3; ++i)
#pragma unroll
        for (int j = 0; j < 4; ++j)
#pragma unroll
            for (int q = 0; q < 4; ++q) acc[i][j][q] = 0.f;

    const int nStage = K >> 5;
    {
#pragma unroll
        for (int it = 0; it < 3; ++it) cpa16(adst[it], asrc[it]);
#pragma unroll
        for (int it = 0; it < 2; ++it) cpa16(bdst[it], bsrc[it]);
        CP_COMMIT();
    }
    int buf = 0;
#pragma unroll 1
    for (int s = 0; s < nStage; ++s) {
        CP_WAIT0();
        __syncthreads();
        if (s + 1 < nStage) {
            const unsigned ao = (buf ^ 1) * ASTG, bo = (buf ^ 1) * BSTG;
            const int ka = (s + 1) * 32;
            const size_t kb = (size_t)(s + 1) * Map::BSTRIDE32;
#pragma unroll
            for (int it = 0; it < 3; ++it) cpa16(adst[it] + ao, asrc[it] + ka);
#pragma unroll
            for (int it = 0; it < 2; ++it) cpa16(bdst[it] + bo, bsrc[it] + kb);
            CP_COMMIT();
        }
#pragma unroll
        for (int kk = 0; kk < 32; kk += 16) {
            unsigned ah[3][4], al[3][4], bh[4][2];
            const int l15 = lane & 15;
#pragma unroll
            for (int mi = 0; mi < 3; ++mi) {
                ldsm4(ah[mi], &Ash[buf][m0 + mi * 16 + l15][kk + (lane >> 4) * 8]);
                ldsm4(al[mi], &Asl[buf][m0 + mi * 16 + l15][kk + (lane >> 4) * 8]);
            }
#pragma unroll
            for (int ni = 0; ni < 4; ++ni)
                ldsm2t(bh[ni], &Bs[buf][kk + l15][n0 + ni * 8]);
#pragma unroll
            for (int mi = 0; mi < 3; ++mi)
#pragma unroll
                for (int ni = 0; ni < 4; ++ni) {
                    mma16816(acc[mi][ni], ah[mi], bh[ni]);
                    mma16816(acc[mi][ni], al[mi], bh[ni]);
                }
        }
        buf ^= 1;
    }

#pragma unroll
    for (int mi = 0; mi < 3; ++mi)
#pragma unroll
        for (int ni = 0; ni < 4; ++ni) {
            const int r = bm + m0 + mi * 16 + (lane >> 2);
            const int cc = bn + n0 + ni * 8 + (lane & 3) * 2;
            const float* a = acc[mi][ni];
            if constexpr (Map::CMODE == 0) {
                st_pair_h(map.cRowH(z, r) + cc,     map.cRowL(z, r) + cc,     a[0], a[1]);
                st_pair_h(map.cRowH(z, r + 8) + cc, map.cRowL(z, r + 8) + cc, a[2], a[3]);
            } else if constexpr (Map::CMODE == 1) {
                __half2 v0; v0.x = __float2half(a[0]); v0.y = __float2half(a[1]);
                __half2 v1; v1.x = __float2half(a[2]); v1.y = __float2half(a[3]);
                *(__half2*)(map.cRow(z, r) + cc)     = v0;
                *(__half2*)(map.cRow(z, r + 8) + cc) = v1;
            } else {
                *(float2*)(map.cRowF(z, r) + cc)     = make_float2(a[0], a[1]);
                *(float2*)(map.cRowF(z, r + 8) + cc) = make_float2(a[2], a[3]);
            }
        }
}

// =====================================================================
// Gram: C[i,j] = sum_n q[i,n]*k[j,n].  q split h/l, k hi only.
// BM=BN=96 BK=32, split-K=8, 2-stage cp.async. 18 MMA / kk-pair.
// =====================================================================
__global__ __launch_bounds__(256, 2) void gram_mma(
    const __half* __restrict__ dwh, const __half* __restrict__ dwl,
    float* __restrict__ gramp)
{
    __shared__ alignas(16) __half Ash[2][96][40];
    __shared__ alignas(16) __half Asl[2][96][40];
    __shared__ alignas(16) __half Bsh[2][96][40];
    constexpr unsigned STG = 96 * 40 * 2;
    constexpr int KS_LEN = 8192 / KSPLIT_;          // 1024
    constexpr int NSTG = KS_LEN / 32;               // 32

    const int z = blockIdx.z;
    const int ks = z & (KSPLIT_ - 1), bh_ = z / KSPLIT_;
    const int h = bh_ & 7, b = bh_ >> 3;
    const int bi = blockIdx.y * 96, bj = blockIdx.x * 96;
    const int tid = threadIdx.x, lane = tid & 31, w = tid >> 5;
    const int m0 = (w >> 2) * 48, n0 = (w & 3) * 24;
    const int kbase = ks * KS_LEN;

    // 1152 chunks: 0..383 qh, 384..767 ql, 768..1151 kh ; 5 iters (last partial)
    const __half* src[5]; unsigned dst[5]; bool val[5];
#pragma unroll
    for (int it = 0; it < 5; ++it) {
        int idx = tid + it * 256;
        val[it] = idx < 1152;
        int which = idx / 384; if (which > 2) which = 2;
        int w2 = idx % 384;
        int row = w2 >> 2, c4 = w2 & 3;
        size_t off;
        const __half* basep;
        if (which == 0) {
            int qi = bi + row;
            off = ((size_t)(b * C3_ + h * 24 + (qi >> 3)) << 16) + ((size_t)(qi & 7) << 13);
            basep = dwh;
        } else if (which == 1) {
            int qi = bi + row;
            off = ((size_t)(b * C_ + h * 24 + (qi >> 3)) << 16) + ((size_t)(qi & 7) << 13);
            basep = dwl;
        } else {
            int kj = bj + row;
            off = ((size_t)(b * C3_ + C_ + h * 24 + (kj >> 3)) << 16) + ((size_t)(kj & 7) << 13);
            basep = dwh;
        }
        src[it] = basep + off + kbase + c4 * 8;
        __half* d;
        if      (which == 0) d = &Ash[0][row][c4 * 8];
        else if (which == 1) d = &Asl[0][row][c4 * 8];
        else                 d = &Bsh[0][row][c4 * 8];
        dst[it] = (unsigned)__cvta_generic_to_shared(d);
    }

    float acc[3][3][4];
#pragma unroll
    for (int i = 0; i < 3; ++i)
#pragma unroll
        for (int j = 0; j < 3; ++j)
#pragma unroll
            for (int q = 0; q < 4; ++q) acc[i][j][q] = 0.f;

    {
#pragma unroll
        for (int it = 0; it < 5; ++it) if (val[it]) cpa16(dst[it], src[it]);
        CP_COMMIT();
    }
    int buf = 0;
#pragma unroll 1
    for (int s = 0; s < NSTG; ++s) {
        CP_WAIT0();
        __syncthreads();
        if (s + 1 < NSTG) {
            const unsigned o = (buf ^ 1) * STG;
            const int ka = (s + 1) * 32;
#pragma unroll
            for (int it = 0; it < 5; ++it) if (val[it]) cpa16(dst[it] + o, src[it] + ka);
            CP_COMMIT();
        }
#pragma unroll
        for (int kk = 0; kk < 32; kk += 16) {
            unsigned ah[3][4], al[3][4], bh2[3][2];
            const int l15 = lane & 15;
#pragma unroll
            for (int mi = 0; mi < 3; ++mi) {
                ldsm4(ah[mi], &Ash[buf][m0 + mi * 16 + l15][kk + (lane >> 4) * 8]);
                ldsm4(al[mi], &Asl[buf][m0 + mi * 16 + l15][kk + (lane >> 4) * 8]);
            }
#pragma unroll
            for (int ni = 0; ni < 3; ++ni)
                ldsm2(bh2[ni], &Bsh[buf][n0 + ni * 8 + (l15 & 7)][kk + ((l15 >> 3) << 3)]);
#pragma unroll
            for (int mi = 0; mi < 3; ++mi)
#pragma unroll
                for (int ni = 0; ni < 3; ++ni) {
                    mma16816(acc[mi][ni], ah[mi], bh2[ni]);
                    mma16816(acc[mi][ni], al[mi], bh2[ni]);
                }
        }
        buf ^= 1;
    }

    float* gp = gramp + ((size_t)ks * (B_ * HEADS_) + bh_) * (C_ * C_);
#pragma unroll
    for (int mi = 0; mi < 3; ++mi)
#pragma unroll
        for (int ni = 0; ni < 3; ++ni) {
            const int r = bi + m0 + mi * 16 + (lane >> 2);
            const int cc = bj + n0 + ni * 8 + (lane & 3) * 2;
            const float* a = acc[mi][ni];
            *(float2*)(gp + (size_t)r * C_ + cc)       = make_float2(a[0], a[1]);
            *(float2*)(gp + (size_t)(r + 8) * C_ + cc) = make_float2(a[2], a[3]);
        }
}

// ---------------- depthwise 3x3 (fp16 h/l in) + norm partials -----------------
__global__ __launch_bounds__(256) void dw_kernel(
    const __half* __restrict__ inh, const __half* __restrict__ inl,
    const float* __restrict__ dww,
    __half* __restrict__ outh, __half* __restrict__ outl,
    float* __restrict__ partq, float* __restrict__ partk)
{
    const int chg = blockIdx.z;            // b*576 + c
    const int c = chg % C3_;
    const int b = chg / C3_;
    const size_t base = (size_t)chg << 16;

    float w[9];
#pragma unroll
    for (int i = 0; i < 9; ++i) w[i] = __ldg(&dww[c * 9 + i]);

    __shared__ float s[34][34];
    const int ox = blockIdx.x * 32 - 1, oy = blockIdx.y * 32 - 1;
    for (int t = threadIdx.x; t < 34 * 34; t += 256) {
        int lx = t % 34, ly = t / 34;
        int gx = ox + lx, gy = oy + ly;
        float v = 0.f;
        if ((unsigned)gx < W_ && (unsigned)gy < H_) {
            size_t idx = base + gy * W_ + gx;
            v = __half2float(inh[idx]) + __half2float(inl[idx]);
        }
        s[ly][lx] = v;
    }
    __syncthreads();

    const int tx = threadIdx.x & 31, ty0 = threadIdx.x >> 5;
    float ss = 0.f;
#pragma unroll
    for (int r = 0; r < 4; ++r) {
        int ly = ty0 + 8 * r;
        float acc = s[ly + 0][tx + 0] * w[0] + s[ly + 0][tx + 1] * w[1] + s[ly + 0][tx + 2] * w[2]
                  + s[ly + 1][tx + 0] * w[3] + s[ly + 1][tx + 1] * w[4] + s[ly + 1][tx + 2] * w[5]
                  + s[ly + 2][tx + 0] * w[6] + s[ly + 2][tx + 1] * w[7] + s[ly + 2][tx + 2] * w[8];
        ss += acc * acc;
        size_t sp = (size_t)(blockIdx.y * 32 + ly) * W_ + blockIdx.x * 32 + tx;
        __half hh = __float2half(acc);
        outh[base + sp] = hh;
        if (c < C_)
            outl[(((size_t)(b * C_ + c)) << 16) + sp] = __float2half(acc - __half2float(hh));
    }

    if (c < 2 * C_) {
        __shared__ float red[8];
#pragma unroll
        for (int o = 16; o > 0; o >>= 1) ss += __shfl_xor_sync(0xffffffffu, ss, o);
        if ((threadIdx.x & 31) == 0) red[threadIdx.x >> 5] = ss;
        __syncthreads();
        if (threadIdx.x == 0) {
            float tot = 0.f;
#pragma unroll
            for (int i = 0; i < 8; ++i) tot += red[i];
            if (c < C_)
                partq[((b * C_ + c) * 8 + blockIdx.y) * 8 + blockIdx.x] = tot;
            else
                partk[((b * C_ + (c - C_)) * 8 + blockIdx.y) * 8 + blockIdx.x] = tot;
        }
    }
}

__global__ void norms_finish(
    const float* __restrict__ partq, const float* __restrict__ partk,
    float* __restrict__ invq, float* __restrict__ invk)
{
    int idx = blockIdx.x * blockDim.x + threadIdx.x;
    if (idx < B_ * C_ * 8) {
        float sq = 0.f, sk = 0.f;
#pragma unroll
        for (int i = 0; i < 8; ++i) { sq += partq[idx * 8 + i]; sk += partk[idx * 8 + i]; }
        invq[idx] = 1.f / fmaxf(sqrtf(sq), 1e-12f);
        invk[idx] = 1.f / fmaxf(sqrtf(sk), 1e-12f);
    }
}

// ---------------- split-K reduce + scale + softmax -> fp16 h/l ---------------
__global__ void softmax_kernel(
    const float* __restrict__ gramp, const float* __restrict__ invq,
    const float* __restrict__ invk, const float* __restrict__ temp,
    __half* __restrict__ attnh, __half* __restrict__ attnl)
{
    const int i = blockIdx.x % C_;
    const int bh = blockIdx.x / C_;
    const int head = bh & 7, b = bh >> 3;
    const int j = threadIdx.x;

    const long long base = (long long)bh * (C_ * C_) + i * C_ + j;
    float s = 0.f;
#pragma unroll
    for (int ks = 0; ks < KSPLIT_; ++ks)
        s += gramp[(long long)ks * (B_ * HEADS_ * C_ * C_) + base];

    s *= invq[(b * C_ + head * 24 + (i >> 3)) * 8 + (i & 7)]
       * invk[(b * C_ + head * 24 + (j >> 3)) * 8 + (j & 7)]
       * temp[head];

    __shared__ float red[8];
    float m = s;
#pragma unroll
    for (int o = 16; o > 0; o >>= 1) m = fmaxf(m, __shfl_xor_sync(0xffffffffu, m, o));
    if ((threadIdx.x & 31) == 0) red[threadIdx.x >> 5] = m;
    __syncthreads();
    m = fmaxf(fmaxf(fmaxf(red[0], red[1]), fmaxf(red[2], red[3])), fmaxf(red[4], red[5]));

    float p = expf(s - m);
    float sum = p;
#pragma unroll
    for (int o = 16; o > 0; o >>= 1) sum += __shfl_xor_sync(0xffffffffu, sum, o);
    __syncthreads();
    if ((threadIdx.x & 31) == 0) red[threadIdx.x >> 5] = sum;
    __syncthreads();
    sum = red[0] + red[1] + red[2] + red[3] + red[4] + red[5];

    float v = p / sum;
    __half hh = __float2half(v);
    attnh[base] = hh;
    attnl[base] = __float2half(v - __half2float(hh));
}

// ---------------- launch -------------------------------------------------------
extern "C" void kernel_launch(void* const* d_in, const int* in_sizes, int n_in,
                              void* d_out, int out_size)
{
    const float* x      = (const float*)d_in[0];
    const float* qkv_w  = (const float*)d_in[1];
    const float* dw_w   = (const float*)d_in[2];
    const float* proj_w = (const float*)d_in[3];
    const float* temp   = (const float*)d_in[4];
    float* out = (float*)d_out;

    __half *xh, *wqh, *wql, *wph, *wpl, *qkvh, *qkvl, *dwh, *dwl, *av, *attnh, *attnl;
    float *gramp, *partq, *partk, *invq, *invk;
    cudaGetSymbolAddress((void**)&xh,   g_xh);
    cudaGetSymbolAddress((void**)&wqh,  g_wqh);
    cudaGetSymbolAddress((void**)&wql,  g_wql);
    cudaGetSymbolAddress((void**)&wph,  g_wph);
    cudaGetSymbolAddress((void**)&wpl,  g_wpl);
    cudaGetSymbolAddress((void**)&qkvh, g_qkvh);
    cudaGetSymbolAddress((void**)&qkvl, g_qkvl);
    cudaGetSymbolAddress((void**)&dwh,  g_dwh);
    cudaGetSymbolAddress((void**)&dwl,  g_dwl);
    cudaGetSymbolAddress((void**)&av,   g_av);
    cudaGetSymbolAddress((void**)&attnh, g_attnh);
    cudaGetSymbolAddress((void**)&attnl, g_attnl);
    cudaGetSymbolAddress((void**)&gramp, g_gramp);
    cudaGetSymbolAddress((void**)&partq, g_partq);
    cudaGetSymbolAddress((void**)&partk, g_partk);
    cudaGetSymbolAddress((void**)&invq,  g_invq);
    cudaGetSymbolAddress((void**)&invk,  g_invk);

    // 0) splits: weights h/l, x h only
    split_h_kernel<<<(B_ * C_ * HW_ / 4 + 255) / 256, 256>>>(x, xh, B_ * C_ * HW_);
    split_hl_kernel<<<(C3_ * C_ / 4 + 255) / 256, 256>>>(qkv_w, wqh, wql, C3_ * C_);
    split_hl_kernel<<<(C_ * C_ / 4 + 255) / 256, 256>>>(proj_w, wph, wpl, C_ * C_);

    // 1) qkv = qkv_w @ x
    {
        QkvMap m{wqh, wql, xh, qkvh, qkvl};
        gemm_mma<QkvMap><<<dim3(HW_ / 128, C3_ / 96, B_), 256>>>(m, C_);
    }
    // 2) depthwise 3x3 + norm partials
    dw_kernel<<<dim3(W_ / 32, H_ / 32, B_ * C3_), 256>>>(qkvh, qkvl, dw_w, dwh, dwl, partq, partk);
    // 3) norms
    norms_finish<<<(B_ * C_ * 8 + 255) / 256, 256>>>(partq, partk, invq, invk);
    // 4) gram partials
    gram_mma<<<dim3(2, 2, B_ * HEADS_ * KSPLIT_), 256>>>(dwh, dwl, gramp);
    // 5) softmax
    softmax_kernel<<<B_ * HEADS_ * C_, C_>>>(gramp, invq, invk, temp, attnh, attnl);
    // 6) av = attn @ v
    {
        AvMap m{attnh, attnl, dwh, av};
        gemm_mma<AvMap><<<dim3(HW_ / HEADS_ / 128, C_ / 96, B_ * HEADS_), 256>>>(m, C_);
    }
    // 7) out = proj_w @ av
    {
        ProjMap m{wph, wpl, av, out};
        gemm_mma<ProjMap><<<dim3(HW_ / 128, C_ / 96, B_), 256>>>(m, C_);
    }
}

// round 9
// speedup vs baseline: 1.3731x; 1.1190x over previous
#include <cuda_runtime.h>
#include <cuda_fp16.h>
#include <cstdint>

#define B_      2
#define C_      192
#define C3_     576
#define H_      256
#define W_      256
#define HW_     65536
#define HEADS_  8
#define KSPLIT_ 8

// ---------------- scratch (device globals: allocation-free rule) ----------------
__device__ __half g_xh  [(size_t)B_ * C_ * HW_];                 // x -> fp16
__device__ __half g_wqh [C3_ * C_];
__device__ __half g_wql [C3_ * C_];
__device__ __half g_wph [C_ * C_];
__device__ __half g_wpl [C_ * C_];
__device__ __half g_qkvh[(size_t)B_ * C3_ * HW_];                // qkv (fp16 hi only)
__device__ __half g_dwh [(size_t)B_ * C3_ * HW_];                // dw out hi (q,k,v)
__device__ __half g_dwl [(size_t)B_ * C_ * HW_];                 // dw out lo (q only)
__device__ __half g_av  [(size_t)B_ * C_ * HW_];                 // attn@v (fp16)
__device__ float  g_gramp[(size_t)KSPLIT_ * B_ * HEADS_ * C_ * C_];
__device__ __half g_attnh[(size_t)B_ * HEADS_ * C_ * C_];
__device__ float g_partq[B_ * C_ * 64];
__device__ float g_partk[B_ * C_ * 64];
__device__ float g_invq [B_ * C_ * 8];
__device__ float g_invk [B_ * C_ * 8];

// ---------------- mma / ldmatrix / cp.async helpers ----------------
__device__ __forceinline__ void ldsm4(unsigned* r, const void* p) {
    unsigned a = (unsigned)__cvta_generic_to_shared(p);
    asm volatile("ldmatrix.sync.aligned.m8n8.x4.shared.b16 {%0,%1,%2,%3}, [%4];"
                 : "=r"(r[0]), "=r"(r[1]), "=r"(r[2]), "=r"(r[3]) : "r"(a));
}
__device__ __forceinline__ void ldsm2t(unsigned* r, const void* p) {
    unsigned a = (unsigned)__cvta_generic_to_shared(p);
    asm volatile("ldmatrix.sync.aligned.m8n8.x2.trans.shared.b16 {%0,%1}, [%2];"
                 : "=r"(r[0]), "=r"(r[1]) : "r"(a));
}
__device__ __forceinline__ void ldsm2(unsigned* r, const void* p) {
    unsigned a = (unsigned)__cvta_generic_to_shared(p);
    asm volatile("ldmatrix.sync.aligned.m8n8.x2.shared.b16 {%0,%1}, [%2];"
                 : "=r"(r[0]), "=r"(r[1]) : "r"(a));
}
__device__ __forceinline__ void mma16816(float* c, const unsigned* a, const unsigned* b) {
    asm volatile("mma.sync.aligned.m16n8k16.row.col.f32.f16.f16.f32 "
                 "{%0,%1,%2,%3},{%4,%5,%6,%7},{%8,%9},{%0,%1,%2,%3};"
                 : "+f"(c[0]), "+f"(c[1]), "+f"(c[2]), "+f"(c[3])
                 : "r"(a[0]), "r"(a[1]), "r"(a[2]), "r"(a[3]), "r"(b[0]), "r"(b[1]));
}
__device__ __forceinline__ void cpa16(unsigned dst, const void* src) {
    asm volatile("cp.async.cg.shared.global [%0], [%1], 16;\n" :: "r"(dst), "l"(src));
}
#define CP_COMMIT() asm volatile("cp.async.commit_group;\n")
#define CP_WAIT0()  asm volatile("cp.async.wait_group 0;\n")

__device__ __forceinline__ void st_pair_h(__half* ph, __half* pl, float x, float y) {
    __half hx = __float2half(x), hy = __float2half(y);
    __half2 hp; hp.x = hx; hp.y = hy; *(__half2*)ph = hp;
    __half2 lp;
    lp.x = __float2half(x - __half2float(hx));
    lp.y = __float2half(y - __half2float(hy));
    *(__half2*)pl = lp;
}

// ---------------- fp32 -> fp16 split kernels ----------------
__global__ __launch_bounds__(256) void split_hl_kernel(
    const float* __restrict__ in, __half* __restrict__ oh,
    __half* __restrict__ ol, int n)
{
    int i = (blockIdx.x * 256 + threadIdx.x) * 4;
    if (i < n) {
        float4 v = *(const float4*)(in + i);
        st_pair_h(oh + i,     ol + i,     v.x, v.y);
        st_pair_h(oh + i + 2, ol + i + 2, v.z, v.w);
    }
}
__global__ __launch_bounds__(256) void split_h_kernel(
    const float* __restrict__ in, __half* __restrict__ oh, int n)
{
    int i = (blockIdx.x * 256 + threadIdx.x) * 4;
    if (i < n) {
        float4 v = *(const float4*)(in + i);
        __half2 a; a.x = __float2half(v.x); a.y = __float2half(v.y);
        __half2 b; b.x = __float2half(v.z); b.y = __float2half(v.w);
        ((__half2*)(oh + i))[0] = a;
        ((__half2*)(oh + i))[1] = b;
    }
}

// ---------------- maps ----------------
struct QkvMap {
    const __half *Ah, *Al, *B; __half *Cc;
    static constexpr int CMODE = 1;                    // fp16 single out
    static constexpr bool A_SPLIT = true;
    static constexpr size_t BSTRIDE32 = (size_t)32 * HW_;
    __device__ const __half* aRowH(int z, int m) const { return Ah + (size_t)m * C_; }
    __device__ const __half* aRowL(int z, int m) const { return Al + (size_t)m * C_; }
    __device__ const __half* bRow(int z, int k) const { return B + ((size_t)z * C_ + k) * HW_; }
    __device__ __half* cRow(int z, int m) const { return Cc + ((size_t)z * C3_ + m) * HW_; }
    __device__ float*  cRowF(int z, int m) const { return nullptr; }
};
struct AvMap {
    const __half *Ah, *Al, *B; __half *Cc;
    static constexpr int CMODE = 1;                    // fp16 single out
    static constexpr bool A_SPLIT = false;             // attn hi only
    static constexpr size_t BSTRIDE32 = (size_t)4 << 16;
    __device__ const __half* aRowH(int z, int m) const { return Ah + (size_t)z * (C_ * C_) + (size_t)m * C_; }
    __device__ const __half* aRowL(int z, int m) const { return Ah; }
    __device__ const __half* bRow(int z, int k) const {
        int b = z >> 3, h = z & 7;
        return B + ((size_t)(b * C3_ + 2 * C_ + h * 24 + (k >> 3)) << 16) + ((k & 7) << 13);
    }
    __device__ __half* cRow(int z, int m) const {
        int b = z >> 3, h = z & 7;
        return Cc + ((size_t)(b * C_ + h * 24 + (m >> 3)) << 16) + ((m & 7) << 13);
    }
    __device__ float*  cRowF(int z, int m) const { return nullptr; }
};
struct ProjMap {
    const __half *Ah, *Al, *B; float* C;
    static constexpr int CMODE = 2;                    // fp32 out
    static constexpr bool A_SPLIT = true;
    static constexpr size_t BSTRIDE32 = (size_t)32 * HW_;
    __device__ const __half* aRowH(int z, int m) const { return Ah + (size_t)m * C_; }
    __device__ const __half* aRowL(int z, int m) const { return Al + (size_t)m * C_; }
    __device__ const __half* bRow(int z, int k) const { return B + ((size_t)z * C_ + k) * HW_; }
    __device__ float* cRowF(int z, int m) const { return C + ((size_t)z * C_ + m) * HW_; }
    __device__ __half* cRow(int z, int m) const { return nullptr; }
};

// =====================================================================
// fp16 MMA GEMM: C = (Ah [+Al]) @ B.  BM=96 BN=128 BK=32,
// 2-stage cp.async, 256 threads, warp tile 48x32.
// =====================================================================
template <class Map>
__global__ __launch_bounds__(256, 2) void gemm_mma(const Map map, const int K)
{
    __shared__ alignas(16) __half Ash[2][96][40];
    __shared__ alignas(16) __half Asl[2][96][40];
    __shared__ alignas(16) __half Bs [2][32][136];
    constexpr unsigned ASTG = 96 * 40 * 2;
    constexpr unsigned BSTG = 32 * 136 * 2;
    constexpr int NAIT = Map::A_SPLIT ? 3 : 2;
    constexpr int NACHUNK = Map::A_SPLIT ? 768 : 384;

    const int z = blockIdx.z, bm = blockIdx.y * 96, bn = blockIdx.x * 128;
    const int tid = threadIdx.x, lane = tid & 31, w = tid >> 5;
    const int m0 = (w >> 2) * 48, n0 = (w & 3) * 32;

    // A loaders
    const __half* asrc[NAIT]; unsigned adst[NAIT]; bool aval[NAIT];
#pragma unroll
    for (int it = 0; it < NAIT; ++it) {
        int idx = tid + it * 256;
        aval[it] = idx < NACHUNK;
        if (idx >= NACHUNK) idx = NACHUNK - 1;
        int which = idx / 384, w2 = idx % 384;
        int row = w2 >> 2, c4 = w2 & 3;
        const __half* base = which ? map.aRowL(z, bm + row) : map.aRowH(z, bm + row);
        asrc[it] = base + c4 * 8;
        adst[it] = (unsigned)__cvta_generic_to_shared(which ? &Asl[0][row][c4 * 8] : &Ash[0][row][c4 * 8]);
    }
    // B loaders: 512 chunks, 2 iters
    const __half* bsrc[2]; unsigned bdst[2];
#pragma unroll
    for (int it = 0; it < 2; ++it) {
        int idx = tid + it * 256;
        int row = idx >> 4, c4 = idx & 15;
        bsrc[it] = map.bRow(z, row) + bn + c4 * 8;
        bdst[it] = (unsigned)__cvta_generic_to_shared(&Bs[0][row][c4 * 8]);
    }

    float acc[3][4][4];
#pragma unroll
    for (int i = 0; i < 3; ++i)
#pragma unroll
        for (int j = 0; j < 4; ++j)
#pragma unroll
            for (int q = 0; q < 4; ++q) acc[i][j][q] = 0.f;

    const int nStage = K >> 5;
    {
#pragma unroll
        for (int it = 0; it < NAIT; ++it) if (aval[it]) cpa16(adst[it], asrc[it]);
#pragma unroll
        for (int it = 0; it < 2; ++it) cpa16(bdst[it], bsrc[it]);
        CP_COMMIT();
    }
    int buf = 0;
#pragma unroll 1
    for (int s = 0; s < nStage; ++s) {
        CP_WAIT0();
        __syncthreads();
        if (s + 1 < nStage) {
            const unsigned ao = (buf ^ 1) * ASTG, bo = (buf ^ 1) * BSTG;
            const int ka = (s + 1) * 32;
            const size_t kb = (size_t)(s + 1) * Map::BSTRIDE32;
#pragma unroll
            for (int it = 0; it < NAIT; ++it) if (aval[it]) cpa16(adst[it] + ao, asrc[it] + ka);
#pragma unroll
            for (int it = 0; it < 2; ++it) cpa16(bdst[it] + bo, bsrc[it] + kb);
            CP_COMMIT();
        }
#pragma unroll
        for (int kk = 0; kk < 32; kk += 16) {
            unsigned ah[3][4], al[3][4], bh[4][2];
            const int l15 = lane & 15;
#pragma unroll
            for (int mi = 0; mi < 3; ++mi) {
                ldsm4(ah[mi], &Ash[buf][m0 + mi * 16 + l15][kk + (lane >> 4) * 8]);
                if constexpr (Map::A_SPLIT)
                    ldsm4(al[mi], &Asl[buf][m0 + mi * 16 + l15][kk + (lane >> 4) * 8]);
            }
#pragma unroll
            for (int ni = 0; ni < 4; ++ni)
                ldsm2t(bh[ni], &Bs[buf][kk + l15][n0 + ni * 8]);
#pragma unroll
            for (int mi = 0; mi < 3; ++mi)
#pragma unroll
                for (int ni = 0; ni < 4; ++ni) {
                    mma16816(acc[mi][ni], ah[mi], bh[ni]);
                    if constexpr (Map::A_SPLIT)
                        mma16816(acc[mi][ni], al[mi], bh[ni]);
                }
        }
        buf ^= 1;
    }

#pragma unroll
    for (int mi = 0; mi < 3; ++mi)
#pragma unroll
        for (int ni = 0; ni < 4; ++ni) {
            const int r = bm + m0 + mi * 16 + (lane >> 2);
            const int cc = bn + n0 + ni * 8 + (lane & 3) * 2;
            const float* a = acc[mi][ni];
            if constexpr (Map::CMODE == 1) {
                __half2 v0; v0.x = __float2half(a[0]); v0.y = __float2half(a[1]);
                __half2 v1; v1.x = __float2half(a[2]); v1.y = __float2half(a[3]);
                *(__half2*)(map.cRow(z, r) + cc)     = v0;
                *(__half2*)(map.cRow(z, r + 8) + cc) = v1;
            } else {
                *(float2*)(map.cRowF(z, r) + cc)     = make_float2(a[0], a[1]);
                *(float2*)(map.cRowF(z, r + 8) + cc) = make_float2(a[2], a[3]);
            }
        }
}

// =====================================================================
// Gram: C[i,j] = sum_n q[i,n]*k[j,n].  q split h/l, k hi only.
// BM=BN=96 BK=32, split-K=8, 2-stage cp.async.
// =====================================================================
__global__ __launch_bounds__(256, 2) void gram_mma(
    const __half* __restrict__ dwh, const __half* __restrict__ dwl,
    float* __restrict__ gramp)
{
    __shared__ alignas(16) __half Ash[2][96][40];
    __shared__ alignas(16) __half Asl[2][96][40];
    __shared__ alignas(16) __half Bsh[2][96][40];
    constexpr unsigned STG = 96 * 40 * 2;
    constexpr int KS_LEN = 8192 / KSPLIT_;
    constexpr int NSTG = KS_LEN / 32;

    const int z = blockIdx.z;
    const int ks = z & (KSPLIT_ - 1), bh_ = z / KSPLIT_;
    const int h = bh_ & 7, b = bh_ >> 3;
    const int bi = blockIdx.y * 96, bj = blockIdx.x * 96;
    const int tid = threadIdx.x, lane = tid & 31, w = tid >> 5;
    const int m0 = (w >> 2) * 48, n0 = (w & 3) * 24;
    const int kbase = ks * KS_LEN;

    const __half* src[5]; unsigned dst[5]; bool val[5];
#pragma unroll
    for (int it = 0; it < 5; ++it) {
        int idx = tid + it * 256;
        val[it] = idx < 1152;
        int which = idx / 384; if (which > 2) which = 2;
        int w2 = idx % 384;
        int row = w2 >> 2, c4 = w2 & 3;
        size_t off;
        const __half* basep;
        if (which == 0) {
            int qi = bi + row;
            off = ((size_t)(b * C3_ + h * 24 + (qi >> 3)) << 16) + ((size_t)(qi & 7) << 13);
            basep = dwh;
        } else if (which == 1) {
            int qi = bi + row;
            off = ((size_t)(b * C_ + h * 24 + (qi >> 3)) << 16) + ((size_t)(qi & 7) << 13);
            basep = dwl;
        } else {
            int kj = bj + row;
            off = ((size_t)(b * C3_ + C_ + h * 24 + (kj >> 3)) << 16) + ((size_t)(kj & 7) << 13);
            basep = dwh;
        }
        src[it] = basep + off + kbase + c4 * 8;
        __half* d;
        if      (which == 0) d = &Ash[0][row][c4 * 8];
        else if (which == 1) d = &Asl[0][row][c4 * 8];
        else                 d = &Bsh[0][row][c4 * 8];
        dst[it] = (unsigned)__cvta_generic_to_shared(d);
    }

    float acc[3][3][4];
#pragma unroll
    for (int i = 0; i < 3; ++i)
#pragma unroll
        for (int j = 0; j < 3; ++j)
#pragma unroll
            for (int q = 0; q < 4; ++q) acc[i][j][q] = 0.f;

    {
#pragma unroll
        for (int it = 0; it < 5; ++it) if (val[it]) cpa16(dst[it], src[it]);
        CP_COMMIT();
    }
    int buf = 0;
#pragma unroll 1
    for (int s = 0; s < NSTG; ++s) {
        CP_WAIT0();
        __syncthreads();
        if (s + 1 < NSTG) {
            const unsigned o = (buf ^ 1) * STG;
            const int ka = (s + 1) * 32;
#pragma unroll
            for (int it = 0; it < 5; ++it) if (val[it]) cpa16(dst[it] + o, src[it] + ka);
            CP_COMMIT();
        }
#pragma unroll
        for (int kk = 0; kk < 32; kk += 16) {
            unsigned ah[3][4], al[3][4], bh2[3][2];
            const int l15 = lane & 15;
#pragma unroll
            for (int mi = 0; mi < 3; ++mi) {
                ldsm4(ah[mi], &Ash[buf][m0 + mi * 16 + l15][kk + (lane >> 4) * 8]);
                ldsm4(al[mi], &Asl[buf][m0 + mi * 16 + l15][kk + (lane >> 4) * 8]);
            }
#pragma unroll
            for (int ni = 0; ni < 3; ++ni)
                ldsm2(bh2[ni], &Bsh[buf][n0 + ni * 8 + (l15 & 7)][kk + ((l15 >> 3) << 3)]);
#pragma unroll
            for (int mi = 0; mi < 3; ++mi)
#pragma unroll
                for (int ni = 0; ni < 3; ++ni) {
                    mma16816(acc[mi][ni], ah[mi], bh2[ni]);
                    mma16816(acc[mi][ni], al[mi], bh2[ni]);
                }
        }
        buf ^= 1;
    }

    float* gp = gramp + ((size_t)ks * (B_ * HEADS_) + bh_) * (C_ * C_);
#pragma unroll
    for (int mi = 0; mi < 3; ++mi)
#pragma unroll
        for (int ni = 0; ni < 3; ++ni) {
            const int r = bi + m0 + mi * 16 + (lane >> 2);
            const int cc = bj + n0 + ni * 8 + (lane & 3) * 2;
            const float* a = acc[mi][ni];
            *(float2*)(gp + (size_t)r * C_ + cc)       = make_float2(a[0], a[1]);
            *(float2*)(gp + (size_t)(r + 8) * C_ + cc) = make_float2(a[2], a[3]);
        }
}

// ---------------- depthwise 3x3 (fp16 hi in) + norm partials -----------------
__global__ __launch_bounds__(256) void dw_kernel(
    const __half* __restrict__ inh, const float* __restrict__ dww,
    __half* __restrict__ outh, __half* __restrict__ outl,
    float* __restrict__ partq, float* __restrict__ partk)
{
    const int chg = blockIdx.z;            // b*576 + c
    const int c = chg % C3_;
    const int b = chg / C3_;
    const size_t base = (size_t)chg << 16;

    float w[9];
#pragma unroll
    for (int i = 0; i < 9; ++i) w[i] = __ldg(&dww[c * 9 + i]);

    __shared__ float s[34][34];
    const int ox = blockIdx.x * 32 - 1, oy = blockIdx.y * 32 - 1;
    for (int t = threadIdx.x; t < 34 * 34; t += 256) {
        int lx = t % 34, ly = t / 34;
        int gx = ox + lx, gy = oy + ly;
        float v = 0.f;
        if ((unsigned)gx < W_ && (unsigned)gy < H_) v = __half2float(inh[base + gy * W_ + gx]);
        s[ly][lx] = v;
    }
    __syncthreads();

    const int tx = threadIdx.x & 31, ty0 = threadIdx.x >> 5;
    float ss = 0.f;
#pragma unroll
    for (int r = 0; r < 4; ++r) {
        int ly = ty0 + 8 * r;
        float acc = s[ly + 0][tx + 0] * w[0] + s[ly + 0][tx + 1] * w[1] + s[ly + 0][tx + 2] * w[2]
                  + s[ly + 1][tx + 0] * w[3] + s[ly + 1][tx + 1] * w[4] + s[ly + 1][tx + 2] * w[5]
                  + s[ly + 2][tx + 0] * w[6] + s[ly + 2][tx + 1] * w[7] + s[ly + 2][tx + 2] * w[8];
        ss += acc * acc;
        size_t sp = (size_t)(blockIdx.y * 32 + ly) * W_ + blockIdx.x * 32 + tx;
        __half hh = __float2half(acc);
        outh[base + sp] = hh;
        if (c < C_)
            outl[(((size_t)(b * C_ + c)) << 16) + sp] = __float2half(acc - __half2float(hh));
    }

    if (c < 2 * C_) {
        __shared__ float red[8];
#pragma unroll
        for (int o = 16; o > 0; o >>= 1) ss += __shfl_xor_sync(0xffffffffu, ss, o);
        if ((threadIdx.x & 31) == 0) red[threadIdx.x >> 5] = ss;
        __syncthreads();
        if (threadIdx.x == 0) {
            float tot = 0.f;
#pragma unroll
            for (int i = 0; i < 8; ++i) tot += red[i];
            if (c < C_)
                partq[((b * C_ + c) * 8 + blockIdx.y) * 8 + blockIdx.x] = tot;
            else
                partk[((b * C_ + (c - C_)) * 8 + blockIdx.y) * 8 + blockIdx.x] = tot;
        }
    }
}

__global__ void norms_finish(
    const float* __restrict__ partq, const float* __restrict__ partk,
    float* __restrict__ invq, float* __restrict__ invk)
{
    int idx = blockIdx.x * blockDim.x + threadIdx.x;
    if (idx < B_ * C_ * 8) {
        float sq = 0.f, sk = 0.f;
#pragma unroll
        for (int i = 0; i < 8; ++i) { sq += partq[idx * 8 + i]; sk += partk[idx * 8 + i]; }
        invq[idx] = 1.f / fmaxf(sqrtf(sq), 1e-12f);
        invk[idx] = 1.f / fmaxf(sqrtf(sk), 1e-12f);
    }
}

// ---------------- split-K reduce + scale + softmax -> fp16 ---------------
__global__ void softmax_kernel(
    const float* __restrict__ gramp, const float* __restrict__ invq,
    const float* __restrict__ invk, const float* __restrict__ temp,
    __half* __restrict__ attnh)
{
    const int i = blockIdx.x % C_;
    const int bh = blockIdx.x / C_;
    const int head = bh & 7, b = bh >> 3;
    const int j = threadIdx.x;

    const long long base = (long long)bh * (C_ * C_) + i * C_ + j;
    float s = 0.f;
#pragma unroll
    for (int ks = 0; ks < KSPLIT_; ++ks)
        s += gramp[(long long)ks * (B_ * HEADS_ * C_ * C_) + base];

    s *= invq[(b * C_ + head * 24 + (i >> 3)) * 8 + (i & 7)]
       * invk[(b * C_ + head * 24 + (j >> 3)) * 8 + (j & 7)]
       * temp[head];

    __shared__ float red[8];
    float m = s;
#pragma unroll
    for (int o = 16; o > 0; o >>= 1) m = fmaxf(m, __shfl_xor_sync(0xffffffffu, m, o));
    if ((threadIdx.x & 31) == 0) red[threadIdx.x >> 5] = m;
    __syncthreads();
    m = fmaxf(fmaxf(fmaxf(red[0], red[1]), fmaxf(red[2], red[3])), fmaxf(red[4], red[5]));

    float p = expf(s - m);
    float sum = p;
#pragma unroll
    for (int o = 16; o > 0; o >>= 1) sum += __shfl_xor_sync(0xffffffffu, sum, o);
    __syncthreads();
    if ((threadIdx.x & 31) == 0) red[threadIdx.x >> 5] = sum;
    __syncthreads();
    sum = red[0] + red[1] + red[2] + red[3] + red[4] + red[5];

    attnh[base] = __float2half(p / sum);
}

// ---------------- launch -------------------------------------------------------
extern "C" void kernel_launch(void* const* d_in, const int* in_sizes, int n_in,
                              void* d_out, int out_size)
{
    const float* x      = (const float*)d_in[0];
    const float* qkv_w  = (const float*)d_in[1];
    const float* dw_w   = (const float*)d_in[2];
    const float* proj_w = (const float*)d_in[3];
    const float* temp   = (const float*)d_in[4];
    float* out = (float*)d_out;

    __half *xh, *wqh, *wql, *wph, *wpl, *qkvh, *dwh, *dwl, *av, *attnh;
    float *gramp, *partq, *partk, *invq, *invk;
    cudaGetSymbolAddress((void**)&xh,   g_xh);
    cudaGetSymbolAddress((void**)&wqh,  g_wqh);
    cudaGetSymbolAddress((void**)&wql,  g_wql);
    cudaGetSymbolAddress((void**)&wph,  g_wph);
    cudaGetSymbolAddress((void**)&wpl,  g_wpl);
    cudaGetSymbolAddress((void**)&qkvh, g_qkvh);
    cudaGetSymbolAddress((void**)&dwh,  g_dwh);
    cudaGetSymbolAddress((void**)&dwl,  g_dwl);
    cudaGetSymbolAddress((void**)&av,   g_av);
    cudaGetSymbolAddress((void**)&attnh, g_attnh);
    cudaGetSymbolAddress((void**)&gramp, g_gramp);
    cudaGetSymbolAddress((void**)&partq, g_partq);
    cudaGetSymbolAddress((void**)&partk, g_partk);
    cudaGetSymbolAddress((void**)&invq,  g_invq);
    cudaGetSymbolAddress((void**)&invk,  g_invk);

    // 0) splits
    split_h_kernel<<<(B_ * C_ * HW_ / 4 + 255) / 256, 256>>>(x, xh, B_ * C_ * HW_);
    split_hl_kernel<<<(C3_ * C_ / 4 + 255) / 256, 256>>>(qkv_w, wqh, wql, C3_ * C_);
    split_hl_kernel<<<(C_ * C_ / 4 + 255) / 256, 256>>>(proj_w, wph, wpl, C_ * C_);

    // 1) qkv = qkv_w @ x  (fp16 hi out)
    {
        QkvMap m{wqh, wql, xh, qkvh};
        gemm_mma<QkvMap><<<dim3(HW_ / 128, C3_ / 96, B_), 256>>>(m, C_);
    }
    // 2) depthwise 3x3 + norm partials
    dw_kernel<<<dim3(W_ / 32, H_ / 32, B_ * C3_), 256>>>(qkvh, dw_w, dwh, dwl, partq, partk);
    // 3) norms
    norms_finish<<<(B_ * C_ * 8 + 255) / 256, 256>>>(partq, partk, invq, invk);
    // 4) gram partials
    gram_mma<<<dim3(2, 2, B_ * HEADS_ * KSPLIT_), 256>>>(dwh, dwl, gramp);
    // 5) softmax
    softmax_kernel<<<B_ * HEADS_ * C_, C_>>>(gramp, invq, invk, temp, attnh);
    // 6) av = attn @ v  (single product)
    {
        AvMap m{attnh, nullptr, dwh, av};
        gemm_mma<AvMap><<<dim3(HW_ / HEADS_ / 128, C_ / 96, B_ * HEADS_), 256>>>(m, C_);
    }
    // 7) out = proj_w @ av
    {
        ProjMap m{wph, wpl, av, out};
        gemm_mma<ProjMap><<<dim3(HW_ / 128, C_ / 96, B_), 256>>>(m, C_);
    }
}

// round 10
// speedup vs baseline: 1.4870x; 1.0830x over previous
#include <cuda_runtime.h>
#include <cuda_fp16.h>
#include <cstdint>

#define B_      2
#define C_      192
#define C3_     576
#define H_      256
#define W_      256
#define HW_     65536
#define HEADS_  8
#define KSPLIT_ 8

// ---------------- scratch (device globals: allocation-free rule) ----------------
__device__ __half g_xh  [(size_t)B_ * C_ * HW_];                 // x -> fp16
__device__ __half g_wqh [C3_ * C_];
__device__ __half g_wph [C_ * C_];
__device__ __half g_wpl [C_ * C_];
__device__ __half g_qkvh[(size_t)B_ * C3_ * HW_];                // qkv (fp16 hi only)
__device__ __half g_dwh [(size_t)B_ * C3_ * HW_];                // dw out hi (q,k,v)
__device__ __half g_dwl [(size_t)B_ * C_ * HW_];                 // dw out lo (q only)
__device__ __half g_av  [(size_t)B_ * C_ * HW_];                 // attn@v (fp16)
__device__ float  g_gramp[(size_t)KSPLIT_ * B_ * HEADS_ * C_ * C_];
__device__ __half g_attnh[(size_t)B_ * HEADS_ * C_ * C_];
__device__ float g_partq[B_ * C_ * 64];
__device__ float g_partk[B_ * C_ * 64];
__device__ float g_invq [B_ * C_ * 8];
__device__ float g_invk [B_ * C_ * 8];

// ---------------- mma / ldmatrix / cp.async helpers ----------------
__device__ __forceinline__ void ldsm4(unsigned* r, const void* p) {
    unsigned a = (unsigned)__cvta_generic_to_shared(p);
    asm volatile("ldmatrix.sync.aligned.m8n8.x4.shared.b16 {%0,%1,%2,%3}, [%4];"
                 : "=r"(r[0]), "=r"(r[1]), "=r"(r[2]), "=r"(r[3]) : "r"(a));
}
__device__ __forceinline__ void ldsm2t(unsigned* r, const void* p) {
    unsigned a = (unsigned)__cvta_generic_to_shared(p);
    asm volatile("ldmatrix.sync.aligned.m8n8.x2.trans.shared.b16 {%0,%1}, [%2];"
                 : "=r"(r[0]), "=r"(r[1]) : "r"(a));
}
__device__ __forceinline__ void ldsm2(unsigned* r, const void* p) {
    unsigned a = (unsigned)__cvta_generic_to_shared(p);
    asm volatile("ldmatrix.sync.aligned.m8n8.x2.shared.b16 {%0,%1}, [%2];"
                 : "=r"(r[0]), "=r"(r[1]) : "r"(a));
}
__device__ __forceinline__ void mma16816(float* c, const unsigned* a, const unsigned* b) {
    asm volatile("mma.sync.aligned.m16n8k16.row.col.f32.f16.f16.f32 "
                 "{%0,%1,%2,%3},{%4,%5,%6,%7},{%8,%9},{%0,%1,%2,%3};"
                 : "+f"(c[0]), "+f"(c[1]), "+f"(c[2]), "+f"(c[3])
                 : "r"(a[0]), "r"(a[1]), "r"(a[2]), "r"(a[3]), "r"(b[0]), "r"(b[1]));
}
__device__ __forceinline__ void cpa16(unsigned dst, const void* src) {
    asm volatile("cp.async.cg.shared.global [%0], [%1], 16;\n" :: "r"(dst), "l"(src));
}
#define CP_COMMIT() asm volatile("cp.async.commit_group;\n")
#define CP_WAIT0()  asm volatile("cp.async.wait_group 0;\n")

__device__ __forceinline__ void st_pair_h(__half* ph, __half* pl, float x, float y) {
    __half hx = __float2half(x), hy = __float2half(y);
    __half2 hp; hp.x = hx; hp.y = hy; *(__half2*)ph = hp;
    __half2 lp;
    lp.x = __float2half(x - __half2float(hx));
    lp.y = __float2half(y - __half2float(hy));
    *(__half2*)pl = lp;
}

// ---------------- fp32 -> fp16 split kernels ----------------
__global__ __launch_bounds__(256) void split_hl_kernel(
    const float* __restrict__ in, __half* __restrict__ oh,
    __half* __restrict__ ol, int n)
{
    int i = (blockIdx.x * 256 + threadIdx.x) * 4;
    if (i < n) {
        float4 v = *(const float4*)(in + i);
        st_pair_h(oh + i,     ol + i,     v.x, v.y);
        st_pair_h(oh + i + 2, ol + i + 2, v.z, v.w);
    }
}
__global__ __launch_bounds__(256) void split_h_kernel(
    const float* __restrict__ in, __half* __restrict__ oh, int n)
{
    int i = (blockIdx.x * 256 + threadIdx.x) * 4;
    if (i < n) {
        float4 v = *(const float4*)(in + i);
        __half2 a; a.x = __float2half(v.x); a.y = __float2half(v.y);
        __half2 b; b.x = __float2half(v.z); b.y = __float2half(v.w);
        ((__half2*)(oh + i))[0] = a;
        ((__half2*)(oh + i))[1] = b;
    }
}

// ---------------- maps ----------------
struct QkvMap {
    const __half *Ah, *Al, *B; __half *Cc;
    static constexpr int CMODE = 1;                    // fp16 single out
    static constexpr bool A_SPLIT = false;             // weight hi only
    static constexpr size_t BSTRIDE32 = (size_t)32 * HW_;
    __device__ const __half* aRowH(int z, int m) const { return Ah + (size_t)m * C_; }
    __device__ const __half* aRowL(int z, int m) const { return Ah; }
    __device__ const __half* bRow(int z, int k) const { return B + ((size_t)z * C_ + k) * HW_; }
    __device__ __half* cRow(int z, int m) const { return Cc + ((size_t)z * C3_ + m) * HW_; }
    __device__ float*  cRowF(int z, int m) const { return nullptr; }
};
struct AvMap {
    const __half *Ah, *Al, *B; __half *Cc;
    static constexpr int CMODE = 1;                    // fp16 single out
    static constexpr bool A_SPLIT = false;             // attn hi only
    static constexpr size_t BSTRIDE32 = (size_t)4 << 16;
    __device__ const __half* aRowH(int z, int m) const { return Ah + (size_t)z * (C_ * C_) + (size_t)m * C_; }
    __device__ const __half* aRowL(int z, int m) const { return Ah; }
    __device__ const __half* bRow(int z, int k) const {
        int b = z >> 3, h = z & 7;
        return B + ((size_t)(b * C3_ + 2 * C_ + h * 24 + (k >> 3)) << 16) + ((k & 7) << 13);
    }
    __device__ __half* cRow(int z, int m) const {
        int b = z >> 3, h = z & 7;
        return Cc + ((size_t)(b * C_ + h * 24 + (m >> 3)) << 16) + ((m & 7) << 13);
    }
    __device__ float*  cRowF(int z, int m) const { return nullptr; }
};
struct ProjMap {
    const __half *Ah, *Al, *B; float* C;
    static constexpr int CMODE = 2;                    // fp32 out
    static constexpr bool A_SPLIT = true;
    static constexpr size_t BSTRIDE32 = (size_t)32 * HW_;
    __device__ const __half* aRowH(int z, int m) const { return Ah + (size_t)m * C_; }
    __device__ const __half* aRowL(int z, int m) const { return Al + (size_t)m * C_; }
    __device__ const __half* bRow(int z, int k) const { return B + ((size_t)z * C_ + k) * HW_; }
    __device__ float* cRowF(int z, int m) const { return C + ((size_t)z * C_ + m) * HW_; }
    __device__ __half* cRow(int z, int m) const { return nullptr; }
};

// =====================================================================
// fp16 MMA GEMM: C = (Ah [+Al]) @ B.  BM=96 BN=128 BK=32,
// 2-stage cp.async, 256 threads, warp tile 48x32.
// =====================================================================
template <class Map>
__global__ __launch_bounds__(256, 2) void gemm_mma(const Map map, const int K)
{
    __shared__ alignas(16) __half Ash[2][96][40];
    __shared__ alignas(16) __half Asl[2][96][40];
    __shared__ alignas(16) __half Bs [2][32][136];
    constexpr unsigned ASTG = 96 * 40 * 2;
    constexpr unsigned BSTG = 32 * 136 * 2;
    constexpr int NAIT = Map::A_SPLIT ? 3 : 2;
    constexpr int NACHUNK = Map::A_SPLIT ? 768 : 384;

    const int z = blockIdx.z, bm = blockIdx.y * 96, bn = blockIdx.x * 128;
    const int tid = threadIdx.x, lane = tid & 31, w = tid >> 5;
    const int m0 = (w >> 2) * 48, n0 = (w & 3) * 32;

    // A loaders
    const __half* asrc[NAIT]; unsigned adst[NAIT]; bool aval[NAIT];
#pragma unroll
    for (int it = 0; it < NAIT; ++it) {
        int idx = tid + it * 256;
        aval[it] = idx < NACHUNK;
        if (idx >= NACHUNK) idx = NACHUNK - 1;
        int which = idx / 384, w2 = idx % 384;
        int row = w2 >> 2, c4 = w2 & 3;
        const __half* base = which ? map.aRowL(z, bm + row) : map.aRowH(z, bm + row);
        asrc[it] = base + c4 * 8;
        adst[it] = (unsigned)__cvta_generic_to_shared(which ? &Asl[0][row][c4 * 8] : &Ash[0][row][c4 * 8]);
    }
    // B loaders: 512 chunks, 2 iters
    const __half* bsrc[2]; unsigned bdst[2];
#pragma unroll
    for (int it = 0; it < 2; ++it) {
        int idx = tid + it * 256;
        int row = idx >> 4, c4 = idx & 15;
        bsrc[it] = map.bRow(z, row) + bn + c4 * 8;
        bdst[it] = (unsigned)__cvta_generic_to_shared(&Bs[0][row][c4 * 8]);
    }

    float acc[3][4][4];
#pragma unroll
    for (int i = 0; i < 3; ++i)
#pragma unroll
        for (int j = 0; j < 4; ++j)
#pragma unroll
            for (int q = 0; q < 4; ++q) acc[i][j][q] = 0.f;

    const int nStage = K >> 5;
    {
#pragma unroll
        for (int it = 0; it < NAIT; ++it) if (aval[it]) cpa16(adst[it], asrc[it]);
#pragma unroll
        for (int it = 0; it < 2; ++it) cpa16(bdst[it], bsrc[it]);
        CP_COMMIT();
    }
    int buf = 0;
#pragma unroll 1
    for (int s = 0; s < nStage; ++s) {
        CP_WAIT0();
        __syncthreads();
        if (s + 1 < nStage) {
            const unsigned ao = (buf ^ 1) * ASTG, bo = (buf ^ 1) * BSTG;
            const int ka = (s + 1) * 32;
            const size_t kb = (size_t)(s + 1) * Map::BSTRIDE32;
#pragma unroll
            for (int it = 0; it < NAIT; ++it) if (aval[it]) cpa16(adst[it] + ao, asrc[it] + ka);
#pragma unroll
            for (int it = 0; it < 2; ++it) cpa16(bdst[it] + bo, bsrc[it] + kb);
            CP_COMMIT();
        }
#pragma unroll
        for (int kk = 0; kk < 32; kk += 16) {
            unsigned ah[3][4], al[3][4], bh[4][2];
            const int l15 = lane & 15;
#pragma unroll
            for (int mi = 0; mi < 3; ++mi) {
                ldsm4(ah[mi], &Ash[buf][m0 + mi * 16 + l15][kk + (lane >> 4) * 8]);
                if constexpr (Map::A_SPLIT)
                    ldsm4(al[mi], &Asl[buf][m0 + mi * 16 + l15][kk + (lane >> 4) * 8]);
            }
#pragma unroll
            for (int ni = 0; ni < 4; ++ni)
                ldsm2t(bh[ni], &Bs[buf][kk + l15][n0 + ni * 8]);
#pragma unroll
            for (int mi = 0; mi < 3; ++mi)
#pragma unroll
                for (int ni = 0; ni < 4; ++ni) {
                    mma16816(acc[mi][ni], ah[mi], bh[ni]);
                    if constexpr (Map::A_SPLIT)
                        mma16816(acc[mi][ni], al[mi], bh[ni]);
                }
        }
        buf ^= 1;
    }

#pragma unroll
    for (int mi = 0; mi < 3; ++mi)
#pragma unroll
        for (int ni = 0; ni < 4; ++ni) {
            const int r = bm + m0 + mi * 16 + (lane >> 2);
            const int cc = bn + n0 + ni * 8 + (lane & 3) * 2;
            const float* a = acc[mi][ni];
            if constexpr (Map::CMODE == 1) {
                __half2 v0; v0.x = __float2half(a[0]); v0.y = __float2half(a[1]);
                __half2 v1; v1.x = __float2half(a[2]); v1.y = __float2half(a[3]);
                *(__half2*)(map.cRow(z, r) + cc)     = v0;
                *(__half2*)(map.cRow(z, r + 8) + cc) = v1;
            } else {
                *(float2*)(map.cRowF(z, r) + cc)     = make_float2(a[0], a[1]);
                *(float2*)(map.cRowF(z, r + 8) + cc) = make_float2(a[2], a[3]);
            }
        }
}

// =====================================================================
// Gram: C[i,j] = sum_n q[i,n]*k[j,n].  q split h/l, k hi only.
// BM=BN=96 BK=32, split-K=8, 2-stage cp.async.
// =====================================================================
__global__ __launch_bounds__(256, 2) void gram_mma(
    const __half* __restrict__ dwh, const __half* __restrict__ dwl,
    float* __restrict__ gramp)
{
    __shared__ alignas(16) __half Ash[2][96][40];
    __shared__ alignas(16) __half Asl[2][96][40];
    __shared__ alignas(16) __half Bsh[2][96][40];
    constexpr unsigned STG = 96 * 40 * 2;
    constexpr int KS_LEN = 8192 / KSPLIT_;
    constexpr int NSTG = KS_LEN / 32;

    const int z = blockIdx.z;
    const int ks = z & (KSPLIT_ - 1), bh_ = z / KSPLIT_;
    const int h = bh_ & 7, b = bh_ >> 3;
    const int bi = blockIdx.y * 96, bj = blockIdx.x * 96;
    const int tid = threadIdx.x, lane = tid & 31, w = tid >> 5;
    const int m0 = (w >> 2) * 48, n0 = (w & 3) * 24;
    const int kbase = ks * KS_LEN;

    const __half* src[5]; unsigned dst[5]; bool val[5];
#pragma unroll
    for (int it = 0; it < 5; ++it) {
        int idx = tid + it * 256;
        val[it] = idx < 1152;
        int which = idx / 384; if (which > 2) which = 2;
        int w2 = idx % 384;
        int row = w2 >> 2, c4 = w2 & 3;
        size_t off;
        const __half* basep;
        if (which == 0) {
            int qi = bi + row;
            off = ((size_t)(b * C3_ + h * 24 + (qi >> 3)) << 16) + ((size_t)(qi & 7) << 13);
            basep = dwh;
        } else if (which == 1) {
            int qi = bi + row;
            off = ((size_t)(b * C_ + h * 24 + (qi >> 3)) << 16) + ((size_t)(qi & 7) << 13);
            basep = dwl;
        } else {
            int kj = bj + row;
            off = ((size_t)(b * C3_ + C_ + h * 24 + (kj >> 3)) << 16) + ((size_t)(kj & 7) << 13);
            basep = dwh;
        }
        src[it] = basep + off + kbase + c4 * 8;
        __half* d;
        if      (which == 0) d = &Ash[0][row][c4 * 8];
        else if (which == 1) d = &Asl[0][row][c4 * 8];
        else                 d = &Bsh[0][row][c4 * 8];
        dst[it] = (unsigned)__cvta_generic_to_shared(d);
    }

    float acc[3][3][4];
#pragma unroll
    for (int i = 0; i < 3; ++i)
#pragma unroll
        for (int j = 0; j < 3; ++j)
#pragma unroll
            for (int q = 0; q < 4; ++q) acc[i][j][q] = 0.f;

    {
#pragma unroll
        for (int it = 0; it < 5; ++it) if (val[it]) cpa16(dst[it], src[it]);
        CP_COMMIT();
    }
    int buf = 0;
#pragma unroll 1
    for (int s = 0; s < NSTG; ++s) {
        CP_WAIT0();
        __syncthreads();
        if (s + 1 < NSTG) {
            const unsigned o = (buf ^ 1) * STG;
            const int ka = (s + 1) * 32;
#pragma unroll
            for (int it = 0; it < 5; ++it) if (val[it]) cpa16(dst[it] + o, src[it] + ka);
            CP_COMMIT();
        }
#pragma unroll
        for (int kk = 0; kk < 32; kk += 16) {
            unsigned ah[3][4], al[3][4], bh2[3][2];
            const int l15 = lane & 15;
#pragma unroll
            for (int mi = 0; mi < 3; ++mi) {
                ldsm4(ah[mi], &Ash[buf][m0 + mi * 16 + l15][kk + (lane >> 4) * 8]);
                ldsm4(al[mi], &Asl[buf][m0 + mi * 16 + l15][kk + (lane >> 4) * 8]);
            }
#pragma unroll
            for (int ni = 0; ni < 3; ++ni)
                ldsm2(bh2[ni], &Bsh[buf][n0 + ni * 8 + (l15 & 7)][kk + ((l15 >> 3) << 3)]);
#pragma unroll
            for (int mi = 0; mi < 3; ++mi)
#pragma unroll
                for (int ni = 0; ni < 3; ++ni) {
                    mma16816(acc[mi][ni], ah[mi], bh2[ni]);
                    mma16816(acc[mi][ni], al[mi], bh2[ni]);
                }
        }
        buf ^= 1;
    }

    float* gp = gramp + ((size_t)ks * (B_ * HEADS_) + bh_) * (C_ * C_);
#pragma unroll
    for (int mi = 0; mi < 3; ++mi)
#pragma unroll
        for (int ni = 0; ni < 3; ++ni) {
            const int r = bi + m0 + mi * 16 + (lane >> 2);
            const int cc = bj + n0 + ni * 8 + (lane & 3) * 2;
            const float* a = acc[mi][ni];
            *(float2*)(gp + (size_t)r * C_ + cc)       = make_float2(a[0], a[1]);
            *(float2*)(gp + (size_t)(r + 8) * C_ + cc) = make_float2(a[2], a[3]);
        }
}

// ---------------- depthwise 3x3 (fp16 hi in) + norm partials -----------------
__global__ __launch_bounds__(256) void dw_kernel(
    const __half* __restrict__ inh, const float* __restrict__ dww,
    __half* __restrict__ outh, __half* __restrict__ outl,
    float* __restrict__ partq, float* __restrict__ partk)
{
    const int chg = blockIdx.z;            // b*576 + c
    const int c = chg % C3_;
    const int b = chg / C3_;
    const size_t base = (size_t)chg << 16;

    float w[9];
#pragma unroll
    for (int i = 0; i < 9; ++i) w[i] = __ldg(&dww[c * 9 + i]);

    __shared__ float s[34][34];
    const int ox = blockIdx.x * 32 - 1, oy = blockIdx.y * 32 - 1;
    for (int t = threadIdx.x; t < 34 * 34; t += 256) {
        int lx = t % 34, ly = t / 34;
        int gx = ox + lx, gy = oy + ly;
        float v = 0.f;
        if ((unsigned)gx < W_ && (unsigned)gy < H_) v = __half2float(inh[base + gy * W_ + gx]);
        s[ly][lx] = v;
    }
    __syncthreads();

    const int tx = threadIdx.x & 31, ty0 = threadIdx.x >> 5;
    float ss = 0.f;
#pragma unroll
    for (int r = 0; r < 4; ++r) {
        int ly = ty0 + 8 * r;
        float acc = s[ly + 0][tx + 0] * w[0] + s[ly + 0][tx + 1] * w[1] + s[ly + 0][tx + 2] * w[2]
                  + s[ly + 1][tx + 0] * w[3] + s[ly + 1][tx + 1] * w[4] + s[ly + 1][tx + 2] * w[5]
                  + s[ly + 2][tx + 0] * w[6] + s[ly + 2][tx + 1] * w[7] + s[ly + 2][tx + 2] * w[8];
        ss += acc * acc;
        size_t sp = (size_t)(blockIdx.y * 32 + ly) * W_ + blockIdx.x * 32 + tx;
        __half hh = __float2half(acc);
        outh[base + sp] = hh;
        if (c < C_)
            outl[(((size_t)(b * C_ + c)) << 16) + sp] = __float2half(acc - __half2float(hh));
    }

    if (c < 2 * C_) {
        __shared__ float red[8];
#pragma unroll
        for (int o = 16; o > 0; o >>= 1) ss += __shfl_xor_sync(0xffffffffu, ss, o);
        if ((threadIdx.x & 31) == 0) red[threadIdx.x >> 5] = ss;
        __syncthreads();
        if (threadIdx.x == 0) {
            float tot = 0.f;
#pragma unroll
            for (int i = 0; i < 8; ++i) tot += red[i];
            if (c < C_)
                partq[((b * C_ + c) * 8 + blockIdx.y) * 8 + blockIdx.x] = tot;
            else
                partk[((b * C_ + (c - C_)) * 8 + blockIdx.y) * 8 + blockIdx.x] = tot;
        }
    }
}

__global__ void norms_finish(
    const float* __restrict__ partq, const float* __restrict__ partk,
    float* __restrict__ invq, float* __restrict__ invk)
{
    int idx = blockIdx.x * blockDim.x + threadIdx.x;
    if (idx < B_ * C_ * 8) {
        float sq = 0.f, sk = 0.f;
#pragma unroll
        for (int i = 0; i < 8; ++i) { sq += partq[idx * 8 + i]; sk += partk[idx * 8 + i]; }
        invq[idx] = 1.f / fmaxf(sqrtf(sq), 1e-12f);
        invk[idx] = 1.f / fmaxf(sqrtf(sk), 1e-12f);
    }
}

// ---------------- split-K reduce + scale + softmax -> fp16 ---------------
__global__ void softmax_kernel(
    const float* __restrict__ gramp, const float* __restrict__ invq,
    const float* __restrict__ invk, const float* __restrict__ temp,
    __half* __restrict__ attnh)
{
    const int i = blockIdx.x % C_;
    const int bh = blockIdx.x / C_;
    const int head = bh & 7, b = bh >> 3;
    const int j = threadIdx.x;

    const long long base = (long long)bh * (C_ * C_) + i * C_ + j;
    float s = 0.f;
#pragma unroll
    for (int ks = 0; ks < KSPLIT_; ++ks)
        s += gramp[(long long)ks * (B_ * HEADS_ * C_ * C_) + base];

    s *= invq[(b * C_ + head * 24 + (i >> 3)) * 8 + (i & 7)]
       * invk[(b * C_ + head * 24 + (j >> 3)) * 8 + (j & 7)]
       * temp[head];

    __shared__ float red[8];
    float m = s;
#pragma unroll
    for (int o = 16; o > 0; o >>= 1) m = fmaxf(m, __shfl_xor_sync(0xffffffffu, m, o));
    if ((threadIdx.x & 31) == 0) red[threadIdx.x >> 5] = m;
    __syncthreads();
    m = fmaxf(fmaxf(fmaxf(red[0], red[1]), fmaxf(red[2], red[3])), fmaxf(red[4], red[5]));

    float p = expf(s - m);
    float sum = p;
#pragma unroll
    for (int o = 16; o > 0; o >>= 1) sum += __shfl_xor_sync(0xffffffffu, sum, o);
    __syncthreads();
    if ((threadIdx.x & 31) == 0) red[threadIdx.x >> 5] = sum;
    __syncthreads();
    sum = red[0] + red[1] + red[2] + red[3] + red[4] + red[5];

    attnh[base] = __float2half(p / sum);
}

// ---------------- launch -------------------------------------------------------
extern "C" void kernel_launch(void* const* d_in, const int* in_sizes, int n_in,
                              void* d_out, int out_size)
{
    const float* x      = (const float*)d_in[0];
    const float* qkv_w  = (const float*)d_in[1];
    const float* dw_w   = (const float*)d_in[2];
    const float* proj_w = (const float*)d_in[3];
    const float* temp   = (const float*)d_in[4];
    float* out = (float*)d_out;

    __half *xh, *wqh, *wph, *wpl, *qkvh, *dwh, *dwl, *av, *attnh;
    float *gramp, *partq, *partk, *invq, *invk;
    cudaGetSymbolAddress((void**)&xh,   g_xh);
    cudaGetSymbolAddress((void**)&wqh,  g_wqh);
    cudaGetSymbolAddress((void**)&wph,  g_wph);
    cudaGetSymbolAddress((void**)&wpl,  g_wpl);
    cudaGetSymbolAddress((void**)&qkvh, g_qkvh);
    cudaGetSymbolAddress((void**)&dwh,  g_dwh);
    cudaGetSymbolAddress((void**)&dwl,  g_dwl);
    cudaGetSymbolAddress((void**)&av,   g_av);
    cudaGetSymbolAddress((void**)&attnh, g_attnh);
    cudaGetSymbolAddress((void**)&gramp, g_gramp);
    cudaGetSymbolAddress((void**)&partq, g_partq);
    cudaGetSymbolAddress((void**)&partk, g_partk);
    cudaGetSymbolAddress((void**)&invq,  g_invq);
    cudaGetSymbolAddress((void**)&invk,  g_invk);

    // 0) splits: x hi, qkv_w hi, proj_w hi/lo
    split_h_kernel<<<(B_ * C_ * HW_ / 4 + 255) / 256, 256>>>(x, xh, B_ * C_ * HW_);
    split_h_kernel<<<(C3_ * C_ / 4 + 255) / 256, 256>>>(qkv_w, wqh, C3_ * C_);
    split_hl_kernel<<<(C_ * C_ / 4 + 255) / 256, 256>>>(proj_w, wph, wpl, C_ * C_);

    // 1) qkv = qkv_w @ x  (single product, fp16 hi out)
    {
        QkvMap m{wqh, nullptr, xh, qkvh};
        gemm_mma<QkvMap><<<dim3(HW_ / 128, C3_ / 96, B_), 256>>>(m, C_);
    }
    // 2) depthwise 3x3 + norm partials
    dw_kernel<<<dim3(W_ / 32, H_ / 32, B_ * C3_), 256>>>(qkvh, dw_w, dwh, dwl, partq, partk);
    // 3) norms
    norms_finish<<<(B_ * C_ * 8 + 255) / 256, 256>>>(partq, partk, invq, invk);
    // 4) gram partials
    gram_mma<<<dim3(2, 2, B_ * HEADS_ * KSPLIT_), 256>>>(dwh, dwl, gramp);
    // 5) softmax
    softmax_kernel<<<B_ * HEADS_ * C_, C_>>>(gramp, invq, invk, temp, attnh);
    // 6) av = attn @ v  (single product)
    {
        AvMap m{attnh, nullptr, dwh, av};
        gemm_mma<AvMap><<<dim3(HW_ / HEADS_ / 128, C_ / 96, B_ * HEADS_), 256>>>(m, C_);
    }
    // 7) out = proj_w @ av
    {
        ProjMap m{wph, wpl, av, out};
        gemm_mma<ProjMap><<<dim3(HW_ / 128, C_ / 96, B_), 256>>>(m, C_);
    }
}

// round 11
// speedup vs baseline: 1.6083x; 1.0816x over previous
#include <cuda_runtime.h>
#include <cuda_fp16.h>
#include <cstdint>

#define B_      2
#define C_      192
#define C3_     576
#define H_      256
#define W_      256
#define HW_     65536
#define HEADS_  8
#define KSPLIT_ 8

// ---------------- scratch (device globals: allocation-free rule) ----------------
__device__ __half g_xh  [(size_t)B_ * C_ * HW_];                 // x -> fp16
__device__ __half g_wqh [C3_ * C_];
__device__ __half g_wph [C_ * C_];
__device__ __half g_qkvh[(size_t)B_ * C3_ * HW_];                // qkv (fp16)
__device__ __half g_dwh [(size_t)B_ * C3_ * HW_];                // dw out (q,k,v fp16)
__device__ __half g_av  [(size_t)B_ * C_ * HW_];                 // attn@v (fp16)
__device__ float  g_gramp[(size_t)KSPLIT_ * B_ * HEADS_ * C_ * C_];
__device__ __half g_attnh[(size_t)B_ * HEADS_ * C_ * C_];
__device__ float g_partq[B_ * C_ * 64];
__device__ float g_partk[B_ * C_ * 64];
__device__ float g_invq [B_ * C_ * 8];
__device__ float g_invk [B_ * C_ * 8];

// ---------------- mma / ldmatrix / cp.async helpers ----------------
__device__ __forceinline__ void ldsm4(unsigned* r, const void* p) {
    unsigned a = (unsigned)__cvta_generic_to_shared(p);
    asm volatile("ldmatrix.sync.aligned.m8n8.x4.shared.b16 {%0,%1,%2,%3}, [%4];"
                 : "=r"(r[0]), "=r"(r[1]), "=r"(r[2]), "=r"(r[3]) : "r"(a));
}
__device__ __forceinline__ void ldsm2t(unsigned* r, const void* p) {
    unsigned a = (unsigned)__cvta_generic_to_shared(p);
    asm volatile("ldmatrix.sync.aligned.m8n8.x2.trans.shared.b16 {%0,%1}, [%2];"
                 : "=r"(r[0]), "=r"(r[1]) : "r"(a));
}
__device__ __forceinline__ void ldsm2(unsigned* r, const void* p) {
    unsigned a = (unsigned)__cvta_generic_to_shared(p);
    asm volatile("ldmatrix.sync.aligned.m8n8.x2.shared.b16 {%0,%1}, [%2];"
                 : "=r"(r[0]), "=r"(r[1]) : "r"(a));
}
__device__ __forceinline__ void mma16816(float* c, const unsigned* a, const unsigned* b) {
    asm volatile("mma.sync.aligned.m16n8k16.row.col.f32.f16.f16.f32 "
                 "{%0,%1,%2,%3},{%4,%5,%6,%7},{%8,%9},{%0,%1,%2,%3};"
                 : "+f"(c[0]), "+f"(c[1]), "+f"(c[2]), "+f"(c[3])
                 : "r"(a[0]), "r"(a[1]), "r"(a[2]), "r"(a[3]), "r"(b[0]), "r"(b[1]));
}
__device__ __forceinline__ void cpa16(unsigned dst, const void* src) {
    asm volatile("cp.async.cg.shared.global [%0], [%1], 16;\n" :: "r"(dst), "l"(src));
}
#define CP_COMMIT() asm volatile("cp.async.commit_group;\n")
#define CP_WAIT0()  asm volatile("cp.async.wait_group 0;\n")

// ---------------- fp32 -> fp16 convert ----------------
__global__ __launch_bounds__(256) void split_h_kernel(
    const float* __restrict__ in, __half* __restrict__ oh, int n)
{
    int i = (blockIdx.x * 256 + threadIdx.x) * 4;
    if (i < n) {
        float4 v = *(const float4*)(in + i);
        __half2 a; a.x = __float2half(v.x); a.y = __float2half(v.y);
        __half2 b; b.x = __float2half(v.z); b.y = __float2half(v.w);
        ((__half2*)(oh + i))[0] = a;
        ((__half2*)(oh + i))[1] = b;
    }
}

// ---------------- maps ----------------
struct QkvMap {
    const __half *Ah, *B; __half *Cc;
    static constexpr int CMODE = 1;                    // fp16 out
    static constexpr size_t BSTRIDE32 = (size_t)32 * HW_;
    __device__ const __half* aRowH(int z, int m) const { return Ah + (size_t)m * C_; }
    __device__ const __half* bRow(int z, int k) const { return B + ((size_t)z * C_ + k) * HW_; }
    __device__ __half* cRow(int z, int m) const { return Cc + ((size_t)z * C3_ + m) * HW_; }
    __device__ float*  cRowF(int z, int m) const { return nullptr; }
};
struct AvMap {
    const __half *Ah, *B; __half *Cc;
    static constexpr int CMODE = 1;
    static constexpr size_t BSTRIDE32 = (size_t)4 << 16;
    __device__ const __half* aRowH(int z, int m) const { return Ah + (size_t)z * (C_ * C_) + (size_t)m * C_; }
    __device__ const __half* bRow(int z, int k) const {
        int b = z >> 3, h = z & 7;
        return B + ((size_t)(b * C3_ + 2 * C_ + h * 24 + (k >> 3)) << 16) + ((k & 7) << 13);
    }
    __device__ __half* cRow(int z, int m) const {
        int b = z >> 3, h = z & 7;
        return Cc + ((size_t)(b * C_ + h * 24 + (m >> 3)) << 16) + ((m & 7) << 13);
    }
    __device__ float*  cRowF(int z, int m) const { return nullptr; }
};
struct ProjMap {
    const __half *Ah, *B; float* C;
    static constexpr int CMODE = 2;                    // fp32 out
    static constexpr size_t BSTRIDE32 = (size_t)32 * HW_;
    __device__ const __half* aRowH(int z, int m) const { return Ah + (size_t)m * C_; }
    __device__ const __half* bRow(int z, int k) const { return B + ((size_t)z * C_ + k) * HW_; }
    __device__ float* cRowF(int z, int m) const { return C + ((size_t)z * C_ + m) * HW_; }
    __device__ __half* cRow(int z, int m) const { return nullptr; }
};

// =====================================================================
// fp16 MMA GEMM: C = Ah @ B.  BM=96 BN=128 BK=32,
// 2-stage cp.async, 256 threads, warp tile 48x32.
// =====================================================================
template <class Map>
__global__ __launch_bounds__(256, 2) void gemm_mma(const Map map, const int K)
{
    __shared__ alignas(16) __half Ash[2][96][40];
    __shared__ alignas(16) __half Bs [2][32][136];
    constexpr unsigned ASTG = 96 * 40 * 2;
    constexpr unsigned BSTG = 32 * 136 * 2;

    const int z = blockIdx.z, bm = blockIdx.y * 96, bn = blockIdx.x * 128;
    const int tid = threadIdx.x, lane = tid & 31, w = tid >> 5;
    const int m0 = (w >> 2) * 48, n0 = (w & 3) * 32;

    // A loaders: 384 chunks, 2 iters (last partial)
    const __half* asrc[2]; unsigned adst[2]; bool aval[2];
#pragma unroll
    for (int it = 0; it < 2; ++it) {
        int idx = tid + it * 256;
        aval[it] = idx < 384;
        if (idx >= 384) idx = 383;
        int row = idx >> 2, c4 = idx & 3;
        asrc[it] = map.aRowH(z, bm + row) + c4 * 8;
        adst[it] = (unsigned)__cvta_generic_to_shared(&Ash[0][row][c4 * 8]);
    }
    // B loaders: 512 chunks, 2 iters
    const __half* bsrc[2]; unsigned bdst[2];
#pragma unroll
    for (int it = 0; it < 2; ++it) {
        int idx = tid + it * 256;
        int row = idx >> 4, c4 = idx & 15;
        bsrc[it] = map.bRow(z, row) + bn + c4 * 8;
        bdst[it] = (unsigned)__cvta_generic_to_shared(&Bs[0][row][c4 * 8]);
    }

    float acc[3][4][4];
#pragma unroll
    for (int i = 0; i < 3; ++i)
#pragma unroll
        for (int j = 0; j < 4; ++j)
#pragma unroll
            for (int q = 0; q < 4; ++q) acc[i][j][q] = 0.f;

    const int nStage = K >> 5;
    {
#pragma unroll
        for (int it = 0; it < 2; ++it) if (aval[it]) cpa16(adst[it], asrc[it]);
#pragma unroll
        for (int it = 0; it < 2; ++it) cpa16(bdst[it], bsrc[it]);
        CP_COMMIT();
    }
    int buf = 0;
#pragma unroll 1
    for (int s = 0; s < nStage; ++s) {
        CP_WAIT0();
        __syncthreads();
        if (s + 1 < nStage) {
            const unsigned ao = (buf ^ 1) * ASTG, bo = (buf ^ 1) * BSTG;
            const int ka = (s + 1) * 32;
            const size_t kb = (size_t)(s + 1) * Map::BSTRIDE32;
#pragma unroll
            for (int it = 0; it < 2; ++it) if (aval[it]) cpa16(adst[it] + ao, asrc[it] + ka);
#pragma unroll
            for (int it = 0; it < 2; ++it) cpa16(bdst[it] + bo, bsrc[it] + kb);
            CP_COMMIT();
        }
#pragma unroll
        for (int kk = 0; kk < 32; kk += 16) {
            unsigned ah[3][4], bh[4][2];
            const int l15 = lane & 15;
#pragma unroll
            for (int mi = 0; mi < 3; ++mi)
                ldsm4(ah[mi], &Ash[buf][m0 + mi * 16 + l15][kk + (lane >> 4) * 8]);
#pragma unroll
            for (int ni = 0; ni < 4; ++ni)
                ldsm2t(bh[ni], &Bs[buf][kk + l15][n0 + ni * 8]);
#pragma unroll
            for (int mi = 0; mi < 3; ++mi)
#pragma unroll
                for (int ni = 0; ni < 4; ++ni)
                    mma16816(acc[mi][ni], ah[mi], bh[ni]);
        }
        buf ^= 1;
    }

#pragma unroll
    for (int mi = 0; mi < 3; ++mi)
#pragma unroll
        for (int ni = 0; ni < 4; ++ni) {
            const int r = bm + m0 + mi * 16 + (lane >> 2);
            const int cc = bn + n0 + ni * 8 + (lane & 3) * 2;
            const float* a = acc[mi][ni];
            if constexpr (Map::CMODE == 1) {
                __half2 v0; v0.x = __float2half(a[0]); v0.y = __float2half(a[1]);
                __half2 v1; v1.x = __float2half(a[2]); v1.y = __float2half(a[3]);
                *(__half2*)(map.cRow(z, r) + cc)     = v0;
                *(__half2*)(map.cRow(z, r + 8) + cc) = v1;
            } else {
                *(float2*)(map.cRowF(z, r) + cc)     = make_float2(a[0], a[1]);
                *(float2*)(map.cRowF(z, r + 8) + cc) = make_float2(a[2], a[3]);
            }
        }
}

// =====================================================================
// Gram: C[i,j] = sum_n q[i,n]*k[j,n]  (both fp16 hi only).
// BM=BN=96 BK=32, split-K=8, 2-stage cp.async.
// =====================================================================
__global__ __launch_bounds__(256, 2) void gram_mma(
    const __half* __restrict__ dwh, float* __restrict__ gramp)
{
    __shared__ alignas(16) __half Ash[2][96][40];
    __shared__ alignas(16) __half Bsh[2][96][40];
    constexpr unsigned STG = 96 * 40 * 2;
    constexpr int KS_LEN = 8192 / KSPLIT_;
    constexpr int NSTG = KS_LEN / 32;

    const int z = blockIdx.z;
    const int ks = z & (KSPLIT_ - 1), bh_ = z / KSPLIT_;
    const int h = bh_ & 7, b = bh_ >> 3;
    const int bi = blockIdx.y * 96, bj = blockIdx.x * 96;
    const int tid = threadIdx.x, lane = tid & 31, w = tid >> 5;
    const int m0 = (w >> 2) * 48, n0 = (w & 3) * 24;
    const int kbase = ks * KS_LEN;

    // 768 chunks: 0..383 q -> Ash, 384..767 k -> Bsh; 3 iters exact
    const __half* src[3]; unsigned dst[3];
#pragma unroll
    for (int it = 0; it < 3; ++it) {
        int idx = tid + it * 256;
        int which = idx / 384, w2 = idx % 384;
        int row = w2 >> 2, c4 = w2 & 3;
        size_t off;
        if (which == 0) {
            int qi = bi + row;
            off = ((size_t)(b * C3_ + h * 24 + (qi >> 3)) << 16) + ((size_t)(qi & 7) << 13);
        } else {
            int kj = bj + row;
            off = ((size_t)(b * C3_ + C_ + h * 24 + (kj >> 3)) << 16) + ((size_t)(kj & 7) << 13);
        }
        src[it] = dwh + off + kbase + c4 * 8;
        __half* d = which == 0 ? &Ash[0][row][c4 * 8] : &Bsh[0][row][c4 * 8];
        dst[it] = (unsigned)__cvta_generic_to_shared(d);
    }

    float acc[3][3][4];
#pragma unroll
    for (int i = 0; i < 3; ++i)
#pragma unroll
        for (int j = 0; j < 3; ++j)
#pragma unroll
            for (int q = 0; q < 4; ++q) acc[i][j][q] = 0.f;

    {
#pragma unroll
        for (int it = 0; it < 3; ++it) cpa16(dst[it], src[it]);
        CP_COMMIT();
    }
    int buf = 0;
#pragma unroll 1
    for (int s = 0; s < NSTG; ++s) {
        CP_WAIT0();
        __syncthreads();
        if (s + 1 < NSTG) {
            const unsigned o = (buf ^ 1) * STG;
            const int ka = (s + 1) * 32;
#pragma unroll
            for (int it = 0; it < 3; ++it) cpa16(dst[it] + o, src[it] + ka);
            CP_COMMIT();
        }
#pragma unroll
        for (int kk = 0; kk < 32; kk += 16) {
            unsigned ah[3][4], bh2[3][2];
            const int l15 = lane & 15;
#pragma unroll
            for (int mi = 0; mi < 3; ++mi)
                ldsm4(ah[mi], &Ash[buf][m0 + mi * 16 + l15][kk + (lane >> 4) * 8]);
#pragma unroll
            for (int ni = 0; ni < 3; ++ni)
                ldsm2(bh2[ni], &Bsh[buf][n0 + ni * 8 + (l15 & 7)][kk + ((l15 >> 3) << 3)]);
#pragma unroll
            for (int mi = 0; mi < 3; ++mi)
#pragma unroll
                for (int ni = 0; ni < 3; ++ni)
                    mma16816(acc[mi][ni], ah[mi], bh2[ni]);
        }
        buf ^= 1;
    }

    float* gp = gramp + ((size_t)ks * (B_ * HEADS_) + bh_) * (C_ * C_);
#pragma unroll
    for (int mi = 0; mi < 3; ++mi)
#pragma unroll
        for (int ni = 0; ni < 3; ++ni) {
            const int r = bi + m0 + mi * 16 + (lane >> 2);
            const int cc = bj + n0 + ni * 8 + (lane & 3) * 2;
            const float* a = acc[mi][ni];
            *(float2*)(gp + (size_t)r * C_ + cc)       = make_float2(a[0], a[1]);
            *(float2*)(gp + (size_t)(r + 8) * C_ + cc) = make_float2(a[2], a[3]);
        }
}

// ---------------- depthwise 3x3 (fp16 in/out) + norm partials -----------------
__global__ __launch_bounds__(256) void dw_kernel(
    const __half* __restrict__ inh, const float* __restrict__ dww,
    __half* __restrict__ outh,
    float* __restrict__ partq, float* __restrict__ partk)
{
    const int chg = blockIdx.z;            // b*576 + c
    const int c = chg % C3_;
    const int b = chg / C3_;
    const size_t base = (size_t)chg << 16;

    float w[9];
#pragma unroll
    for (int i = 0; i < 9; ++i) w[i] = __ldg(&dww[c * 9 + i]);

    __shared__ float s[34][34];
    const int ox = blockIdx.x * 32 - 1, oy = blockIdx.y * 32 - 1;
    for (int t = threadIdx.x; t < 34 * 34; t += 256) {
        int lx = t % 34, ly = t / 34;
        int gx = ox + lx, gy = oy + ly;
        float v = 0.f;
        if ((unsigned)gx < W_ && (unsigned)gy < H_) v = __half2float(inh[base + gy * W_ + gx]);
        s[ly][lx] = v;
    }
    __syncthreads();

    const int tx = threadIdx.x & 31, ty0 = threadIdx.x >> 5;
    float ss = 0.f;
#pragma unroll
    for (int r = 0; r < 4; ++r) {
        int ly = ty0 + 8 * r;
        float acc = s[ly + 0][tx + 0] * w[0] + s[ly + 0][tx + 1] * w[1] + s[ly + 0][tx + 2] * w[2]
                  + s[ly + 1][tx + 0] * w[3] + s[ly + 1][tx + 1] * w[4] + s[ly + 1][tx + 2] * w[5]
                  + s[ly + 2][tx + 0] * w[6] + s[ly + 2][tx + 1] * w[7] + s[ly + 2][tx + 2] * w[8];
        ss += acc * acc;
        size_t sp = (size_t)(blockIdx.y * 32 + ly) * W_ + blockIdx.x * 32 + tx;
        outh[base + sp] = __float2half(acc);
    }

    if (c < 2 * C_) {
        __shared__ float red[8];
#pragma unroll
        for (int o = 16; o > 0; o >>= 1) ss += __shfl_xor_sync(0xffffffffu, ss, o);
        if ((threadIdx.x & 31) == 0) red[threadIdx.x >> 5] = ss;
        __syncthreads();
        if (threadIdx.x == 0) {
            float tot = 0.f;
#pragma unroll
            for (int i = 0; i < 8; ++i) tot += red[i];
            if (c < C_)
                partq[((b * C_ + c) * 8 + blockIdx.y) * 8 + blockIdx.x] = tot;
            else
                partk[((b * C_ + (c - C_)) * 8 + blockIdx.y) * 8 + blockIdx.x] = tot;
        }
    }
}

__global__ void norms_finish(
    const float* __restrict__ partq, const float* __restrict__ partk,
    float* __restrict__ invq, float* __restrict__ invk)
{
    int idx = blockIdx.x * blockDim.x + threadIdx.x;
    if (idx < B_ * C_ * 8) {
        float sq = 0.f, sk = 0.f;
#pragma unroll
        for (int i = 0; i < 8; ++i) { sq += partq[idx * 8 + i]; sk += partk[idx * 8 + i]; }
        invq[idx] = 1.f / fmaxf(sqrtf(sq), 1e-12f);
        invk[idx] = 1.f / fmaxf(sqrtf(sk), 1e-12f);
    }
}

// ---------------- split-K reduce + scale + softmax -> fp16 ---------------
__global__ void softmax_kernel(
    const float* __restrict__ gramp, const float* __restrict__ invq,
    const float* __restrict__ invk, const float* __restrict__ temp,
    __half* __restrict__ attnh)
{
    const int i = blockIdx.x % C_;
    const int bh = blockIdx.x / C_;
    const int head = bh & 7, b = bh >> 3;
    const int j = threadIdx.x;

    const long long base = (long long)bh * (C_ * C_) + i * C_ + j;
    float s = 0.f;
#pragma unroll
    for (int ks = 0; ks < KSPLIT_; ++ks)
        s += gramp[(long long)ks * (B_ * HEADS_ * C_ * C_) + base];

    s *= invq[(b * C_ + head * 24 + (i >> 3)) * 8 + (i & 7)]
       * invk[(b * C_ + head * 24 + (j >> 3)) * 8 + (j & 7)]
       * temp[head];

    __shared__ float red[8];
    float m = s;
#pragma unroll
    for (int o = 16; o > 0; o >>= 1) m = fmaxf(m, __shfl_xor_sync(0xffffffffu, m, o));
    if ((threadIdx.x & 31) == 0) red[threadIdx.x >> 5] = m;
    __syncthreads();
    m = fmaxf(fmaxf(fmaxf(red[0], red[1]), fmaxf(red[2], red[3])), fmaxf(red[4], red[5]));

    float p = expf(s - m);
    float sum = p;
#pragma unroll
    for (int o = 16; o > 0; o >>= 1) sum += __shfl_xor_sync(0xffffffffu, sum, o);
    __syncthreads();
    if ((threadIdx.x & 31) == 0) red[threadIdx.x >> 5] = sum;
    __syncthreads();
    sum = red[0] + red[1] + red[2] + red[3] + red[4] + red[5];

    attnh[base] = __float2half(p / sum);
}

// ---------------- launch -------------------------------------------------------
extern "C" void kernel_launch(void* const* d_in, const int* in_sizes, int n_in,
                              void* d_out, int out_size)
{
    const float* x      = (const float*)d_in[0];
    const float* qkv_w  = (const float*)d_in[1];
    const float* dw_w   = (const float*)d_in[2];
    const float* proj_w = (const float*)d_in[3];
    const float* temp   = (const float*)d_in[4];
    float* out = (float*)d_out;

    __half *xh, *wqh, *wph, *qkvh, *dwh, *av, *attnh;
    float *gramp, *partq, *partk, *invq, *invk;
    cudaGetSymbolAddress((void**)&xh,   g_xh);
    cudaGetSymbolAddress((void**)&wqh,  g_wqh);
    cudaGetSymbolAddress((void**)&wph,  g_wph);
    cudaGetSymbolAddress((void**)&qkvh, g_qkvh);
    cudaGetSymbolAddress((void**)&dwh,  g_dwh);
    cudaGetSymbolAddress((void**)&av,   g_av);
    cudaGetSymbolAddress((void**)&attnh, g_attnh);
    cudaGetSymbolAddress((void**)&gramp, g_gramp);
    cudaGetSymbolAddress((void**)&partq, g_partq);
    cudaGetSymbolAddress((void**)&partk, g_partk);
    cudaGetSymbolAddress((void**)&invq,  g_invq);
    cudaGetSymbolAddress((void**)&invk,  g_invk);

    // 0) fp16 converts
    split_h_kernel<<<(B_ * C_ * HW_ / 4 + 255) / 256, 256>>>(x, xh, B_ * C_ * HW_);
    split_h_kernel<<<(C3_ * C_ / 4 + 255) / 256, 256>>>(qkv_w, wqh, C3_ * C_);
    split_h_kernel<<<(C_ * C_ / 4 + 255) / 256, 256>>>(proj_w, wph, C_ * C_);

    // 1) qkv = qkv_w @ x
    {
        QkvMap m{wqh, xh, qkvh};
        gemm_mma<QkvMap><<<dim3(HW_ / 128, C3_ / 96, B_), 256>>>(m, C_);
    }
    // 2) depthwise 3x3 + norm partials
    dw_kernel<<<dim3(W_ / 32, H_ / 32, B_ * C3_), 256>>>(qkvh, dw_w, dwh, partq, partk);
    // 3) norms
    norms_finish<<<(B_ * C_ * 8 + 255) / 256, 256>>>(partq, partk, invq, invk);
    // 4) gram partials
    gram_mma<<<dim3(2, 2, B_ * HEADS_ * KSPLIT_), 256>>>(dwh, gramp);
    // 5) softmax
    softmax_kernel<<<B_ * HEADS_ * C_, C_>>>(gramp, invq, invk, temp, attnh);
    // 6) av = attn @ v
    {
        AvMap m{attnh, dwh, av};
        gemm_mma<AvMap><<<dim3(HW_ / HEADS_ / 128, C_ / 96, B_ * HEADS_), 256>>>(m, C_);
    }
    // 7) out = proj_w @ av
    {
        ProjMap m{wph, av, out};
        gemm_mma<ProjMap><<<dim3(HW_ / 128, C_ / 96, B_), 256>>>(m, C_);
    }
}

// round 12
// speedup vs baseline: 1.7097x; 1.0630x over previous
#include <cuda_runtime.h>
#include <cuda_fp16.h>
#include <cstdint>

#define B_      2
#define C_      192
#define C3_     576
#define H_      256
#define W_      256
#define HW_     65536
#define HEADS_  8
#define KSPLIT_ 8

// ---------------- scratch (device globals: allocation-free rule) ----------------
__device__ __half g_xh  [(size_t)B_ * C_ * HW_];
__device__ __half g_wqh [C3_ * C_];
__device__ __half g_wph [C_ * C_];
__device__ __half g_qkvh[(size_t)B_ * C3_ * HW_];
__device__ __half g_dwh [(size_t)B_ * C3_ * HW_];
__device__ __half g_av  [(size_t)B_ * C_ * HW_];
__device__ float  g_gramp[(size_t)KSPLIT_ * B_ * HEADS_ * C_ * C_];
__device__ __half g_attnh[(size_t)B_ * HEADS_ * C_ * C_];
__device__ float g_partq[B_ * C_ * 64];
__device__ float g_partk[B_ * C_ * 64];
__device__ float g_invq [B_ * C_ * 8];
__device__ float g_invk [B_ * C_ * 8];

// ---------------- mma / ldmatrix / cp.async helpers ----------------
__device__ __forceinline__ void ldsm4(unsigned* r, const void* p) {
    unsigned a = (unsigned)__cvta_generic_to_shared(p);
    asm volatile("ldmatrix.sync.aligned.m8n8.x4.shared.b16 {%0,%1,%2,%3}, [%4];"
                 : "=r"(r[0]), "=r"(r[1]), "=r"(r[2]), "=r"(r[3]) : "r"(a));
}
__device__ __forceinline__ void ldsm2t(unsigned* r, const void* p) {
    unsigned a = (unsigned)__cvta_generic_to_shared(p);
    asm volatile("ldmatrix.sync.aligned.m8n8.x2.trans.shared.b16 {%0,%1}, [%2];"
                 : "=r"(r[0]), "=r"(r[1]) : "r"(a));
}
__device__ __forceinline__ void ldsm2(unsigned* r, const void* p) {
    unsigned a = (unsigned)__cvta_generic_to_shared(p);
    asm volatile("ldmatrix.sync.aligned.m8n8.x2.shared.b16 {%0,%1}, [%2];"
                 : "=r"(r[0]), "=r"(r[1]) : "r"(a));
}
__device__ __forceinline__ void mma16816(float* c, const unsigned* a, const unsigned* b) {
    asm volatile("mma.sync.aligned.m16n8k16.row.col.f32.f16.f16.f32 "
                 "{%0,%1,%2,%3},{%4,%5,%6,%7},{%8,%9},{%0,%1,%2,%3};"
                 : "+f"(c[0]), "+f"(c[1]), "+f"(c[2]), "+f"(c[3])
                 : "r"(a[0]), "r"(a[1]), "r"(a[2]), "r"(a[3]), "r"(b[0]), "r"(b[1]));
}
__device__ __forceinline__ void cpa16(unsigned dst, const void* src) {
    asm volatile("cp.async.cg.shared.global [%0], [%1], 16;\n" :: "r"(dst), "l"(src));
}
#define CP_COMMIT() asm volatile("cp.async.commit_group;\n")
#define CP_WAIT2()  asm volatile("cp.async.wait_group 2;\n" ::: "memory")

// ---------------- fp32 -> fp16 convert ----------------
__global__ __launch_bounds__(256) void split_h_kernel(
    const float* __restrict__ in, __half* __restrict__ oh, int n)
{
    int i = (blockIdx.x * 256 + threadIdx.x) * 4;
    if (i < n) {
        float4 v = *(const float4*)(in + i);
        __half2 a; a.x = __float2half(v.x); a.y = __float2half(v.y);
        __half2 b; b.x = __float2half(v.z); b.y = __float2half(v.w);
        ((__half2*)(oh + i))[0] = a;
        ((__half2*)(oh + i))[1] = b;
    }
}

// ---------------- maps ----------------
struct QkvMap {
    const __half *Ah, *B; __half *Cc;
    static constexpr int CMODE = 1;
    static constexpr size_t BSTRIDE32 = (size_t)32 * HW_;
    __device__ const __half* aRowH(int z, int m) const { return Ah + (size_t)m * C_; }
    __device__ const __half* bRow(int z, int k) const { return B + ((size_t)z * C_ + k) * HW_; }
    __device__ __half* cRow(int z, int m) const { return Cc + ((size_t)z * C3_ + m) * HW_; }
    __device__ float*  cRowF(int z, int m) const { return nullptr; }
};
struct AvMap {
    const __half *Ah, *B; __half *Cc;
    static constexpr int CMODE = 1;
    static constexpr size_t BSTRIDE32 = (size_t)4 << 16;
    __device__ const __half* aRowH(int z, int m) const { return Ah + (size_t)z * (C_ * C_) + (size_t)m * C_; }
    __device__ const __half* bRow(int z, int k) const {
        int b = z >> 3, h = z & 7;
        return B + ((size_t)(b * C3_ + 2 * C_ + h * 24 + (k >> 3)) << 16) + ((k & 7) << 13);
    }
    __device__ __half* cRow(int z, int m) const {
        int b = z >> 3, h = z & 7;
        return Cc + ((size_t)(b * C_ + h * 24 + (m >> 3)) << 16) + ((m & 7) << 13);
    }
    __device__ float*  cRowF(int z, int m) const { return nullptr; }
};
struct ProjMap {
    const __half *Ah, *B; float* C;
    static constexpr int CMODE = 2;
    static constexpr size_t BSTRIDE32 = (size_t)32 * HW_;
    __device__ const __half* aRowH(int z, int m) const { return Ah + (size_t)m * C_; }
    __device__ const __half* bRow(int z, int k) const { return B + ((size_t)z * C_ + k) * HW_; }
    __device__ float* cRowF(int z, int m) const { return C + ((size_t)z * C_ + m) * HW_; }
    __device__ __half* cRow(int z, int m) const { return nullptr; }
};

// =====================================================================
// fp16 MMA GEMM: C = Ah @ B.  BM=96 BN=128 BK=32, 4-stage cp.async ring
// (3 load groups in flight), 256 threads, warp tile 48x32. Dynamic smem.
// =====================================================================
#define GEMM_ASTGB 7680u            // 96*40*2
#define GEMM_BSTGB 8704u            // 32*136*2
#define GEMM_SMEM  (4 * (GEMM_ASTGB + GEMM_BSTGB))   // 65536

template <class Map>
__global__ __launch_bounds__(256, 2) void gemm_mma(const Map map, const int K)
{
    extern __shared__ char smraw[];
    __half* Abase = (__half*)smraw;                       // 4 x 3840 halves
    __half* Bbase = (__half*)(smraw + 4 * GEMM_ASTGB);    // 4 x 4352 halves

    const int z = blockIdx.z, bm = blockIdx.y * 96, bn = blockIdx.x * 128;
    const int tid = threadIdx.x, lane = tid & 31, w = tid >> 5;
    const int m0 = (w >> 2) * 48, n0 = (w & 3) * 32;

    // A loaders: 384 chunks, 2 iters (last partial)
    const __half* asrc[2]; unsigned adst[2]; bool aval[2];
#pragma unroll
    for (int it = 0; it < 2; ++it) {
        int idx = tid + it * 256;
        aval[it] = idx < 384;
        if (idx >= 384) idx = 383;
        int row = idx >> 2, c4 = idx & 3;
        asrc[it] = map.aRowH(z, bm + row) + c4 * 8;
        adst[it] = (unsigned)__cvta_generic_to_shared(Abase + row * 40 + c4 * 8);
    }
    // B loaders: 512 chunks, 2 iters
    const __half* bsrc[2]; unsigned bdst[2];
#pragma unroll
    for (int it = 0; it < 2; ++it) {
        int idx = tid + it * 256;
        int row = idx >> 4, c4 = idx & 15;
        bsrc[it] = map.bRow(z, row) + bn + c4 * 8;
        bdst[it] = (unsigned)__cvta_generic_to_shared(Bbase + row * 136 + c4 * 8);
    }

    float acc[3][4][4];
#pragma unroll
    for (int i = 0; i < 3; ++i)
#pragma unroll
        for (int j = 0; j < 4; ++j)
#pragma unroll
            for (int q = 0; q < 4; ++q) acc[i][j][q] = 0.f;

    const int nStage = K >> 5;
    // prologue: stages 0,1,2 (one commit group each)
#pragma unroll
    for (int p = 0; p < 3; ++p) {
        if (p < nStage) {
#pragma unroll
            for (int it = 0; it < 2; ++it) if (aval[it]) cpa16(adst[it] + p * GEMM_ASTGB, asrc[it] + p * 32);
#pragma unroll
            for (int it = 0; it < 2; ++it) cpa16(bdst[it] + p * GEMM_BSTGB, bsrc[it] + (size_t)p * Map::BSTRIDE32);
        }
        CP_COMMIT();
    }

#pragma unroll 1
    for (int s = 0; s < nStage; ++s) {
        CP_WAIT2();
        __syncthreads();
        if (s + 3 < nStage) {
            const unsigned b4 = (unsigned)((s + 3) & 3);
            const int ka = (s + 3) * 32;
            const size_t kb = (size_t)(s + 3) * Map::BSTRIDE32;
#pragma unroll
            for (int it = 0; it < 2; ++it) if (aval[it]) cpa16(adst[it] + b4 * GEMM_ASTGB, asrc[it] + ka);
#pragma unroll
            for (int it = 0; it < 2; ++it) cpa16(bdst[it] + b4 * GEMM_BSTGB, bsrc[it] + kb);
        }
        CP_COMMIT();
        const __half* As  = Abase + (s & 3) * 3840;
        const __half* Bsp = Bbase + (s & 3) * 4352;
#pragma unroll
        for (int kk = 0; kk < 32; kk += 16) {
            unsigned ah[3][4], bh[4][2];
            const int l15 = lane & 15;
#pragma unroll
            for (int mi = 0; mi < 3; ++mi)
                ldsm4(ah[mi], As + (m0 + mi * 16 + l15) * 40 + kk + (lane >> 4) * 8);
#pragma unroll
            for (int ni = 0; ni < 4; ++ni)
                ldsm2t(bh[ni], Bsp + (kk + l15) * 136 + n0 + ni * 8);
#pragma unroll
            for (int mi = 0; mi < 3; ++mi)
#pragma unroll
                for (int ni = 0; ni < 4; ++ni)
                    mma16816(acc[mi][ni], ah[mi], bh[ni]);
        }
    }

#pragma unroll
    for (int mi = 0; mi < 3; ++mi)
#pragma unroll
        for (int ni = 0; ni < 4; ++ni) {
            const int r = bm + m0 + mi * 16 + (lane >> 2);
            const int cc = bn + n0 + ni * 8 + (lane & 3) * 2;
            const float* a = acc[mi][ni];
            if constexpr (Map::CMODE == 1) {
                __half2 v0; v0.x = __float2half(a[0]); v0.y = __float2half(a[1]);
                __half2 v1; v1.x = __float2half(a[2]); v1.y = __float2half(a[3]);
                *(__half2*)(map.cRow(z, r) + cc)     = v0;
                *(__half2*)(map.cRow(z, r + 8) + cc) = v1;
            } else {
                *(float2*)(map.cRowF(z, r) + cc)     = make_float2(a[0], a[1]);
                *(float2*)(map.cRowF(z, r + 8) + cc) = make_float2(a[2], a[3]);
            }
        }
}

// =====================================================================
// Gram: C[i,j] = sum_n q[i,n]*k[j,n] (fp16). BM=BN=96 BK=32,
// split-K=8, 4-stage cp.async ring, dynamic smem.
// =====================================================================
#define GRAM_STGB 7680u
#define GRAM_SMEM (4 * 2 * GRAM_STGB)   // 61440

__global__ __launch_bounds__(256, 2) void gram_mma(
    const __half* __restrict__ dwh, float* __restrict__ gramp)
{
    extern __shared__ char smraw[];
    __half* Abase = (__half*)smraw;                      // 4 x 3840 halves
    __half* Bbase = (__half*)(smraw + 4 * GRAM_STGB);

    constexpr int KS_LEN = 8192 / KSPLIT_;
    constexpr int NSTG = KS_LEN / 32;

    const int z = blockIdx.z;
    const int ks = z & (KSPLIT_ - 1), bh_ = z / KSPLIT_;
    const int h = bh_ & 7, b = bh_ >> 3;
    const int bi = blockIdx.y * 96, bj = blockIdx.x * 96;
    const int tid = threadIdx.x, lane = tid & 31, w = tid >> 5;
    const int m0 = (w >> 2) * 48, n0 = (w & 3) * 24;
    const int kbase = ks * KS_LEN;

    // 768 chunks: 0..383 q -> A, 384..767 k -> B; 3 iters exact
    const __half* src[3]; unsigned dst[3];
#pragma unroll
    for (int it = 0; it < 3; ++it) {
        int idx = tid + it * 256;
        int which = idx / 384, w2 = idx % 384;
        int row = w2 >> 2, c4 = w2 & 3;
        size_t off;
        if (which == 0) {
            int qi = bi + row;
            off = ((size_t)(b * C3_ + h * 24 + (qi >> 3)) << 16) + ((size_t)(qi & 7) << 13);
        } else {
            int kj = bj + row;
            off = ((size_t)(b * C3_ + C_ + h * 24 + (kj >> 3)) << 16) + ((size_t)(kj & 7) << 13);
        }
        src[it] = dwh + off + kbase + c4 * 8;
        __half* d = (which == 0 ? Abase : Bbase) + row * 40 + c4 * 8;
        dst[it] = (unsigned)__cvta_generic_to_shared(d);
    }

    float acc[3][3][4];
#pragma unroll
    for (int i = 0; i < 3; ++i)
#pragma unroll
        for (int j = 0; j < 3; ++j)
#pragma unroll
            for (int q = 0; q < 4; ++q) acc[i][j][q] = 0.f;

#pragma unroll
    for (int p = 0; p < 3; ++p) {
#pragma unroll
        for (int it = 0; it < 3; ++it) cpa16(dst[it] + p * GRAM_STGB, src[it] + p * 32);
        CP_COMMIT();
    }

#pragma unroll 1
    for (int s = 0; s < NSTG; ++s) {
        CP_WAIT2();
        __syncthreads();
        if (s + 3 < NSTG) {
            const unsigned b4 = (unsigned)((s + 3) & 3);
            const int ka = (s + 3) * 32;
#pragma unroll
            for (int it = 0; it < 3; ++it) cpa16(dst[it] + b4 * GRAM_STGB, src[it] + ka);
        }
        CP_COMMIT();
        const __half* As = Abase + (s & 3) * 3840;
        const __half* Bs = Bbase + (s & 3) * 3840;
#pragma unroll
        for (int kk = 0; kk < 32; kk += 16) {
            unsigned ah[3][4], bh2[3][2];
            const int l15 = lane & 15;
#pragma unroll
            for (int mi = 0; mi < 3; ++mi)
                ldsm4(ah[mi], As + (m0 + mi * 16 + l15) * 40 + kk + (lane >> 4) * 8);
#pragma unroll
            for (int ni = 0; ni < 3; ++ni)
                ldsm2(bh2[ni], Bs + (n0 + ni * 8 + (l15 & 7)) * 40 + kk + ((l15 >> 3) << 3));
#pragma unroll
            for (int mi = 0; mi < 3; ++mi)
#pragma unroll
                for (int ni = 0; ni < 3; ++ni)
                    mma16816(acc[mi][ni], ah[mi], bh2[ni]);
        }
    }

    float* gp = gramp + ((size_t)ks * (B_ * HEADS_) + bh_) * (C_ * C_);
#pragma unroll
    for (int mi = 0; mi < 3; ++mi)
#pragma unroll
        for (int ni = 0; ni < 3; ++ni) {
            const int r = bi + m0 + mi * 16 + (lane >> 2);
            const int cc = bj + n0 + ni * 8 + (lane & 3) * 2;
            const float* a = acc[mi][ni];
            *(float2*)(gp + (size_t)r * C_ + cc)       = make_float2(a[0], a[1]);
            *(float2*)(gp + (size_t)(r + 8) * C_ + cc) = make_float2(a[2], a[3]);
        }
}

// ---------------- depthwise 3x3 (fp16 in/out) + norm partials -----------------
__global__ __launch_bounds__(256) void dw_kernel(
    const __half* __restrict__ inh, const float* __restrict__ dww,
    __half* __restrict__ outh,
    float* __restrict__ partq, float* __restrict__ partk)
{
    const int chg = blockIdx.z;            // b*576 + c
    const int c = chg % C3_;
    const int b = chg / C3_;
    const size_t base = (size_t)chg << 16;

    float w[9];
#pragma unroll
    for (int i = 0; i < 9; ++i) w[i] = __ldg(&dww[c * 9 + i]);

    __shared__ float s[34][34];
    const int ox = blockIdx.x * 32 - 1, oy = blockIdx.y * 32 - 1;
    for (int t = threadIdx.x; t < 34 * 34; t += 256) {
        int lx = t % 34, ly = t / 34;
        int gx = ox + lx, gy = oy + ly;
        float v = 0.f;
        if ((unsigned)gx < W_ && (unsigned)gy < H_) v = __half2float(inh[base + gy * W_ + gx]);
        s[ly][lx] = v;
    }
    __syncthreads();

    const int tx = threadIdx.x & 31, ty0 = threadIdx.x >> 5;
    float ss = 0.f;
#pragma unroll
    for (int r = 0; r < 4; ++r) {
        int ly = ty0 + 8 * r;
        float acc = s[ly + 0][tx + 0] * w[0] + s[ly + 0][tx + 1] * w[1] + s[ly + 0][tx + 2] * w[2]
                  + s[ly + 1][tx + 0] * w[3] + s[ly + 1][tx + 1] * w[4] + s[ly + 1][tx + 2] * w[5]
                  + s[ly + 2][tx + 0] * w[6] + s[ly + 2][tx + 1] * w[7] + s[ly + 2][tx + 2] * w[8];
        ss += acc * acc;
        size_t sp = (size_t)(blockIdx.y * 32 + ly) * W_ + blockIdx.x * 32 + tx;
        outh[base + sp] = __float2half(acc);
    }

    if (c < 2 * C_) {
        __shared__ float red[8];
#pragma unroll
        for (int o = 16; o > 0; o >>= 1) ss += __shfl_xor_sync(0xffffffffu, ss, o);
        if ((threadIdx.x & 31) == 0) red[threadIdx.x >> 5] = ss;
        __syncthreads();
        if (threadIdx.x == 0) {
            float tot = 0.f;
#pragma unroll
            for (int i = 0; i < 8; ++i) tot += red[i];
            if (c < C_)
                partq[((b * C_ + c) * 8 + blockIdx.y) * 8 + blockIdx.x] = tot;
            else
                partk[((b * C_ + (c - C_)) * 8 + blockIdx.y) * 8 + blockIdx.x] = tot;
        }
    }
}

__global__ void norms_finish(
    const float* __restrict__ partq, const float* __restrict__ partk,
    float* __restrict__ invq, float* __restrict__ invk)
{
    int idx = blockIdx.x * blockDim.x + threadIdx.x;
    if (idx < B_ * C_ * 8) {
        float sq = 0.f, sk = 0.f;
#pragma unroll
        for (int i = 0; i < 8; ++i) { sq += partq[idx * 8 + i]; sk += partk[idx * 8 + i]; }
        invq[idx] = 1.f / fmaxf(sqrtf(sq), 1e-12f);
        invk[idx] = 1.f / fmaxf(sqrtf(sk), 1e-12f);
    }
}

// ---------------- split-K reduce + scale + softmax -> fp16 ---------------
__global__ void softmax_kernel(
    const float* __restrict__ gramp, const float* __restrict__ invq,
    const float* __restrict__ invk, const float* __restrict__ temp,
    __half* __restrict__ attnh)
{
    const int i = blockIdx.x % C_;
    const int bh = blockIdx.x / C_;
    const int head = bh & 7, b = bh >> 3;
    const int j = threadIdx.x;

    const long long base = (long long)bh * (C_ * C_) + i * C_ + j;
    float s = 0.f;
#pragma unroll
    for (int ks = 0; ks < KSPLIT_; ++ks)
        s += gramp[(long long)ks * (B_ * HEADS_ * C_ * C_) + base];

    s *= invq[(b * C_ + head * 24 + (i >> 3)) * 8 + (i & 7)]
       * invk[(b * C_ + head * 24 + (j >> 3)) * 8 + (j & 7)]
       * temp[head];

    __shared__ float red[8];
    float m = s;
#pragma unroll
    for (int o = 16; o > 0; o >>= 1) m = fmaxf(m, __shfl_xor_sync(0xffffffffu, m, o));
    if ((threadIdx.x & 31) == 0) red[threadIdx.x >> 5] = m;
    __syncthreads();
    m = fmaxf(fmaxf(fmaxf(red[0], red[1]), fmaxf(red[2], red[3])), fmaxf(red[4], red[5]));

    float p = expf(s - m);
    float sum = p;
#pragma unroll
    for (int o = 16; o > 0; o >>= 1) sum += __shfl_xor_sync(0xffffffffu, sum, o);
    __syncthreads();
    if ((threadIdx.x & 31) == 0) red[threadIdx.x >> 5] = sum;
    __syncthreads();
    sum = red[0] + red[1] + red[2] + red[3] + red[4] + red[5];

    attnh[base] = __float2half(p / sum);
}

// ---------------- launch -------------------------------------------------------
extern "C" void kernel_launch(void* const* d_in, const int* in_sizes, int n_in,
                              void* d_out, int out_size)
{
    const float* x      = (const float*)d_in[0];
    const float* qkv_w  = (const float*)d_in[1];
    const float* dw_w   = (const float*)d_in[2];
    const float* proj_w = (const float*)d_in[3];
    const float* temp   = (const float*)d_in[4];
    float* out = (float*)d_out;

    __half *xh, *wqh, *wph, *qkvh, *dwh, *av, *attnh;
    float *gramp, *partq, *partk, *invq, *invk;
    cudaGetSymbolAddress((void**)&xh,   g_xh);
    cudaGetSymbolAddress((void**)&wqh,  g_wqh);
    cudaGetSymbolAddress((void**)&wph,  g_wph);
    cudaGetSymbolAddress((void**)&qkvh, g_qkvh);
    cudaGetSymbolAddress((void**)&dwh,  g_dwh);
    cudaGetSymbolAddress((void**)&av,   g_av);
    cudaGetSymbolAddress((void**)&attnh, g_attnh);
    cudaGetSymbolAddress((void**)&gramp, g_gramp);
    cudaGetSymbolAddress((void**)&partq, g_partq);
    cudaGetSymbolAddress((void**)&partk, g_partk);
    cudaGetSymbolAddress((void**)&invq,  g_invq);
    cudaGetSymbolAddress((void**)&invk,  g_invk);

    cudaFuncSetAttribute(gemm_mma<QkvMap>,  cudaFuncAttributeMaxDynamicSharedMemorySize, GEMM_SMEM);
    cudaFuncSetAttribute(gemm_mma<AvMap>,   cudaFuncAttributeMaxDynamicSharedMemorySize, GEMM_SMEM);
    cudaFuncSetAttribute(gemm_mma<ProjMap>, cudaFuncAttributeMaxDynamicSharedMemorySize, GEMM_SMEM);
    cudaFuncSetAttribute(gram_mma,          cudaFuncAttributeMaxDynamicSharedMemorySize, GRAM_SMEM);

    // 0) fp16 converts
    split_h_kernel<<<(B_ * C_ * HW_ / 4 + 255) / 256, 256>>>(x, xh, B_ * C_ * HW_);
    split_h_kernel<<<(C3_ * C_ / 4 + 255) / 256, 256>>>(qkv_w, wqh, C3_ * C_);
    split_h_kernel<<<(C_ * C_ / 4 + 255) / 256, 256>>>(proj_w, wph, C_ * C_);

    // 1) qkv = qkv_w @ x
    {
        QkvMap m{wqh, xh, qkvh};
        gemm_mma<QkvMap><<<dim3(HW_ / 128, C3_ / 96, B_), 256, GEMM_SMEM>>>(m, C_);
    }
    // 2) depthwise 3x3 + norm partials
    dw_kernel<<<dim3(W_ / 32, H_ / 32, B_ * C3_), 256>>>(qkvh, dw_w, dwh, partq, partk);
    // 3) norms
    norms_finish<<<(B_ * C_ * 8 + 255) / 256, 256>>>(partq, partk, invq, invk);
    // 4) gram partials
    gram_mma<<<dim3(2, 2, B_ * HEADS_ * KSPLIT_), 256, GRAM_SMEM>>>(dwh, gramp);
    // 5) softmax
    softmax_kernel<<<B_ * HEADS_ * C_, C_>>>(gramp, invq, invk, temp, attnh);
    // 6) av = attn @ v
    {
        AvMap m{attnh, dwh, av};
        gemm_mma<AvMap><<<dim3(HW_ / HEADS_ / 128, C_ / 96, B_ * HEADS_), 256, GEMM_SMEM>>>(m, C_);
    }
    // 7) out = proj_w @ av
    {
        ProjMap m{wph, av, out};
        gemm_mma<ProjMap><<<dim3(HW_ / 128, C_ / 96, B_), 256, GEMM_SMEM>>>(m, C_);
    }
}

// round 13
// speedup vs baseline: 1.7158x; 1.0035x over previous
#include <cuda_runtime.h>
#include <cuda_fp16.h>
#include <cstdint>

#define B_      2
#define C_      192
#define C3_     576
#define H_      256
#define W_      256
#define HW_     65536
#define HEADS_  8
#define KSPLIT_ 4

// ---------------- scratch (device globals: allocation-free rule) ----------------
__device__ __half g_xh  [(size_t)B_ * C_ * HW_];
__device__ __half g_wqh [C3_ * C_];
__device__ __half g_wph [C_ * C_];
__device__ __half g_qkvh[(size_t)B_ * C3_ * HW_];
__device__ __half g_dwh [(size_t)B_ * C3_ * HW_];
__device__ __half g_av  [(size_t)B_ * C_ * HW_];
__device__ float  g_gramp[(size_t)KSPLIT_ * B_ * HEADS_ * C_ * C_];
__device__ __half g_attnh[(size_t)B_ * HEADS_ * C_ * C_];
__device__ float g_partq[B_ * C_ * 64];
__device__ float g_partk[B_ * C_ * 64];
__device__ float g_invq [B_ * C_ * 8];
__device__ float g_invk [B_ * C_ * 8];

// ---------------- mma / ldmatrix / cp.async helpers ----------------
__device__ __forceinline__ void ldsm4(unsigned* r, const void* p) {
    unsigned a = (unsigned)__cvta_generic_to_shared(p);
    asm volatile("ldmatrix.sync.aligned.m8n8.x4.shared.b16 {%0,%1,%2,%3}, [%4];"
                 : "=r"(r[0]), "=r"(r[1]), "=r"(r[2]), "=r"(r[3]) : "r"(a));
}
__device__ __forceinline__ void ldsm4t(unsigned* r, const void* p) {
    unsigned a = (unsigned)__cvta_generic_to_shared(p);
    asm volatile("ldmatrix.sync.aligned.m8n8.x4.trans.shared.b16 {%0,%1,%2,%3}, [%4];"
                 : "=r"(r[0]), "=r"(r[1]), "=r"(r[2]), "=r"(r[3]) : "r"(a));
}
__device__ __forceinline__ void ldsm2(unsigned* r, const void* p) {
    unsigned a = (unsigned)__cvta_generic_to_shared(p);
    asm volatile("ldmatrix.sync.aligned.m8n8.x2.shared.b16 {%0,%1}, [%2];"
                 : "=r"(r[0]), "=r"(r[1]) : "r"(a));
}
__device__ __forceinline__ void mma16816(float* c, const unsigned* a, const unsigned* b) {
    asm volatile("mma.sync.aligned.m16n8k16.row.col.f32.f16.f16.f32 "
                 "{%0,%1,%2,%3},{%4,%5,%6,%7},{%8,%9},{%0,%1,%2,%3};"
                 : "+f"(c[0]), "+f"(c[1]), "+f"(c[2]), "+f"(c[3])
                 : "r"(a[0]), "r"(a[1]), "r"(a[2]), "r"(a[3]), "r"(b[0]), "r"(b[1]));
}
__device__ __forceinline__ void cpa16(unsigned dst, const void* src) {
    asm volatile("cp.async.cg.shared.global [%0], [%1], 16;\n" :: "r"(dst), "l"(src));
}
#define CP_COMMIT() asm volatile("cp.async.commit_group;\n")
#define CP_WAIT2()  asm volatile("cp.async.wait_group 2;\n" ::: "memory")

// ---------------- fp32 -> fp16 convert ----------------
__global__ __launch_bounds__(256) void split_h_kernel(
    const float* __restrict__ in, __half* __restrict__ oh, int n)
{
    int i = (blockIdx.x * 256 + threadIdx.x) * 4;
    if (i < n) {
        float4 v = *(const float4*)(in + i);
        __half2 a; a.x = __float2half(v.x); a.y = __float2half(v.y);
        __half2 b; b.x = __float2half(v.z); b.y = __float2half(v.w);
        ((__half2*)(oh + i))[0] = a;
        ((__half2*)(oh + i))[1] = b;
    }
}

// ---------------- maps ----------------
struct QkvMap {
    const __half *Ah, *B; __half *Cc;
    static constexpr int CMODE = 1;
    static constexpr size_t BSTRIDE32 = (size_t)32 * HW_;
    __device__ const __half* aRowH(int z, int m) const { return Ah + (size_t)m * C_; }
    __device__ const __half* bRow(int z, int k) const { return B + ((size_t)z * C_ + k) * HW_; }
    __device__ __half* cRow(int z, int m) const { return Cc + ((size_t)z * C3_ + m) * HW_; }
    __device__ float*  cRowF(int z, int m) const { return nullptr; }
};
struct AvMap {
    const __half *Ah, *B; __half *Cc;
    static constexpr int CMODE = 1;
    static constexpr size_t BSTRIDE32 = (size_t)4 << 16;
    __device__ const __half* aRowH(int z, int m) const { return Ah + (size_t)z * (C_ * C_) + (size_t)m * C_; }
    __device__ const __half* bRow(int z, int k) const {
        int b = z >> 3, h = z & 7;
        return B + ((size_t)(b * C3_ + 2 * C_ + h * 24 + (k >> 3)) << 16) + ((k & 7) << 13);
    }
    __device__ __half* cRow(int z, int m) const {
        int b = z >> 3, h = z & 7;
        return Cc + ((size_t)(b * C_ + h * 24 + (m >> 3)) << 16) + ((m & 7) << 13);
    }
    __device__ float*  cRowF(int z, int m) const { return nullptr; }
};
struct ProjMap {
    const __half *Ah, *B; float* C;
    static constexpr int CMODE = 2;
    static constexpr size_t BSTRIDE32 = (size_t)32 * HW_;
    __device__ const __half* aRowH(int z, int m) const { return Ah + (size_t)m * C_; }
    __device__ const __half* bRow(int z, int k) const { return B + ((size_t)z * C_ + k) * HW_; }
    __device__ float* cRowF(int z, int m) const { return C + ((size_t)z * C_ + m) * HW_; }
    __device__ __half* cRow(int z, int m) const { return nullptr; }
};

// =====================================================================
// fp16 MMA GEMM: C = Ah @ B.  BM=96 BN=128 BK=32, 4-stage cp.async ring,
// 256 threads, warp tile 48x32, ldsm4t B-frags. Dynamic smem.
// =====================================================================
#define GEMM_ASTGB 7680u            // 96*40*2
#define GEMM_BSTGB 8704u            // 32*136*2
#define GEMM_SMEM  (4 * (GEMM_ASTGB + GEMM_BSTGB))   // 65536

template <class Map>
__global__ __launch_bounds__(256, 2) void gemm_mma(const Map map, const int K)
{
    extern __shared__ char smraw[];
    __half* Abase = (__half*)smraw;
    __half* Bbase = (__half*)(smraw + 4 * GEMM_ASTGB);

    const int z = blockIdx.z, bm = blockIdx.y * 96, bn = blockIdx.x * 128;
    const int tid = threadIdx.x, lane = tid & 31, w = tid >> 5;
    const int m0 = (w >> 2) * 48, n0 = (w & 3) * 32;

    const __half* asrc[2]; unsigned adst[2]; bool aval[2];
#pragma unroll
    for (int it = 0; it < 2; ++it) {
        int idx = tid + it * 256;
        aval[it] = idx < 384;
        if (idx >= 384) idx = 383;
        int row = idx >> 2, c4 = idx & 3;
        asrc[it] = map.aRowH(z, bm + row) + c4 * 8;
        adst[it] = (unsigned)__cvta_generic_to_shared(Abase + row * 40 + c4 * 8);
    }
    const __half* bsrc[2]; unsigned bdst[2];
#pragma unroll
    for (int it = 0; it < 2; ++it) {
        int idx = tid + it * 256;
        int row = idx >> 4, c4 = idx & 15;
        bsrc[it] = map.bRow(z, row) + bn + c4 * 8;
        bdst[it] = (unsigned)__cvta_generic_to_shared(Bbase + row * 136 + c4 * 8);
    }

    float acc[3][4][4];
#pragma unroll
    for (int i = 0; i < 3; ++i)
#pragma unroll
        for (int j = 0; j < 4; ++j)
#pragma unroll
            for (int q = 0; q < 4; ++q) acc[i][j][q] = 0.f;

    const int nStage = K >> 5;
#pragma unroll
    for (int p = 0; p < 3; ++p) {
        if (p < nStage) {
#pragma unroll
            for (int it = 0; it < 2; ++it) if (aval[it]) cpa16(adst[it] + p * GEMM_ASTGB, asrc[it] + p * 32);
#pragma unroll
            for (int it = 0; it < 2; ++it) cpa16(bdst[it] + p * GEMM_BSTGB, bsrc[it] + (size_t)p * Map::BSTRIDE32);
        }
        CP_COMMIT();
    }

#pragma unroll 1
    for (int s = 0; s < nStage; ++s) {
        CP_WAIT2();
        __syncthreads();
        if (s + 3 < nStage) {
            const unsigned b4 = (unsigned)((s + 3) & 3);
            const int ka = (s + 3) * 32;
            const size_t kb = (size_t)(s + 3) * Map::BSTRIDE32;
#pragma unroll
            for (int it = 0; it < 2; ++it) if (aval[it]) cpa16(adst[it] + b4 * GEMM_ASTGB, asrc[it] + ka);
#pragma unroll
            for (int it = 0; it < 2; ++it) cpa16(bdst[it] + b4 * GEMM_BSTGB, bsrc[it] + kb);
        }
        CP_COMMIT();
        const __half* As  = Abase + (s & 3) * 3840;
        const __half* Bsp = Bbase + (s & 3) * 4352;
#pragma unroll
        for (int kk = 0; kk < 32; kk += 16) {
            unsigned ah[3][4], bh[2][4];
            const int l15 = lane & 15;
            const int g = lane >> 3;
            const int brow = kk + ((g & 1) << 3) + (lane & 7);
#pragma unroll
            for (int mi = 0; mi < 3; ++mi)
                ldsm4(ah[mi], As + (m0 + mi * 16 + l15) * 40 + kk + (lane >> 4) * 8);
#pragma unroll
            for (int p = 0; p < 2; ++p) {
                const int bcol = n0 + p * 16 + ((g >> 1) << 3);
                ldsm4t(bh[p], Bsp + brow * 136 + bcol);
            }
#pragma unroll
            for (int mi = 0; mi < 3; ++mi)
#pragma unroll
                for (int p = 0; p < 2; ++p)
#pragma unroll
                    for (int h2 = 0; h2 < 2; ++h2)
                        mma16816(acc[mi][p * 2 + h2], ah[mi], bh[p] + h2 * 2);
        }
    }

#pragma unroll
    for (int mi = 0; mi < 3; ++mi)
#pragma unroll
        for (int ni = 0; ni < 4; ++ni) {
            const int r = bm + m0 + mi * 16 + (lane >> 2);
            const int cc = bn + n0 + ni * 8 + (lane & 3) * 2;
            const float* a = acc[mi][ni];
            if constexpr (Map::CMODE == 1) {
                __half2 v0; v0.x = __float2half(a[0]); v0.y = __float2half(a[1]);
                __half2 v1; v1.x = __float2half(a[2]); v1.y = __float2half(a[3]);
                *(__half2*)(map.cRow(z, r) + cc)     = v0;
                *(__half2*)(map.cRow(z, r + 8) + cc) = v1;
            } else {
                *(float2*)(map.cRowF(z, r) + cc)     = make_float2(a[0], a[1]);
                *(float2*)(map.cRowF(z, r + 8) + cc) = make_float2(a[2], a[3]);
            }
        }
}

// =====================================================================
// Gram: C[i,j] = sum_n q[i,n]*k[j,n] (fp16). BM=BN=96 BK=32,
// split-K=4, 4-stage cp.async ring, dynamic smem, ldsm4 B-frags.
// =====================================================================
#define GRAM_STGB 7680u
#define GRAM_SMEM (4 * 2 * GRAM_STGB)   // 61440

__global__ __launch_bounds__(256, 2) void gram_mma(
    const __half* __restrict__ dwh, float* __restrict__ gramp)
{
    extern __shared__ char smraw[];
    __half* Abase = (__half*)smraw;
    __half* Bbase = (__half*)(smraw + 4 * GRAM_STGB);

    constexpr int KS_LEN = 8192 / KSPLIT_;   // 2048
    constexpr int NSTG = KS_LEN / 32;        // 64

    const int z = blockIdx.z;
    const int ks = z & (KSPLIT_ - 1), bh_ = z / KSPLIT_;
    const int h = bh_ & 7, b = bh_ >> 3;
    const int bi = blockIdx.y * 96, bj = blockIdx.x * 96;
    const int tid = threadIdx.x, lane = tid & 31, w = tid >> 5;
    const int m0 = (w >> 2) * 48, n0 = (w & 3) * 24;
    const int kbase = ks * KS_LEN;

    const __half* src[3]; unsigned dst[3];
#pragma unroll
    for (int it = 0; it < 3; ++it) {
        int idx = tid + it * 256;
        int which = idx / 384, w2 = idx % 384;
        int row = w2 >> 2, c4 = w2 & 3;
        size_t off;
        if (which == 0) {
            int qi = bi + row;
            off = ((size_t)(b * C3_ + h * 24 + (qi >> 3)) << 16) + ((size_t)(qi & 7) << 13);
        } else {
            int kj = bj + row;
            off = ((size_t)(b * C3_ + C_ + h * 24 + (kj >> 3)) << 16) + ((size_t)(kj & 7) << 13);
        }
        src[it] = dwh + off + kbase + c4 * 8;
        __half* d = (which == 0 ? Abase : Bbase) + row * 40 + c4 * 8;
        dst[it] = (unsigned)__cvta_generic_to_shared(d);
    }

    float acc[3][3][4];
#pragma unroll
    for (int i = 0; i < 3; ++i)
#pragma unroll
        for (int j = 0; j < 3; ++j)
#pragma unroll
            for (int q = 0; q < 4; ++q) acc[i][j][q] = 0.f;

#pragma unroll
    for (int p = 0; p < 3; ++p) {
#pragma unroll
        for (int it = 0; it < 3; ++it) cpa16(dst[it] + p * GRAM_STGB, src[it] + p * 32);
        CP_COMMIT();
    }

#pragma unroll 1
    for (int s = 0; s < NSTG; ++s) {
        CP_WAIT2();
        __syncthreads();
        if (s + 3 < NSTG) {
            const unsigned b4 = (unsigned)((s + 3) & 3);
            const int ka = (s + 3) * 32;
#pragma unroll
            for (int it = 0; it < 3; ++it) cpa16(dst[it] + b4 * GRAM_STGB, src[it] + ka);
        }
        CP_COMMIT();
        const __half* As = Abase + (s & 3) * 3840;
        const __half* Bs = Bbase + (s & 3) * 3840;
#pragma unroll
        for (int kk = 0; kk < 32; kk += 16) {
            unsigned ah[3][4], bph[4], b2h[2];
            const int l15 = lane & 15;
            const int g = lane >> 3;
#pragma unroll
            for (int mi = 0; mi < 3; ++mi)
                ldsm4(ah[mi], As + (m0 + mi * 16 + l15) * 40 + kk + (lane >> 4) * 8);
            {
                const int brow = n0 + ((g >> 1) << 3) + (lane & 7);
                const int bcol = kk + ((g & 1) << 3);
                ldsm4(bph, Bs + brow * 40 + bcol);
                ldsm2(b2h, Bs + (n0 + 16 + (l15 & 7)) * 40 + kk + ((l15 >> 3) << 3));
            }
#pragma unroll
            for (int mi = 0; mi < 3; ++mi) {
#pragma unroll
                for (int h2 = 0; h2 < 2; ++h2)
                    mma16816(acc[mi][h2], ah[mi], bph + h2 * 2);
                mma16816(acc[mi][2], ah[mi], b2h);
            }
        }
    }

    float* gp = gramp + ((size_t)ks * (B_ * HEADS_) + bh_) * (C_ * C_);
#pragma unroll
    for (int mi = 0; mi < 3; ++mi)
#pragma unroll
        for (int ni = 0; ni < 3; ++ni) {
            const int r = bi + m0 + mi * 16 + (lane >> 2);
            const int cc = bj + n0 + ni * 8 + (lane & 3) * 2;
            const float* a = acc[mi][ni];
            *(float2*)(gp + (size_t)r * C_ + cc)       = make_float2(a[0], a[1]);
            *(float2*)(gp + (size_t)(r + 8) * C_ + cc) = make_float2(a[2], a[3]);
        }
}

// ---------------- depthwise 3x3 (fp16 in/out) + norm partials -----------------
__global__ __launch_bounds__(256) void dw_kernel(
    const __half* __restrict__ inh, const float* __restrict__ dww,
    __half* __restrict__ outh,
    float* __restrict__ partq, float* __restrict__ partk)
{
    const int chg = blockIdx.z;
    const int c = chg % C3_;
    const int b = chg / C3_;
    const size_t base = (size_t)chg << 16;

    float w[9];
#pragma unroll
    for (int i = 0; i < 9; ++i) w[i] = __ldg(&dww[c * 9 + i]);

    __shared__ float s[34][34];
    const int ox = blockIdx.x * 32 - 1, oy = blockIdx.y * 32 - 1;
    for (int t = threadIdx.x; t < 34 * 34; t += 256) {
        int lx = t % 34, ly = t / 34;
        int gx = ox + lx, gy = oy + ly;
        float v = 0.f;
        if ((unsigned)gx < W_ && (unsigned)gy < H_) v = __half2float(inh[base + gy * W_ + gx]);
        s[ly][lx] = v;
    }
    __syncthreads();

    const int tx = threadIdx.x & 31, ty0 = threadIdx.x >> 5;
    float ss = 0.f;
#pragma unroll
    for (int r = 0; r < 4; ++r) {
        int ly = ty0 + 8 * r;
        float acc = s[ly + 0][tx + 0] * w[0] + s[ly + 0][tx + 1] * w[1] + s[ly + 0][tx + 2] * w[2]
                  + s[ly + 1][tx + 0] * w[3] + s[ly + 1][tx + 1] * w[4] + s[ly + 1][tx + 2] * w[5]
                  + s[ly + 2][tx + 0] * w[6] + s[ly + 2][tx + 1] * w[7] + s[ly + 2][tx + 2] * w[8];
        ss += acc * acc;
        size_t sp = (size_t)(blockIdx.y * 32 + ly) * W_ + blockIdx.x * 32 + tx;
        outh[base + sp] = __float2half(acc);
    }

    if (c < 2 * C_) {
        __shared__ float red[8];
#pragma unroll
        for (int o = 16; o > 0; o >>= 1) ss += __shfl_xor_sync(0xffffffffu, ss, o);
        if ((threadIdx.x & 31) == 0) red[threadIdx.x >> 5] = ss;
        __syncthreads();
        if (threadIdx.x == 0) {
            float tot = 0.f;
#pragma unroll
            for (int i = 0; i < 8; ++i) tot += red[i];
            if (c < C_)
                partq[((b * C_ + c) * 8 + blockIdx.y) * 8 + blockIdx.x] = tot;
            else
                partk[((b * C_ + (c - C_)) * 8 + blockIdx.y) * 8 + blockIdx.x] = tot;
        }
    }
}

__global__ void norms_finish(
    const float* __restrict__ partq, const float* __restrict__ partk,
    float* __restrict__ invq, float* __restrict__ invk)
{
    int idx = blockIdx.x * blockDim.x + threadIdx.x;
    if (idx < B_ * C_ * 8) {
        float sq = 0.f, sk = 0.f;
#pragma unroll
        for (int i = 0; i < 8; ++i) { sq += partq[idx * 8 + i]; sk += partk[idx * 8 + i]; }
        invq[idx] = 1.f / fmaxf(sqrtf(sq), 1e-12f);
        invk[idx] = 1.f / fmaxf(sqrtf(sk), 1e-12f);
    }
}

// ---------------- split-K reduce + scale + softmax -> fp16 ---------------
__global__ void softmax_kernel(
    const float* __restrict__ gramp, const float* __restrict__ invq,
    const float* __restrict__ invk, const float* __restrict__ temp,
    __half* __restrict__ attnh)
{
    const int i = blockIdx.x % C_;
    const int bh = blockIdx.x / C_;
    const int head = bh & 7, b = bh >> 3;
    const int j = threadIdx.x;

    const long long base = (long long)bh * (C_ * C_) + i * C_ + j;
    float s = 0.f;
#pragma unroll
    for (int ks = 0; ks < KSPLIT_; ++ks)
        s += gramp[(long long)ks * (B_ * HEADS_ * C_ * C_) + base];

    s *= invq[(b * C_ + head * 24 + (i >> 3)) * 8 + (i & 7)]
       * invk[(b * C_ + head * 24 + (j >> 3)) * 8 + (j & 7)]
       * temp[head];

    __shared__ float red[8];
    float m = s;
#pragma unroll
    for (int o = 16; o > 0; o >>= 1) m = fmaxf(m, __shfl_xor_sync(0xffffffffu, m, o));
    if ((threadIdx.x & 31) == 0) red[threadIdx.x >> 5] = m;
    __syncthreads();
    m = fmaxf(fmaxf(fmaxf(red[0], red[1]), fmaxf(red[2], red[3])), fmaxf(red[4], red[5]));

    float p = expf(s - m);
    float sum = p;
#pragma unroll
    for (int o = 16; o > 0; o >>= 1) sum += __shfl_xor_sync(0xffffffffu, sum, o);
    __syncthreads();
    if ((threadIdx.x & 31) == 0) red[threadIdx.x >> 5] = sum;
    __syncthreads();
    sum = red[0] + red[1] + red[2] + red[3] + red[4] + red[5];

    attnh[base] = __float2half(p / sum);
}

// ---------------- launch -------------------------------------------------------
extern "C" void kernel_launch(void* const* d_in, const int* in_sizes, int n_in,
                              void* d_out, int out_size)
{
    const float* x      = (const float*)d_in[0];
    const float* qkv_w  = (const float*)d_in[1];
    const float* dw_w   = (const float*)d_in[2];
    const float* proj_w = (const float*)d_in[3];
    const float* temp   = (const float*)d_in[4];
    float* out = (float*)d_out;

    __half *xh, *wqh, *wph, *qkvh, *dwh, *av, *attnh;
    float *gramp, *partq, *partk, *invq, *invk;
    cudaGetSymbolAddress((void**)&xh,   g_xh);
    cudaGetSymbolAddress((void**)&wqh,  g_wqh);
    cudaGetSymbolAddress((void**)&wph,  g_wph);
    cudaGetSymbolAddress((void**)&qkvh, g_qkvh);
    cudaGetSymbolAddress((void**)&dwh,  g_dwh);
    cudaGetSymbolAddress((void**)&av,   g_av);
    cudaGetSymbolAddress((void**)&attnh, g_attnh);
    cudaGetSymbolAddress((void**)&gramp, g_gramp);
    cudaGetSymbolAddress((void**)&partq, g_partq);
    cudaGetSymbolAddress((void**)&partk, g_partk);
    cudaGetSymbolAddress((void**)&invq,  g_invq);
    cudaGetSymbolAddress((void**)&invk,  g_invk);

    cudaFuncSetAttribute(gemm_mma<QkvMap>,  cudaFuncAttributeMaxDynamicSharedMemorySize, GEMM_SMEM);
    cudaFuncSetAttribute(gemm_mma<AvMap>,   cudaFuncAttributeMaxDynamicSharedMemorySize, GEMM_SMEM);
    cudaFuncSetAttribute(gemm_mma<ProjMap>, cudaFuncAttributeMaxDynamicSharedMemorySize, GEMM_SMEM);
    cudaFuncSetAttribute(gram_mma,          cudaFuncAttributeMaxDynamicSharedMemorySize, GRAM_SMEM);

    // 0) fp16 converts
    split_h_kernel<<<(B_ * C_ * HW_ / 4 + 255) / 256, 256>>>(x, xh, B_ * C_ * HW_);
    split_h_kernel<<<(C3_ * C_ / 4 + 255) / 256, 256>>>(qkv_w, wqh, C3_ * C_);
    split_h_kernel<<<(C_ * C_ / 4 + 255) / 256, 256>>>(proj_w, wph, C_ * C_);

    // 1) qkv = qkv_w @ x
    {
        QkvMap m{wqh, xh, qkvh};
        gemm_mma<QkvMap><<<dim3(HW_ / 128, C3_ / 96, B_), 256, GEMM_SMEM>>>(m, C_);
    }
    // 2) depthwise 3x3 + norm partials
    dw_kernel<<<dim3(W_ / 32, H_ / 32, B_ * C3_), 256>>>(qkvh, dw_w, dwh, partq, partk);
    // 3) norms
    norms_finish<<<(B_ * C_ * 8 + 255) / 256, 256>>>(partq, partk, invq, invk);
    // 4) gram partials (split-K = 4)
    gram_mma<<<dim3(2, 2, B_ * HEADS_ * KSPLIT_), 256, GRAM_SMEM>>>(dwh, gramp);
    // 5) softmax
    softmax_kernel<<<B_ * HEADS_ * C_, C_>>>(gramp, invq, invk, temp, attnh);
    // 6) av = attn @ v
    {
        AvMap m{attnh, dwh, av};
        gemm_mma<AvMap><<<dim3(HW_ / HEADS_ / 128, C_ / 96, B_ * HEADS_), 256, GEMM_SMEM>>>(m, C_);
    }
    // 7) out = proj_w @ av
    {
        ProjMap m{wph, av, out};
        gemm_mma<ProjMap><<<dim3(HW_ / 128, C_ / 96, B_), 256, GEMM_SMEM>>>(m, C_);
    }
}

// round 14
// speedup vs baseline: 1.7305x; 1.0086x over previous
#include <cuda_runtime.h>
#include <cuda_fp16.h>
#include <cstdint>

#define B_      2
#define C_      192
#define C3_     576
#define H_      256
#define W_      256
#define HW_     65536
#define HEADS_  8
#define KSPLIT_ 4

// ---------------- scratch (device globals: allocation-free rule) ----------------
__device__ __half g_xh  [(size_t)B_ * C_ * HW_];
__device__ __half g_wqh [C3_ * C_];
__device__ __half g_wph [C_ * C_];
__device__ __half g_qkvh[(size_t)B_ * C3_ * HW_];
__device__ __half g_dwh [(size_t)B_ * C3_ * HW_];
__device__ __half g_av  [(size_t)B_ * C_ * HW_];
__device__ float  g_gramp[(size_t)KSPLIT_ * B_ * HEADS_ * C_ * C_];
__device__ __half g_attnh[(size_t)B_ * HEADS_ * C_ * C_];
__device__ float g_partq[B_ * C_ * 64];
__device__ float g_partk[B_ * C_ * 64];
__device__ float g_invq [B_ * C_ * 8];
__device__ float g_invk [B_ * C_ * 8];

// ---------------- mma / ldmatrix / cp.async helpers ----------------
__device__ __forceinline__ void ldsm4(unsigned* r, const void* p) {
    unsigned a = (unsigned)__cvta_generic_to_shared(p);
    asm volatile("ldmatrix.sync.aligned.m8n8.x4.shared.b16 {%0,%1,%2,%3}, [%4];"
                 : "=r"(r[0]), "=r"(r[1]), "=r"(r[2]), "=r"(r[3]) : "r"(a));
}
__device__ __forceinline__ void ldsm4t(unsigned* r, const void* p) {
    unsigned a = (unsigned)__cvta_generic_to_shared(p);
    asm volatile("ldmatrix.sync.aligned.m8n8.x4.trans.shared.b16 {%0,%1,%2,%3}, [%4];"
                 : "=r"(r[0]), "=r"(r[1]), "=r"(r[2]), "=r"(r[3]) : "r"(a));
}
__device__ __forceinline__ void ldsm2(unsigned* r, const void* p) {
    unsigned a = (unsigned)__cvta_generic_to_shared(p);
    asm volatile("ldmatrix.sync.aligned.m8n8.x2.shared.b16 {%0,%1}, [%2];"
                 : "=r"(r[0]), "=r"(r[1]) : "r"(a));
}
__device__ __forceinline__ void mma16816(float* c, const unsigned* a, const unsigned* b) {
    asm volatile("mma.sync.aligned.m16n8k16.row.col.f32.f16.f16.f32 "
                 "{%0,%1,%2,%3},{%4,%5,%6,%7},{%8,%9},{%0,%1,%2,%3};"
                 : "+f"(c[0]), "+f"(c[1]), "+f"(c[2]), "+f"(c[3])
                 : "r"(a[0]), "r"(a[1]), "r"(a[2]), "r"(a[3]), "r"(b[0]), "r"(b[1]));
}
__device__ __forceinline__ void cpa16(unsigned dst, const void* src) {
    asm volatile("cp.async.cg.shared.global [%0], [%1], 16;\n" :: "r"(dst), "l"(src));
}
#define CP_COMMIT() asm volatile("cp.async.commit_group;\n")
#define CP_WAIT2()  asm volatile("cp.async.wait_group 2;\n" ::: "memory")

// ---------------- fp32 -> fp16 convert ----------------
__global__ __launch_bounds__(256) void split_h_kernel(
    const float* __restrict__ in, __half* __restrict__ oh, int n)
{
    int i = (blockIdx.x * 256 + threadIdx.x) * 4;
    if (i < n) {
        float4 v = *(const float4*)(in + i);
        __half2 a; a.x = __float2half(v.x); a.y = __float2half(v.y);
        __half2 b; b.x = __float2half(v.z); b.y = __float2half(v.w);
        ((__half2*)(oh + i))[0] = a;
        ((__half2*)(oh + i))[1] = b;
    }
}

// ---------------- maps ----------------
struct QkvMap {
    const __half *Ah, *B; __half *Cc;
    static constexpr int CMODE = 1;
    static constexpr size_t BSTRIDE32 = (size_t)32 * HW_;
    __device__ const __half* aRowH(int z, int m) const { return Ah + (size_t)m * C_; }
    __device__ const __half* bRow(int z, int k) const { return B + ((size_t)z * C_ + k) * HW_; }
    __device__ __half* cRow(int z, int m) const { return Cc + ((size_t)z * C3_ + m) * HW_; }
    __device__ float*  cRowF(int z, int m) const { return nullptr; }
};
struct AvMap {
    const __half *Ah, *B; __half *Cc;
    static constexpr int CMODE = 1;
    static constexpr size_t BSTRIDE32 = (size_t)4 << 16;
    __device__ const __half* aRowH(int z, int m) const { return Ah + (size_t)z * (C_ * C_) + (size_t)m * C_; }
    __device__ const __half* bRow(int z, int k) const {
        int b = z >> 3, h = z & 7;
        return B + ((size_t)(b * C3_ + 2 * C_ + h * 24 + (k >> 3)) << 16) + ((k & 7) << 13);
    }
    __device__ __half* cRow(int z, int m) const {
        int b = z >> 3, h = z & 7;
        return Cc + ((size_t)(b * C_ + h * 24 + (m >> 3)) << 16) + ((m & 7) << 13);
    }
    __device__ float*  cRowF(int z, int m) const { return nullptr; }
};
struct ProjMap {
    const __half *Ah, *B; float* C;
    static constexpr int CMODE = 2;
    static constexpr size_t BSTRIDE32 = (size_t)32 * HW_;
    __device__ const __half* aRowH(int z, int m) const { return Ah + (size_t)m * C_; }
    __device__ const __half* bRow(int z, int k) const { return B + ((size_t)z * C_ + k) * HW_; }
    __device__ float* cRowF(int z, int m) const { return C + ((size_t)z * C_ + m) * HW_; }
    __device__ __half* cRow(int z, int m) const { return nullptr; }
};

// =====================================================================
// fp16 MMA GEMM: C = Ah @ B.  BM=96 BN=128 BK=32, 4-stage cp.async ring,
// 384 threads (12 warps, warp tile 32x32), dynamic smem.
// =====================================================================
#define GEMM_ASTGB 7680u            // 96*40*2
#define GEMM_BSTGB 8704u            // 32*136*2
#define GEMM_SMEM  (4 * (GEMM_ASTGB + GEMM_BSTGB))   // 65536

template <class Map>
__global__ __launch_bounds__(384, 2) void gemm_mma(const Map map, const int K)
{
    extern __shared__ char smraw[];
    __half* Abase = (__half*)smraw;
    __half* Bbase = (__half*)(smraw + 4 * GEMM_ASTGB);

    const int z = blockIdx.z, bm = blockIdx.y * 96, bn = blockIdx.x * 128;
    const int tid = threadIdx.x, lane = tid & 31, w = tid >> 5;
    const int m0 = (w >> 2) * 32, n0 = (w & 3) * 32;

    // A loader: 384 chunks, exactly 1 per thread
    const __half* asrc; unsigned adst;
    {
        int row = tid >> 2, c4 = tid & 3;
        asrc = map.aRowH(z, bm + row) + c4 * 8;
        adst = (unsigned)__cvta_generic_to_shared(Abase + row * 40 + c4 * 8);
    }
    // B loaders: 512 chunks, 2 iters (second partial: tid < 128)
    const __half* bsrc[2]; unsigned bdst[2]; bool bval[2];
#pragma unroll
    for (int it = 0; it < 2; ++it) {
        int idx = tid + it * 384;
        bval[it] = idx < 512;
        if (idx >= 512) idx = 511;
        int row = idx >> 4, c4 = idx & 15;
        bsrc[it] = map.bRow(z, row) + bn + c4 * 8;
        bdst[it] = (unsigned)__cvta_generic_to_shared(Bbase + row * 136 + c4 * 8);
    }

    float acc[2][4][4];
#pragma unroll
    for (int i = 0; i < 2; ++i)
#pragma unroll
        for (int j = 0; j < 4; ++j)
#pragma unroll
            for (int q = 0; q < 4; ++q) acc[i][j][q] = 0.f;

    const int nStage = K >> 5;
#pragma unroll
    for (int p = 0; p < 3; ++p) {
        if (p < nStage) {
            cpa16(adst + p * GEMM_ASTGB, asrc + p * 32);
#pragma unroll
            for (int it = 0; it < 2; ++it) if (bval[it]) cpa16(bdst[it] + p * GEMM_BSTGB, bsrc[it] + (size_t)p * Map::BSTRIDE32);
        }
        CP_COMMIT();
    }

#pragma unroll 1
    for (int s = 0; s < nStage; ++s) {
        CP_WAIT2();
        __syncthreads();
        if (s + 3 < nStage) {
            const unsigned b4 = (unsigned)((s + 3) & 3);
            const int ka = (s + 3) * 32;
            const size_t kb = (size_t)(s + 3) * Map::BSTRIDE32;
            cpa16(adst + b4 * GEMM_ASTGB, asrc + ka);
#pragma unroll
            for (int it = 0; it < 2; ++it) if (bval[it]) cpa16(bdst[it] + b4 * GEMM_BSTGB, bsrc[it] + kb);
        }
        CP_COMMIT();
        const __half* As  = Abase + (s & 3) * 3840;
        const __half* Bsp = Bbase + (s & 3) * 4352;
#pragma unroll
        for (int kk = 0; kk < 32; kk += 16) {
            unsigned ah[2][4], bh[2][4];
            const int l15 = lane & 15;
            const int g = lane >> 3;
            const int brow = kk + ((g & 1) << 3) + (lane & 7);
#pragma unroll
            for (int mi = 0; mi < 2; ++mi)
                ldsm4(ah[mi], As + (m0 + mi * 16 + l15) * 40 + kk + (lane >> 4) * 8);
#pragma unroll
            for (int p = 0; p < 2; ++p) {
                const int bcol = n0 + p * 16 + ((g >> 1) << 3);
                ldsm4t(bh[p], Bsp + brow * 136 + bcol);
            }
#pragma unroll
            for (int mi = 0; mi < 2; ++mi)
#pragma unroll
                for (int p = 0; p < 2; ++p)
#pragma unroll
                    for (int h2 = 0; h2 < 2; ++h2)
                        mma16816(acc[mi][p * 2 + h2], ah[mi], bh[p] + h2 * 2);
        }
    }

#pragma unroll
    for (int mi = 0; mi < 2; ++mi)
#pragma unroll
        for (int ni = 0; ni < 4; ++ni) {
            const int r = bm + m0 + mi * 16 + (lane >> 2);
            const int cc = bn + n0 + ni * 8 + (lane & 3) * 2;
            const float* a = acc[mi][ni];
            if constexpr (Map::CMODE == 1) {
                __half2 v0; v0.x = __float2half(a[0]); v0.y = __float2half(a[1]);
                __half2 v1; v1.x = __float2half(a[2]); v1.y = __float2half(a[3]);
                *(__half2*)(map.cRow(z, r) + cc)     = v0;
                *(__half2*)(map.cRow(z, r + 8) + cc) = v1;
            } else {
                *(float2*)(map.cRowF(z, r) + cc)     = make_float2(a[0], a[1]);
                *(float2*)(map.cRowF(z, r + 8) + cc) = make_float2(a[2], a[3]);
            }
        }
}

// =====================================================================
// Gram: C[i,j] = sum_n q[i,n]*k[j,n] (fp16). BM=BN=96 BK=32,
// split-K=4, 4-stage cp.async ring, dynamic smem, ldsm4 B-frags.
// =====================================================================
#define GRAM_STGB 7680u
#define GRAM_SMEM (4 * 2 * GRAM_STGB)   // 61440

__global__ __launch_bounds__(256, 2) void gram_mma(
    const __half* __restrict__ dwh, float* __restrict__ gramp)
{
    extern __shared__ char smraw[];
    __half* Abase = (__half*)smraw;
    __half* Bbase = (__half*)(smraw + 4 * GRAM_STGB);

    constexpr int KS_LEN = 8192 / KSPLIT_;   // 2048
    constexpr int NSTG = KS_LEN / 32;        // 64

    const int z = blockIdx.z;
    const int ks = z & (KSPLIT_ - 1), bh_ = z / KSPLIT_;
    const int h = bh_ & 7, b = bh_ >> 3;
    const int bi = blockIdx.y * 96, bj = blockIdx.x * 96;
    const int tid = threadIdx.x, lane = tid & 31, w = tid >> 5;
    const int m0 = (w >> 2) * 48, n0 = (w & 3) * 24;
    const int kbase = ks * KS_LEN;

    const __half* src[3]; unsigned dst[3];
#pragma unroll
    for (int it = 0; it < 3; ++it) {
        int idx = tid + it * 256;
        int which = idx / 384, w2 = idx % 384;
        int row = w2 >> 2, c4 = w2 & 3;
        size_t off;
        if (which == 0) {
            int qi = bi + row;
            off = ((size_t)(b * C3_ + h * 24 + (qi >> 3)) << 16) + ((size_t)(qi & 7) << 13);
        } else {
            int kj = bj + row;
            off = ((size_t)(b * C3_ + C_ + h * 24 + (kj >> 3)) << 16) + ((size_t)(kj & 7) << 13);
        }
        src[it] = dwh + off + kbase + c4 * 8;
        __half* d = (which == 0 ? Abase : Bbase) + row * 40 + c4 * 8;
        dst[it] = (unsigned)__cvta_generic_to_shared(d);
    }

    float acc[3][3][4];
#pragma unroll
    for (int i = 0; i < 3; ++i)
#pragma unroll
        for (int j = 0; j < 3; ++j)
#pragma unroll
            for (int q = 0; q < 4; ++q) acc[i][j][q] = 0.f;

#pragma unroll
    for (int p = 0; p < 3; ++p) {
#pragma unroll
        for (int it = 0; it < 3; ++it) cpa16(dst[it] + p * GRAM_STGB, src[it] + p * 32);
        CP_COMMIT();
    }

#pragma unroll 1
    for (int s = 0; s < NSTG; ++s) {
        CP_WAIT2();
        __syncthreads();
        if (s + 3 < NSTG) {
            const unsigned b4 = (unsigned)((s + 3) & 3);
            const int ka = (s + 3) * 32;
#pragma unroll
            for (int it = 0; it < 3; ++it) cpa16(dst[it] + b4 * GRAM_STGB, src[it] + ka);
        }
        CP_COMMIT();
        const __half* As = Abase + (s & 3) * 3840;
        const __half* Bs = Bbase + (s & 3) * 3840;
#pragma unroll
        for (int kk = 0; kk < 32; kk += 16) {
            unsigned ah[3][4], bph[4], b2h[2];
            const int l15 = lane & 15;
            const int g = lane >> 3;
#pragma unroll
            for (int mi = 0; mi < 3; ++mi)
                ldsm4(ah[mi], As + (m0 + mi * 16 + l15) * 40 + kk + (lane >> 4) * 8);
            {
                const int brow = n0 + ((g >> 1) << 3) + (lane & 7);
                const int bcol = kk + ((g & 1) << 3);
                ldsm4(bph, Bs + brow * 40 + bcol);
                ldsm2(b2h, Bs + (n0 + 16 + (l15 & 7)) * 40 + kk + ((l15 >> 3) << 3));
            }
#pragma unroll
            for (int mi = 0; mi < 3; ++mi) {
#pragma unroll
                for (int h2 = 0; h2 < 2; ++h2)
                    mma16816(acc[mi][h2], ah[mi], bph + h2 * 2);
                mma16816(acc[mi][2], ah[mi], b2h);
            }
        }
    }

    float* gp = gramp + ((size_t)ks * (B_ * HEADS_) + bh_) * (C_ * C_);
#pragma unroll
    for (int mi = 0; mi < 3; ++mi)
#pragma unroll
        for (int ni = 0; ni < 3; ++ni) {
            const int r = bi + m0 + mi * 16 + (lane >> 2);
            const int cc = bj + n0 + ni * 8 + (lane & 3) * 2;
            const float* a = acc[mi][ni];
            *(float2*)(gp + (size_t)r * C_ + cc)       = make_float2(a[0], a[1]);
            *(float2*)(gp + (size_t)(r + 8) * C_ + cc) = make_float2(a[2], a[3]);
        }
}

// ---------------- depthwise 3x3 (fp16 in/out) + norm partials -----------------
__global__ __launch_bounds__(256) void dw_kernel(
    const __half* __restrict__ inh, const float* __restrict__ dww,
    __half* __restrict__ outh,
    float* __restrict__ partq, float* __restrict__ partk)
{
    const int chg = blockIdx.z;
    const int c = chg % C3_;
    const int b = chg / C3_;
    const size_t base = (size_t)chg << 16;

    float w[9];
#pragma unroll
    for (int i = 0; i < 9; ++i) w[i] = __ldg(&dww[c * 9 + i]);

    __shared__ float s[34][34];
    const int ox = blockIdx.x * 32 - 1, oy = blockIdx.y * 32 - 1;
    for (int t = threadIdx.x; t < 34 * 34; t += 256) {
        int lx = t % 34, ly = t / 34;
        int gx = ox + lx, gy = oy + ly;
        float v = 0.f;
        if ((unsigned)gx < W_ && (unsigned)gy < H_) v = __half2float(inh[base + gy * W_ + gx]);
        s[ly][lx] = v;
    }
    __syncthreads();

    const int tx = threadIdx.x & 31, ty0 = threadIdx.x >> 5;
    float ss = 0.f;
#pragma unroll
    for (int r = 0; r < 4; ++r) {
        int ly = ty0 + 8 * r;
        float acc = s[ly + 0][tx + 0] * w[0] + s[ly + 0][tx + 1] * w[1] + s[ly + 0][tx + 2] * w[2]
                  + s[ly + 1][tx + 0] * w[3] + s[ly + 1][tx + 1] * w[4] + s[ly + 1][tx + 2] * w[5]
                  + s[ly + 2][tx + 0] * w[6] + s[ly + 2][tx + 1] * w[7] + s[ly + 2][tx + 2] * w[8];
        ss += acc * acc;
        size_t sp = (size_t)(blockIdx.y * 32 + ly) * W_ + blockIdx.x * 32 + tx;
        outh[base + sp] = __float2half(acc);
    }

    if (c < 2 * C_) {
        __shared__ float red[8];
#pragma unroll
        for (int o = 16; o > 0; o >>= 1) ss += __shfl_xor_sync(0xffffffffu, ss, o);
        if ((threadIdx.x & 31) == 0) red[threadIdx.x >> 5] = ss;
        __syncthreads();
        if (threadIdx.x == 0) {
            float tot = 0.f;
#pragma unroll
            for (int i = 0; i < 8; ++i) tot += red[i];
            if (c < C_)
                partq[((b * C_ + c) * 8 + blockIdx.y) * 8 + blockIdx.x] = tot;
            else
                partk[((b * C_ + (c - C_)) * 8 + blockIdx.y) * 8 + blockIdx.x] = tot;
        }
    }
}

__global__ void norms_finish(
    const float* __restrict__ partq, const float* __restrict__ partk,
    float* __restrict__ invq, float* __restrict__ invk)
{
    int idx = blockIdx.x * blockDim.x + threadIdx.x;
    if (idx < B_ * C_ * 8) {
        float sq = 0.f, sk = 0.f;
#pragma unroll
        for (int i = 0; i < 8; ++i) { sq += partq[idx * 8 + i]; sk += partk[idx * 8 + i]; }
        invq[idx] = 1.f / fmaxf(sqrtf(sq), 1e-12f);
        invk[idx] = 1.f / fmaxf(sqrtf(sk), 1e-12f);
    }
}

// ---------------- split-K reduce + scale + softmax -> fp16 ---------------
__global__ void softmax_kernel(
    const float* __restrict__ gramp, const float* __restrict__ invq,
    const float* __restrict__ invk, const float* __restrict__ temp,
    __half* __restrict__ attnh)
{
    const int i = blockIdx.x % C_;
    const int bh = blockIdx.x / C_;
    const int head = bh & 7, b = bh >> 3;
    const int j = threadIdx.x;

    const long long base = (long long)bh * (C_ * C_) + i * C_ + j;
    float s = 0.f;
#pragma unroll
    for (int ks = 0; ks < KSPLIT_; ++ks)
        s += gramp[(long long)ks * (B_ * HEADS_ * C_ * C_) + base];

    s *= invq[(b * C_ + head * 24 + (i >> 3)) * 8 + (i & 7)]
       * invk[(b * C_ + head * 24 + (j >> 3)) * 8 + (j & 7)]
       * temp[head];

    __shared__ float red[8];
    float m = s;
#pragma unroll
    for (int o = 16; o > 0; o >>= 1) m = fmaxf(m, __shfl_xor_sync(0xffffffffu, m, o));
    if ((threadIdx.x & 31) == 0) red[threadIdx.x >> 5] = m;
    __syncthreads();
    m = fmaxf(fmaxf(fmaxf(red[0], red[1]), fmaxf(red[2], red[3])), fmaxf(red[4], red[5]));

    float p = expf(s - m);
    float sum = p;
#pragma unroll
    for (int o = 16; o > 0; o >>= 1) sum += __shfl_xor_sync(0xffffffffu, sum, o);
    __syncthreads();
    if ((threadIdx.x & 31) == 0) red[threadIdx.x >> 5] = sum;
    __syncthreads();
    sum = red[0] + red[1] + red[2] + red[3] + red[4] + red[5];

    attnh[base] = __float2half(p / sum);
}

// ---------------- launch -------------------------------------------------------
extern "C" void kernel_launch(void* const* d_in, const int* in_sizes, int n_in,
                              void* d_out, int out_size)
{
    const float* x      = (const float*)d_in[0];
    const float* qkv_w  = (const float*)d_in[1];
    const float* dw_w   = (const float*)d_in[2];
    const float* proj_w = (const float*)d_in[3];
    const float* temp   = (const float*)d_in[4];
    float* out = (float*)d_out;

    __half *xh, *wqh, *wph, *qkvh, *dwh, *av, *attnh;
    float *gramp, *partq, *partk, *invq, *invk;
    cudaGetSymbolAddress((void**)&xh,   g_xh);
    cudaGetSymbolAddress((void**)&wqh,  g_wqh);
    cudaGetSymbolAddress((void**)&wph,  g_wph);
    cudaGetSymbolAddress((void**)&qkvh, g_qkvh);
    cudaGetSymbolAddress((void**)&dwh,  g_dwh);
    cudaGetSymbolAddress((void**)&av,   g_av);
    cudaGetSymbolAddress((void**)&attnh, g_attnh);
    cudaGetSymbolAddress((void**)&gramp, g_gramp);
    cudaGetSymbolAddress((void**)&partq, g_partq);
    cudaGetSymbolAddress((void**)&partk, g_partk);
    cudaGetSymbolAddress((void**)&invq,  g_invq);
    cudaGetSymbolAddress((void**)&invk,  g_invk);

    cudaFuncSetAttribute(gemm_mma<QkvMap>,  cudaFuncAttributeMaxDynamicSharedMemorySize, GEMM_SMEM);
    cudaFuncSetAttribute(gemm_mma<AvMap>,   cudaFuncAttributeMaxDynamicSharedMemorySize, GEMM_SMEM);
    cudaFuncSetAttribute(gemm_mma<ProjMap>, cudaFuncAttributeMaxDynamicSharedMemorySize, GEMM_SMEM);
    cudaFuncSetAttribute(gram_mma,          cudaFuncAttributeMaxDynamicSharedMemorySize, GRAM_SMEM);

    // 0) fp16 converts
    split_h_kernel<<<(B_ * C_ * HW_ / 4 + 255) / 256, 256>>>(x, xh, B_ * C_ * HW_);
    split_h_kernel<<<(C3_ * C_ / 4 + 255) / 256, 256>>>(qkv_w, wqh, C3_ * C_);
    split_h_kernel<<<(C_ * C_ / 4 + 255) / 256, 256>>>(proj_w, wph, C_ * C_);

    // 1) qkv = qkv_w @ x
    {
        QkvMap m{wqh, xh, qkvh};
        gemm_mma<QkvMap><<<dim3(HW_ / 128, C3_ / 96, B_), 384, GEMM_SMEM>>>(m, C_);
    }
    // 2) depthwise 3x3 + norm partials
    dw_kernel<<<dim3(W_ / 32, H_ / 32, B_ * C3_), 256>>>(qkvh, dw_w, dwh, partq, partk);
    // 3) norms
    norms_finish<<<(B_ * C_ * 8 + 255) / 256, 256>>>(partq, partk, invq, invk);
    // 4) gram partials (split-K = 4)
    gram_mma<<<dim3(2, 2, B_ * HEADS_ * KSPLIT_), 256, GRAM_SMEM>>>(dwh, gramp);
    // 5) softmax
    softmax_kernel<<<B_ * HEADS_ * C_, C_>>>(gramp, invq, invk, temp, attnh);
    // 6) av = attn @ v
    {
        AvMap m{attnh, dwh, av};
        gemm_mma<AvMap><<<dim3(HW_ / HEADS_ / 128, C_ / 96, B_ * HEADS_), 384, GEMM_SMEM>>>(m, C_);
    }
    // 7) out = proj_w @ av
    {
        ProjMap m{wph, av, out};
        gemm_mma<ProjMap><<<dim3(HW_ / 128, C_ / 96, B_), 384, GEMM_SMEM>>>(m, C_);
    }
}